// round 5
// baseline (speedup 1.0000x reference)
#include <cuda_runtime.h>

#define NN 50000
#define EE 250000
#define HD 64

// persistent scratch (no allocations allowed)
__device__ float g_x[2][(size_t)NN * HD];   // double-buffered node state
__device__ float g_y[(size_t)EE * HD];      // edge state
__device__ float g_goal[16];                // goal node feature vec (9 used)

// precombined weights (difference segments folded in)
__device__ float g_wfx[192 * 64];           // [xs, xd, y]
__device__ float g_wfy[128 * 64];           // [xj, xi]
__device__ float g_why[18 * 64];            // [vj, vi]
__device__ float g_whx[18 * 64];            // [vc, d*d]
__device__ float g_bhx[64];                 // hx bias + goal fold

__device__ __forceinline__ void atomicMaxF(float* addr, float v) {
    if (v >= 0.f) atomicMax((int*)addr, __float_as_int(v));
    else          atomicMin((unsigned int*)addr, __float_as_uint(v));
}

// ---------------------------------------------------------------------------
// goal = vc[argmax(labels[:,1])]  (first index on ties)
// ---------------------------------------------------------------------------
__global__ void k_goal(const float* __restrict__ v,
                       const float* __restrict__ labels, int n) {
    __shared__ float bv[1024];
    __shared__ int   bi[1024];
    float best = -1e30f; int bidx = 0;
    for (int i = threadIdx.x; i < n; i += 1024) {
        float val = labels[2 * i + 1];
        if (val > best) { best = val; bidx = i; }
    }
    bv[threadIdx.x] = best; bi[threadIdx.x] = bidx;
    __syncthreads();
    for (int s = 512; s > 0; s >>= 1) {
        if (threadIdx.x < s) {
            float ov = bv[threadIdx.x + s]; int oi = bi[threadIdx.x + s];
            if (ov > bv[threadIdx.x] || (ov == bv[threadIdx.x] && oi < bi[threadIdx.x])) {
                bv[threadIdx.x] = ov; bi[threadIdx.x] = oi;
            }
        }
        __syncthreads();
    }
    if (threadIdx.x == 0) {
        int g = bi[0];
        #pragma unroll
        for (int c = 0; c < 7; c++) g_goal[c] = v[g * 7 + c];
        g_goal[7] = labels[2 * g];
        g_goal[8] = labels[2 * g + 1];
    }
}

// ---------------------------------------------------------------------------
// weight precombination kernels
// fx: [d, xs, xd, y]@W -> [xs, xd, y]:  Wxs=W[64:128]+W[0:64], Wxd=W[128:192]-W[0:64], Wy=W[192:256]
// ---------------------------------------------------------------------------
__global__ void k_prep_fx(const float* __restrict__ w1) {
    int idx = blockIdx.x * 256 + threadIdx.x;
    if (idx >= 192 * 64) return;
    int k = idx >> 6, j = idx & 63;
    float o;
    if (k < 64)       o = w1[(64 + k) * 64 + j] + w1[k * 64 + j];
    else if (k < 128) o = w1[(64 + k) * 64 + j] - w1[(k - 64) * 64 + j];
    else              o = w1[(64 + k) * 64 + j];
    g_wfx[idx] = o;
}
// fy: [xj-xi, xj, xi]@W -> [xj, xi]:  Wxj=W[0:64]+W[64:128], Wxi=W[128:192]-W[0:64]
__global__ void k_prep_fy(const float* __restrict__ w1) {
    int idx = blockIdx.x * 256 + threadIdx.x;
    if (idx >= 128 * 64) return;
    int k = idx >> 6, j = idx & 63;
    float o;
    if (k < 64) o = w1[k * 64 + j] + w1[(64 + k) * 64 + j];
    else        o = w1[(64 + k) * 64 + j] - w1[(k - 64) * 64 + j];
    g_wfy[idx] = o;
}
// hy: [vj-vi, vj, vi] -> [vj, vi]; hx: [vc, goal, d, dd] -> [vc, dd] + bias fold
__global__ void k_prep_h(const float* __restrict__ hyw1,
                         const float* __restrict__ hxw1,
                         const float* __restrict__ hxb1) {
    int idx = blockIdx.x * 64 + threadIdx.x;
    if (idx < 1152) {                       // hy combined 18x64
        int k = idx >> 6, j = idx & 63;
        float o;
        if (k < 9) o = hyw1[k * 64 + j] + hyw1[(9 + k) * 64 + j];
        else       o = hyw1[(9 + k) * 64 + j] - hyw1[(k - 9) * 64 + j];
        g_why[idx] = o;
    } else if (idx < 2304) {                // hx combined 18x64
        int r = idx - 1152;
        int k = r >> 6, j = r & 63;
        float o;
        if (k < 9) o = hxw1[k * 64 + j] + hxw1[(18 + k) * 64 + j];
        else       o = hxw1[(18 + k) * 64 + j];   // dd rows = W[27:36], (27+k-9)=18+k
        g_whx[r] = o;
    } else if (idx < 2368) {                // hx bias fold: b + goal@(Wg - Wd)
        int j = idx - 2304;
        float acc = hxb1[j];
        #pragma unroll
        for (int c = 0; c < 9; c++)
            acc += g_goal[c] * (hxw1[(9 + c) * 64 + j] - hxw1[(18 + c) * 64 + j]);
        g_bhx[j] = acc;
    }
}

// ---------------------------------------------------------------------------
// x0 = MLP_hx: combined input [vc, d*d]  (18 -> 64 -> 64), 4 nodes/block
// ---------------------------------------------------------------------------
__global__ void k_x0(const float* __restrict__ v, const float* __restrict__ labels,
                     const float* __restrict__ w2, const float* __restrict__ b2, int n) {
    __shared__ float in_s[4][18];
    __shared__ float h_s[4][64];
    int g = threadIdx.x >> 6, j = threadIdx.x & 63;
    int node = blockIdx.x * 4 + g;
    if (j < 9) {
        float vc = (j < 7) ? v[node * 7 + j] : labels[node * 2 + (j - 7)];
        float d  = vc - g_goal[j];
        in_s[g][j]     = vc;
        in_s[g][9 + j] = d * d;
    }
    __syncthreads();
    {
        float acc = g_bhx[j];
        #pragma unroll
        for (int k = 0; k < 18; k++) acc = fmaf(in_s[g][k], g_whx[k * 64 + j], acc);
        h_s[g][j] = fmaxf(acc, 0.f);
    }
    __syncthreads();
    {
        float acc = b2[j];
        #pragma unroll
        for (int k = 0; k < 64; k++) acc = fmaf(h_s[g][k], w2[k * 64 + j], acc);
        g_x[0][(size_t)node * 64 + j] = acc;
    }
}

// ---------------------------------------------------------------------------
// y0 = MLP_hy: combined input [vj, vi] (18 -> 64 -> 64)
// 16 edges/block, 16 threads/edge, 4 cols/thread
// ---------------------------------------------------------------------------
__global__ __launch_bounds__(256) void k_y0(
        const float* __restrict__ v, const float* __restrict__ labels,
        const int* __restrict__ ei,
        const float* __restrict__ b1,
        const float* __restrict__ w2, const float* __restrict__ b2, int ne) {
    __shared__ float in_s[16][20];
    __shared__ float h_s[16][68];
    int g = threadIdx.x >> 4, tt = threadIdx.x & 15;
    int e = blockIdx.x * 16 + g;
    if (tt < 9) {
        int s = ei[e], d = ei[ne + e];
        float vi = (tt < 7) ? v[s * 7 + tt] : labels[s * 2 + (tt - 7)];
        float vj = (tt < 7) ? v[d * 7 + tt] : labels[d * 2 + (tt - 7)];
        in_s[g][tt]     = vj;
        in_s[g][9 + tt] = vi;
    }
    __syncthreads();
    const float4* w1v = (const float4*)g_why;
    float4 acc = *(const float4*)(b1 + 4 * tt);
    #pragma unroll
    for (int k = 0; k < 18; k++) {
        float sv = in_s[g][k];
        float4 w = w1v[k * 16 + tt];
        acc.x = fmaf(sv, w.x, acc.x);
        acc.y = fmaf(sv, w.y, acc.y);
        acc.z = fmaf(sv, w.z, acc.z);
        acc.w = fmaf(sv, w.w, acc.w);
    }
    *(float4*)(&h_s[g][4 * tt]) = make_float4(fmaxf(acc.x, 0.f), fmaxf(acc.y, 0.f),
                                              fmaxf(acc.z, 0.f), fmaxf(acc.w, 0.f));
    __syncthreads();
    const float4* w2v = (const float4*)w2;
    float4 o = *(const float4*)(b2 + 4 * tt);
    #pragma unroll 8
    for (int k = 0; k < 64; k++) {
        float sv = h_s[g][k];
        float4 w = w2v[k * 16 + tt];
        o.x = fmaf(sv, w.x, o.x);
        o.y = fmaf(sv, w.y, o.y);
        o.z = fmaf(sv, w.z, o.z);
        o.w = fmaf(sv, w.w, o.w);
    }
    *(float4*)(g_y + (size_t)e * 64 + 4 * tt) = o;
}

// ---------------------------------------------------------------------------
// copy x buffer (init for scatter-max)
// ---------------------------------------------------------------------------
__global__ void k_copy(int from, int to, int n4) {
    int i = blockIdx.x * blockDim.x + threadIdx.x;
    if (i < n4) ((float4*)g_x[to])[i] = ((const float4*)g_x[from])[i];
}

// ---------------------------------------------------------------------------
// k_fx: m = MLP_fx combined input [xs, xd, y] (192->64->64), atomicMax to xnew[dst]
// Block: 32 edges x 64 outs, 128 threads, 4x4 register tile / thread.
// Transposed staging in_t[k][edge] (stride 36).
// ---------------------------------------------------------------------------
#define TS 36
__global__ __launch_bounds__(128) void k_fx(
        const int* __restrict__ ei,
        const float* __restrict__ b1,
        const float* __restrict__ w2, const float* __restrict__ b2,
        int rbuf, int wbuf, int ne) {
    __shared__ float in_t[192 * TS];
    __shared__ float h_t[64 * TS];
    int t = threadIdx.x;
    int q = t >> 5, el = t & 31;
    int e = blockIdx.x * 32 + el;
    const float* xr = g_x[rbuf];
    float*       xw = g_x[wbuf];
    bool act = e < ne;
    int s = act ? ei[e] : 0;
    int d = act ? ei[ne + e] : 0;

    const float4* ps = (const float4*)(xr + (size_t)s * 64);
    const float4* pd = (const float4*)(xr + (size_t)d * 64);
    const float4* py = (const float4*)(g_y + (size_t)e * 64);
    // 48 float4-chunks (3 segments x 16), warp q handles chunks 12q..12q+11
    #pragma unroll
    for (int c0 = 0; c0 < 12; c0++) {
        int c = q * 12 + c0;
        int seg = c >> 4, r = c & 15;
        const float4* p = (seg == 0) ? ps : (seg == 1) ? pd : py;
        float4 vv = act ? p[r] : make_float4(0, 0, 0, 0);
        int base = seg * 64 + 4 * r;
        in_t[(base + 0) * TS + el] = vv.x;
        in_t[(base + 1) * TS + el] = vv.y;
        in_t[(base + 2) * TS + el] = vv.z;
        in_t[(base + 3) * TS + el] = vv.w;
    }
    __syncthreads();

    int i = t & 7;    // edge group: edges 4i..4i+3
    int j = t >> 3;   // out group:  outs  4j..4j+3
    float acc[4][4];
    {
        float4 bv = *(const float4*)(b1 + 4 * j);
        #pragma unroll
        for (int ii = 0; ii < 4; ii++) {
            acc[ii][0] = bv.x; acc[ii][1] = bv.y; acc[ii][2] = bv.z; acc[ii][3] = bv.w;
        }
    }
    #pragma unroll 4
    for (int k = 0; k < 192; k++) {
        float4 ev = *(const float4*)(&in_t[k * TS + 4 * i]);
        float4 wv = __ldg((const float4*)(g_wfx + k * 64 + 4 * j));
        acc[0][0] = fmaf(ev.x, wv.x, acc[0][0]); acc[0][1] = fmaf(ev.x, wv.y, acc[0][1]);
        acc[0][2] = fmaf(ev.x, wv.z, acc[0][2]); acc[0][3] = fmaf(ev.x, wv.w, acc[0][3]);
        acc[1][0] = fmaf(ev.y, wv.x, acc[1][0]); acc[1][1] = fmaf(ev.y, wv.y, acc[1][1]);
        acc[1][2] = fmaf(ev.y, wv.z, acc[1][2]); acc[1][3] = fmaf(ev.y, wv.w, acc[1][3]);
        acc[2][0] = fmaf(ev.z, wv.x, acc[2][0]); acc[2][1] = fmaf(ev.z, wv.y, acc[2][1]);
        acc[2][2] = fmaf(ev.z, wv.z, acc[2][2]); acc[2][3] = fmaf(ev.z, wv.w, acc[2][3]);
        acc[3][0] = fmaf(ev.w, wv.x, acc[3][0]); acc[3][1] = fmaf(ev.w, wv.y, acc[3][1]);
        acc[3][2] = fmaf(ev.w, wv.z, acc[3][2]); acc[3][3] = fmaf(ev.w, wv.w, acc[3][3]);
    }
    #pragma unroll
    for (int jj = 0; jj < 4; jj++)
        #pragma unroll
        for (int ii = 0; ii < 4; ii++)
            h_t[(4 * j + jj) * TS + 4 * i + ii] = fmaxf(acc[ii][jj], 0.f);
    __syncthreads();

    {
        float4 bv = *(const float4*)(b2 + 4 * j);
        #pragma unroll
        for (int ii = 0; ii < 4; ii++) {
            acc[ii][0] = bv.x; acc[ii][1] = bv.y; acc[ii][2] = bv.z; acc[ii][3] = bv.w;
        }
    }
    #pragma unroll 4
    for (int k = 0; k < 64; k++) {
        float4 ev = *(const float4*)(&h_t[k * TS + 4 * i]);
        float4 wv = __ldg((const float4*)(w2 + k * 64 + 4 * j));
        acc[0][0] = fmaf(ev.x, wv.x, acc[0][0]); acc[0][1] = fmaf(ev.x, wv.y, acc[0][1]);
        acc[0][2] = fmaf(ev.x, wv.z, acc[0][2]); acc[0][3] = fmaf(ev.x, wv.w, acc[0][3]);
        acc[1][0] = fmaf(ev.y, wv.x, acc[1][0]); acc[1][1] = fmaf(ev.y, wv.y, acc[1][1]);
        acc[1][2] = fmaf(ev.y, wv.z, acc[1][2]); acc[1][3] = fmaf(ev.y, wv.w, acc[1][3]);
        acc[2][0] = fmaf(ev.z, wv.x, acc[2][0]); acc[2][1] = fmaf(ev.z, wv.y, acc[2][1]);
        acc[2][2] = fmaf(ev.z, wv.z, acc[2][2]); acc[2][3] = fmaf(ev.z, wv.w, acc[2][3]);
        acc[3][0] = fmaf(ev.w, wv.x, acc[3][0]); acc[3][1] = fmaf(ev.w, wv.y, acc[3][1]);
        acc[3][2] = fmaf(ev.w, wv.z, acc[3][2]); acc[3][3] = fmaf(ev.w, wv.w, acc[3][3]);
    }
    #pragma unroll
    for (int ii = 0; ii < 4; ii++) {
        int eg = blockIdx.x * 32 + 4 * i + ii;
        if (eg < ne) {
            int dd = ei[ne + eg];
            float* dp = xw + (size_t)dd * 64 + 4 * j;
            atomicMaxF(dp + 0, acc[ii][0]);
            atomicMaxF(dp + 1, acc[ii][1]);
            atomicMaxF(dp + 2, acc[ii][2]);
            atomicMaxF(dp + 3, acc[ii][3]);
        }
    }
}

// ---------------------------------------------------------------------------
// k_fy: y = max(y, MLP_fy combined [xj, xi]) (128->64->64), xj=x[dst], xi=x[src]
// ---------------------------------------------------------------------------
__global__ __launch_bounds__(128) void k_fy(
        const int* __restrict__ ei,
        const float* __restrict__ b1,
        const float* __restrict__ w2, const float* __restrict__ b2,
        int buf, int ne) {
    __shared__ float in_t[128 * TS];
    __shared__ float h_t[64 * TS];
    int t = threadIdx.x;
    int q = t >> 5, el = t & 31;
    int e = blockIdx.x * 32 + el;
    const float* xr = g_x[buf];
    bool act = e < ne;
    int s = act ? ei[e] : 0;
    int d = act ? ei[ne + e] : 0;

    const float4* pj = (const float4*)(xr + (size_t)d * 64);
    const float4* pi = (const float4*)(xr + (size_t)s * 64);
    // 32 chunks (2 segments x 16), warp q handles chunks 8q..8q+7
    #pragma unroll
    for (int c0 = 0; c0 < 8; c0++) {
        int c = q * 8 + c0;
        int seg = c >> 4, r = c & 15;
        const float4* p = (seg == 0) ? pj : pi;
        float4 vv = act ? p[r] : make_float4(0, 0, 0, 0);
        int base = seg * 64 + 4 * r;
        in_t[(base + 0) * TS + el] = vv.x;
        in_t[(base + 1) * TS + el] = vv.y;
        in_t[(base + 2) * TS + el] = vv.z;
        in_t[(base + 3) * TS + el] = vv.w;
    }
    __syncthreads();

    int i = t & 7;
    int j = t >> 3;
    float acc[4][4];
    {
        float4 bv = *(const float4*)(b1 + 4 * j);
        #pragma unroll
        for (int ii = 0; ii < 4; ii++) {
            acc[ii][0] = bv.x; acc[ii][1] = bv.y; acc[ii][2] = bv.z; acc[ii][3] = bv.w;
        }
    }
    #pragma unroll 4
    for (int k = 0; k < 128; k++) {
        float4 ev = *(const float4*)(&in_t[k * TS + 4 * i]);
        float4 wv = __ldg((const float4*)(g_wfy + k * 64 + 4 * j));
        acc[0][0] = fmaf(ev.x, wv.x, acc[0][0]); acc[0][1] = fmaf(ev.x, wv.y, acc[0][1]);
        acc[0][2] = fmaf(ev.x, wv.z, acc[0][2]); acc[0][3] = fmaf(ev.x, wv.w, acc[0][3]);
        acc[1][0] = fmaf(ev.y, wv.x, acc[1][0]); acc[1][1] = fmaf(ev.y, wv.y, acc[1][1]);
        acc[1][2] = fmaf(ev.y, wv.z, acc[1][2]); acc[1][3] = fmaf(ev.y, wv.w, acc[1][3]);
        acc[2][0] = fmaf(ev.z, wv.x, acc[2][0]); acc[2][1] = fmaf(ev.z, wv.y, acc[2][1]);
        acc[2][2] = fmaf(ev.z, wv.z, acc[2][2]); acc[2][3] = fmaf(ev.z, wv.w, acc[2][3]);
        acc[3][0] = fmaf(ev.w, wv.x, acc[3][0]); acc[3][1] = fmaf(ev.w, wv.y, acc[3][1]);
        acc[3][2] = fmaf(ev.w, wv.z, acc[3][2]); acc[3][3] = fmaf(ev.w, wv.w, acc[3][3]);
    }
    #pragma unroll
    for (int jj = 0; jj < 4; jj++)
        #pragma unroll
        for (int ii = 0; ii < 4; ii++)
            h_t[(4 * j + jj) * TS + 4 * i + ii] = fmaxf(acc[ii][jj], 0.f);
    __syncthreads();

    {
        float4 bv = *(const float4*)(b2 + 4 * j);
        #pragma unroll
        for (int ii = 0; ii < 4; ii++) {
            acc[ii][0] = bv.x; acc[ii][1] = bv.y; acc[ii][2] = bv.z; acc[ii][3] = bv.w;
        }
    }
    #pragma unroll 4
    for (int k = 0; k < 64; k++) {
        float4 ev = *(const float4*)(&h_t[k * TS + 4 * i]);
        float4 wv = __ldg((const float4*)(w2 + k * 64 + 4 * j));
        acc[0][0] = fmaf(ev.x, wv.x, acc[0][0]); acc[0][1] = fmaf(ev.x, wv.y, acc[0][1]);
        acc[0][2] = fmaf(ev.x, wv.z, acc[0][2]); acc[0][3] = fmaf(ev.x, wv.w, acc[0][3]);
        acc[1][0] = fmaf(ev.y, wv.x, acc[1][0]); acc[1][1] = fmaf(ev.y, wv.y, acc[1][1]);
        acc[1][2] = fmaf(ev.y, wv.z, acc[1][2]); acc[1][3] = fmaf(ev.y, wv.w, acc[1][3]);
        acc[2][0] = fmaf(ev.z, wv.x, acc[2][0]); acc[2][1] = fmaf(ev.z, wv.y, acc[2][1]);
        acc[2][2] = fmaf(ev.z, wv.z, acc[2][2]); acc[2][3] = fmaf(ev.z, wv.w, acc[2][3]);
        acc[3][0] = fmaf(ev.w, wv.x, acc[3][0]); acc[3][1] = fmaf(ev.w, wv.y, acc[3][1]);
        acc[3][2] = fmaf(ev.w, wv.z, acc[3][2]); acc[3][3] = fmaf(ev.w, wv.w, acc[3][3]);
    }
    #pragma unroll
    for (int ii = 0; ii < 4; ii++) {
        int eg = blockIdx.x * 32 + 4 * i + ii;
        if (eg < ne) {
            float4* yp = (float4*)(g_y + (size_t)eg * 64 + 4 * j);
            float4 old = *yp;
            old.x = fmaxf(old.x, acc[ii][0]);
            old.y = fmaxf(old.y, acc[ii][1]);
            old.z = fmaxf(old.z, acc[ii][2]);
            old.w = fmaxf(old.w, acc[ii][3]);
            *yp = old;
        }
    }
}

// ---------------------------------------------------------------------------
// head: out = w3^T relu(w2^T relu(w1^T x + b1) + b2)
// 16 nodes/block, 16 threads/node, 4 cols/thread, shuffle-reduce
// ---------------------------------------------------------------------------
__global__ __launch_bounds__(256) void k_out(
        const float* __restrict__ w1, const float* __restrict__ b1,
        const float* __restrict__ w2, const float* __restrict__ b2,
        const float* __restrict__ w3, float* __restrict__ out,
        int buf, int n) {
    __shared__ float x_s[16][68];
    __shared__ float h_s[16][68];
    int g = threadIdx.x >> 4, tt = threadIdx.x & 15;
    int node = blockIdx.x * 16 + g;
    *(float4*)(&x_s[g][4 * tt]) = *(const float4*)(g_x[buf] + (size_t)node * 64 + 4 * tt);
    __syncthreads();
    const float4* w1v = (const float4*)w1;
    float4 acc = *(const float4*)(b1 + 4 * tt);
    #pragma unroll 8
    for (int k = 0; k < 64; k++) {
        float sv = x_s[g][k];
        float4 w = w1v[k * 16 + tt];
        acc.x = fmaf(sv, w.x, acc.x);
        acc.y = fmaf(sv, w.y, acc.y);
        acc.z = fmaf(sv, w.z, acc.z);
        acc.w = fmaf(sv, w.w, acc.w);
    }
    *(float4*)(&h_s[g][4 * tt]) = make_float4(fmaxf(acc.x, 0.f), fmaxf(acc.y, 0.f),
                                              fmaxf(acc.z, 0.f), fmaxf(acc.w, 0.f));
    __syncthreads();
    const float4* w2v = (const float4*)w2;
    float4 o = *(const float4*)(b2 + 4 * tt);
    #pragma unroll 8
    for (int k = 0; k < 64; k++) {
        float sv = h_s[g][k];
        float4 w = w2v[k * 16 + tt];
        o.x = fmaf(sv, w.x, o.x);
        o.y = fmaf(sv, w.y, o.y);
        o.z = fmaf(sv, w.z, o.z);
        o.w = fmaf(sv, w.w, o.w);
    }
    float4 w3v = *(const float4*)(w3 + 4 * tt);
    float p = fmaxf(o.x, 0.f) * w3v.x + fmaxf(o.y, 0.f) * w3v.y
            + fmaxf(o.z, 0.f) * w3v.z + fmaxf(o.w, 0.f) * w3v.w;
    #pragma unroll
    for (int sh = 8; sh > 0; sh >>= 1)
        p += __shfl_xor_sync(0xffffffffu, p, sh, 16);
    if (tt == 0) out[node] = p;
}

// ---------------------------------------------------------------------------
extern "C" void kernel_launch(void* const* d_in, const int* in_sizes, int n_in,
                              void* d_out, int out_size) {
    const float* v      = (const float*)d_in[0];
    const float* labels = (const float*)d_in[1];
    const int*   ei     = (const int*)d_in[2];
    // d_in[3] = loop (fixed at 3; unrolled below)
    const float *hx_w1 = (const float*)d_in[4],  *hx_b1 = (const float*)d_in[5];
    const float *hx_w2 = (const float*)d_in[6],  *hx_b2 = (const float*)d_in[7];
    const float *hy_w1 = (const float*)d_in[8],  *hy_b1 = (const float*)d_in[9];
    const float *hy_w2 = (const float*)d_in[10], *hy_b2 = (const float*)d_in[11];
    const float *fx_w1 = (const float*)d_in[12], *fx_b1 = (const float*)d_in[13];
    const float *fx_w2 = (const float*)d_in[14], *fx_b2 = (const float*)d_in[15];
    const float *fy_w1 = (const float*)d_in[16], *fy_b1 = (const float*)d_in[17];
    const float *fy_w2 = (const float*)d_in[18], *fy_b2 = (const float*)d_in[19];
    const float *fe_w1 = (const float*)d_in[20], *fe_b1 = (const float*)d_in[21];
    const float *fe_w2 = (const float*)d_in[22], *fe_b2 = (const float*)d_in[23];
    const float *fe_w3 = (const float*)d_in[24];

    int n  = in_sizes[0] / 7;       // 50000
    int ne = in_sizes[2] / 2;       // 250000
    float* out = (float*)d_out;

    k_goal<<<1, 1024>>>(v, labels, n);
    k_prep_fx<<<(192 * 64 + 255) / 256, 256>>>(fx_w1);
    k_prep_fy<<<(128 * 64 + 255) / 256, 256>>>(fy_w1);
    k_prep_h<<<37, 64>>>(hy_w1, hx_w1, hx_b1);

    k_x0<<<n / 4, 256>>>(v, labels, hx_w2, hx_b2, n);
    k_y0<<<ne / 16, 256>>>(v, labels, ei, hy_b1, hy_w2, hy_b2, ne);

    int copy_blocks = (n * 16 + 255) / 256;    // n*64/4 float4s
    int eb = (ne + 31) / 32;                    // 7813 blocks

    // iter 1: x_a(0) -> x_b(1)
    k_copy<<<copy_blocks, 256>>>(0, 1, n * 16);
    k_fx<<<eb, 128>>>(ei, fx_b1, fx_w2, fx_b2, 0, 1, ne);
    k_fy<<<eb, 128>>>(ei, fy_b1, fy_w2, fy_b2, 1, ne);
    // iter 2: x_b(1) -> x_a(0)
    k_copy<<<copy_blocks, 256>>>(1, 0, n * 16);
    k_fx<<<eb, 128>>>(ei, fx_b1, fx_w2, fx_b2, 1, 0, ne);
    k_fy<<<eb, 128>>>(ei, fy_b1, fy_w2, fy_b2, 0, ne);
    // iter 3: x_a(0) -> x_b(1)
    k_copy<<<copy_blocks, 256>>>(0, 1, n * 16);
    k_fx<<<eb, 128>>>(ei, fx_b1, fx_w2, fx_b2, 0, 1, ne);
    k_fy<<<eb, 128>>>(ei, fy_b1, fy_w2, fy_b2, 1, ne);

    k_out<<<n / 16, 256>>>(fe_w1, fe_b1, fe_w2, fe_b2, fe_w3, out, 1, n);
}

// round 7
// speedup vs baseline: 1.1960x; 1.1960x over previous
#include <cuda_runtime.h>
#include <cuda_bf16.h>
#include <mma.h>
#include <cstdint>

using namespace nvcuda;

#define NN 50000
#define EE 250000

// ---------------- persistent scratch ----------------
__device__ float g_x[2][(size_t)NN * 64];
__device__ float g_y[(size_t)EE * 64];
__device__ float g_goal[16];
__device__ __nv_bfloat16 g_xbh[2][(size_t)NN * 64];
__device__ __nv_bfloat16 g_xbl[2][(size_t)NN * 64];
__device__ __nv_bfloat16 g_ybh[(size_t)EE * 64];
__device__ __nv_bfloat16 g_ybl[(size_t)EE * 64];
__device__ float g_why[18 * 64];
__device__ float g_whx[18 * 64];
__device__ float g_bhx[64];
// bf16 hi/lo folded weights, layout [seg][j(out 0..63)][k(0..63)]  (col-major B: n x k)
__device__ __nv_bfloat16 g_bfx1h[3 * 64 * 64], g_bfx1l[3 * 64 * 64];
__device__ __nv_bfloat16 g_bfx2h[64 * 64],     g_bfx2l[64 * 64];
__device__ __nv_bfloat16 g_bfy1h[2 * 64 * 64], g_bfy1l[2 * 64 * 64];
__device__ __nv_bfloat16 g_bfy2h[64 * 64],     g_bfy2l[64 * 64];

__device__ __forceinline__ void atomicMaxF(float* addr, float v) {
    if (v >= 0.f) atomicMax((int*)addr, __float_as_int(v));
    else          atomicMin((unsigned int*)addr, __float_as_uint(v));
}
// split 2 floats into packed bf16x2 hi + lo residual (a = low half of word)
__device__ __forceinline__ void split2(float a, float b, uint32_t& h, uint32_t& l) {
    asm("cvt.rn.bf16x2.f32 %0, %1, %2;" : "=r"(h) : "f"(b), "f"(a));
    float ha = __uint_as_float(h << 16);
    float hb = __uint_as_float(h & 0xFFFF0000u);
    float la = a - ha, lb = b - hb;
    asm("cvt.rn.bf16x2.f32 %0, %1, %2;" : "=r"(l) : "f"(lb), "f"(la));
}

// ---------------- goal ----------------
__global__ void k_goal(const float* __restrict__ v,
                       const float* __restrict__ labels, int n) {
    __shared__ float bv[1024];
    __shared__ int   bi[1024];
    float best = -1e30f; int bidx = 0;
    for (int i = threadIdx.x; i < n; i += 1024) {
        float val = labels[2 * i + 1];
        if (val > best) { best = val; bidx = i; }
    }
    bv[threadIdx.x] = best; bi[threadIdx.x] = bidx;
    __syncthreads();
    for (int s = 512; s > 0; s >>= 1) {
        if (threadIdx.x < s) {
            float ov = bv[threadIdx.x + s]; int oi = bi[threadIdx.x + s];
            if (ov > bv[threadIdx.x] || (ov == bv[threadIdx.x] && oi < bi[threadIdx.x])) {
                bv[threadIdx.x] = ov; bi[threadIdx.x] = oi;
            }
        }
        __syncthreads();
    }
    if (threadIdx.x == 0) {
        int g = bi[0];
        #pragma unroll
        for (int c = 0; c < 7; c++) g_goal[c] = v[g * 7 + c];
        g_goal[7] = labels[2 * g];
        g_goal[8] = labels[2 * g + 1];
    }
}

// ---------------- fp32 folds for hx/hy ----------------
__global__ void k_prep_h(const float* __restrict__ hyw1,
                         const float* __restrict__ hxw1,
                         const float* __restrict__ hxb1) {
    int idx = blockIdx.x * 64 + threadIdx.x;
    if (idx < 1152) {
        int k = idx >> 6, j = idx & 63;
        float o;
        if (k < 9) o = hyw1[k * 64 + j] + hyw1[(9 + k) * 64 + j];
        else       o = hyw1[(9 + k) * 64 + j] - hyw1[(k - 9) * 64 + j];
        g_why[idx] = o;
    } else if (idx < 2304) {
        int r = idx - 1152;
        int k = r >> 6, j = r & 63;
        float o;
        if (k < 9) o = hxw1[k * 64 + j] + hxw1[(18 + k) * 64 + j];
        else       o = hxw1[(18 + k) * 64 + j];
        g_whx[r] = o;
    } else if (idx < 2368) {
        int j = idx - 2304;
        float acc = hxb1[j];
        #pragma unroll
        for (int c = 0; c < 9; c++)
            acc += g_goal[c] * (hxw1[(9 + c) * 64 + j] - hxw1[(18 + c) * 64 + j]);
        g_bhx[j] = acc;
    }
}

// ---------------- bf16 weight preps (fold + transpose + split) ----------------
__global__ void k_prep_fxw(const float* __restrict__ w1, const float* __restrict__ w2) {
    int idx = blockIdx.x * 256 + threadIdx.x;
    if (idx < 12288) {
        int seg = idx >> 12, r = idx & 4095, j = r >> 6, k = r & 63;
        int kg = seg * 64 + k;
        float c;
        if (kg < 64)       c = w1[(64 + kg) * 64 + j] + w1[kg * 64 + j];
        else if (kg < 128) c = w1[(64 + kg) * 64 + j] - w1[(kg - 64) * 64 + j];
        else               c = w1[(64 + kg) * 64 + j];
        __nv_bfloat16 h = __float2bfloat16(c);
        g_bfx1h[idx] = h;
        g_bfx1l[idx] = __float2bfloat16(c - __bfloat162float(h));
    } else if (idx < 16384) {
        int r = idx - 12288, j = r >> 6, k = r & 63;
        float c = w2[k * 64 + j];
        __nv_bfloat16 h = __float2bfloat16(c);
        g_bfx2h[r] = h;
        g_bfx2l[r] = __float2bfloat16(c - __bfloat162float(h));
    }
}
__global__ void k_prep_fyw(const float* __restrict__ w1, const float* __restrict__ w2) {
    int idx = blockIdx.x * 256 + threadIdx.x;
    if (idx < 8192) {
        int seg = idx >> 12, r = idx & 4095, j = r >> 6, k = r & 63;
        int kg = seg * 64 + k;
        float c;
        if (kg < 64) c = w1[kg * 64 + j] + w1[(64 + kg) * 64 + j];
        else         c = w1[(64 + kg) * 64 + j] - w1[(kg - 64) * 64 + j];
        __nv_bfloat16 h = __float2bfloat16(c);
        g_bfy1h[idx] = h;
        g_bfy1l[idx] = __float2bfloat16(c - __bfloat162float(h));
    } else if (idx < 12288) {
        int r = idx - 8192, j = r >> 6, k = r & 63;
        float c = w2[k * 64 + j];
        __nv_bfloat16 h = __float2bfloat16(c);
        g_bfy2h[r] = h;
        g_bfy2l[r] = __float2bfloat16(c - __bfloat162float(h));
    }
}

// ---------------- x0 / y0 (fp32) ----------------
__global__ void k_x0(const float* __restrict__ v, const float* __restrict__ labels,
                     const float* __restrict__ w2, const float* __restrict__ b2, int n) {
    __shared__ float in_s[4][18];
    __shared__ float h_s[4][64];
    int g = threadIdx.x >> 6, j = threadIdx.x & 63;
    int node = blockIdx.x * 4 + g;
    if (j < 9) {
        float vc = (j < 7) ? v[node * 7 + j] : labels[node * 2 + (j - 7)];
        float d  = vc - g_goal[j];
        in_s[g][j]     = vc;
        in_s[g][9 + j] = d * d;
    }
    __syncthreads();
    {
        float acc = g_bhx[j];
        #pragma unroll
        for (int k = 0; k < 18; k++) acc = fmaf(in_s[g][k], g_whx[k * 64 + j], acc);
        h_s[g][j] = fmaxf(acc, 0.f);
    }
    __syncthreads();
    {
        float acc = b2[j];
        #pragma unroll
        for (int k = 0; k < 64; k++) acc = fmaf(h_s[g][k], w2[k * 64 + j], acc);
        g_x[0][(size_t)node * 64 + j] = acc;
    }
}

__global__ __launch_bounds__(256) void k_y0(
        const float* __restrict__ v, const float* __restrict__ labels,
        const int* __restrict__ ei,
        const float* __restrict__ b1,
        const float* __restrict__ w2, const float* __restrict__ b2, int ne) {
    __shared__ float in_s[16][20];
    __shared__ float h_s[16][68];
    int g = threadIdx.x >> 4, tt = threadIdx.x & 15;
    int e = blockIdx.x * 16 + g;
    if (tt < 9) {
        int s = ei[e], d = ei[ne + e];
        float vi = (tt < 7) ? v[s * 7 + tt] : labels[s * 2 + (tt - 7)];
        float vj = (tt < 7) ? v[d * 7 + tt] : labels[d * 2 + (tt - 7)];
        in_s[g][tt]     = vj;
        in_s[g][9 + tt] = vi;
    }
    __syncthreads();
    const float4* w1v = (const float4*)g_why;
    float4 acc = *(const float4*)(b1 + 4 * tt);
    #pragma unroll
    for (int k = 0; k < 18; k++) {
        float sv = in_s[g][k];
        float4 w = w1v[k * 16 + tt];
        acc.x = fmaf(sv, w.x, acc.x);
        acc.y = fmaf(sv, w.y, acc.y);
        acc.z = fmaf(sv, w.z, acc.z);
        acc.w = fmaf(sv, w.w, acc.w);
    }
    *(float4*)(&h_s[g][4 * tt]) = make_float4(fmaxf(acc.x, 0.f), fmaxf(acc.y, 0.f),
                                              fmaxf(acc.z, 0.f), fmaxf(acc.w, 0.f));
    __syncthreads();
    const float4* w2v = (const float4*)w2;
    float4 o = *(const float4*)(b2 + 4 * tt);
    #pragma unroll 8
    for (int k = 0; k < 64; k++) {
        float sv = h_s[g][k];
        float4 w = w2v[k * 16 + tt];
        o.x = fmaf(sv, w.x, o.x);
        o.y = fmaf(sv, w.y, o.y);
        o.z = fmaf(sv, w.z, o.z);
        o.w = fmaf(sv, w.w, o.w);
    }
    *(float4*)(g_y + (size_t)e * 64 + 4 * tt) = o;
}

// ---------------- converts + copy ----------------
__global__ void k_cvt_x(int buf, int n4) {
    int i = blockIdx.x * 256 + threadIdx.x;
    if (i >= n4) return;
    float4 f = ((const float4*)g_x[buf])[i];
    uint32_t h0, l0, h1, l1;
    split2(f.x, f.y, h0, l0);
    split2(f.z, f.w, h1, l1);
    ((uint2*)g_xbh[buf])[i] = make_uint2(h0, h1);
    ((uint2*)g_xbl[buf])[i] = make_uint2(l0, l1);
}
__global__ void k_cvt_y(int n4) {
    int i = blockIdx.x * 256 + threadIdx.x;
    if (i >= n4) return;
    float4 f = ((const float4*)g_y)[i];
    uint32_t h0, l0, h1, l1;
    split2(f.x, f.y, h0, l0);
    split2(f.z, f.w, h1, l1);
    ((uint2*)g_ybh)[i] = make_uint2(h0, h1);
    ((uint2*)g_ybl)[i] = make_uint2(l0, l1);
}
__global__ void k_copy(int from, int to, int n4) {
    int i = blockIdx.x * blockDim.x + threadIdx.x;
    if (i < n4) ((float4*)g_x[to])[i] = ((const float4*)g_x[from])[i];
}

// ---------------------------------------------------------------------------
// k_edge<KSEG,IS_FX>: persistent wmma bf16 edge-MLP (64 edges/tile, 8 warps).
//   GEMM1: A[64 x KSEG*64] @ W1[KSEG*64 x 64] -> C  (3-product bf16 hi/lo split)
//   GEMM2: relu(C+b1)      @ W2[64 x 64]      -> C
//   IS_FX: segs [x[src], x[dst], y];  ep2: atomicMax into g_x[wbuf][dst]
//   else : segs [x[dst], x[src]];     ep2: y = max(y, .), refresh y mirrors
// ---------------------------------------------------------------------------
template<int KSEG, bool IS_FX>
__global__ __launch_bounds__(256, 2) void k_edge(
        const int* __restrict__ ei,
        const float* __restrict__ b1, const float* __restrict__ b2,
        int rbuf, int wbuf, int ne, int ntiles) {
    extern __shared__ __align__(16) char smem[];
    constexpr int LDA  = KSEG * 64 + 16;          // bf16 elems
    constexpr int SZ_A = 64 * LDA * 2;            // bytes
    constexpr int O_AH = 0, O_AL = SZ_A;
    constexpr int O_HH = 2 * SZ_A;
    constexpr int O_HL = O_HH + 64 * 80 * 2;
    constexpr int O_C  = O_HL + 64 * 80 * 2;      // float [64][80]
    __nv_bfloat16* Ah = (__nv_bfloat16*)(smem + O_AH);
    __nv_bfloat16* Al = (__nv_bfloat16*)(smem + O_AL);
    __nv_bfloat16* Hh = (__nv_bfloat16*)(smem + O_HH);
    __nv_bfloat16* Hl = (__nv_bfloat16*)(smem + O_HL);
    float*         Cs = (float*)(smem + O_C);

    const __nv_bfloat16* W1h = IS_FX ? g_bfx1h : g_bfy1h;
    const __nv_bfloat16* W1l = IS_FX ? g_bfx1l : g_bfy1l;
    const __nv_bfloat16* W2h = IS_FX ? g_bfx2h : g_bfy2h;
    const __nv_bfloat16* W2l = IS_FX ? g_bfx2l : g_bfy2l;

    int tid = threadIdx.x, wid = tid >> 5;
    int mtile = wid >> 1;          // 0..3  (16 edges each)
    int npair = wid & 1;           // 0..1  (two 16-col tiles each)
    int e_loc = tid >> 2, q = tid & 3;

    for (int tile = blockIdx.x; tile < ntiles; tile += gridDim.x) {
        int eg = tile * 64 + e_loc;
        int ec = (eg < ne) ? eg : (ne - 1);
        int s = ei[ec], d = ei[ne + ec];
        {   // ---- stage A (hi/lo), thread (e_loc, q) copies 2 uint4 per seg ----
            const __nv_bfloat16 *xh = g_xbh[rbuf], *xl = g_xbl[rbuf];
            const __nv_bfloat16 *sh[3], *sl[3];
            if (IS_FX) {
                sh[0] = xh + (size_t)s * 64; sh[1] = xh + (size_t)d * 64; sh[2] = g_ybh + (size_t)ec * 64;
                sl[0] = xl + (size_t)s * 64; sl[1] = xl + (size_t)d * 64; sl[2] = g_ybl + (size_t)ec * 64;
            } else {
                sh[0] = xh + (size_t)d * 64; sh[1] = xh + (size_t)s * 64;
                sl[0] = xl + (size_t)d * 64; sl[1] = xl + (size_t)s * 64;
            }
            #pragma unroll
            for (int sg = 0; sg < KSEG; sg++) {
                #pragma unroll
                for (int c = 0; c < 2; c++) {
                    int ch = q * 2 + c;
                    *(uint4*)((char*)Ah + e_loc * (LDA * 2) + sg * 128 + ch * 16) = ((const uint4*)sh[sg])[ch];
                    *(uint4*)((char*)Al + e_loc * (LDA * 2) + sg * 128 + ch * 16) = ((const uint4*)sl[sg])[ch];
                }
            }
        }
        __syncthreads();

        {   // ---- GEMM1 ----
            wmma::fragment<wmma::accumulator, 16, 16, 16, float> acc[2];
            wmma::fill_fragment(acc[0], 0.f);
            wmma::fill_fragment(acc[1], 0.f);
            for (int kt = 0; kt < KSEG * 4; kt++) {
                wmma::fragment<wmma::matrix_a, 16, 16, 16, __nv_bfloat16, wmma::row_major> fah, fal;
                wmma::load_matrix_sync(fah, Ah + mtile * 16 * LDA + kt * 16, LDA);
                wmma::load_matrix_sync(fal, Al + mtile * 16 * LDA + kt * 16, LDA);
                int sg = kt >> 2, kl = (kt & 3) * 16;
                #pragma unroll
                for (int t = 0; t < 2; t++) {
                    int n0 = (npair * 2 + t) * 16;
                    wmma::fragment<wmma::matrix_b, 16, 16, 16, __nv_bfloat16, wmma::col_major> fbh, fbl;
                    wmma::load_matrix_sync(fbh, W1h + sg * 4096 + n0 * 64 + kl, 64);
                    wmma::load_matrix_sync(fbl, W1l + sg * 4096 + n0 * 64 + kl, 64);
                    wmma::mma_sync(acc[t], fah, fbh, acc[t]);
                    wmma::mma_sync(acc[t], fah, fbl, acc[t]);
                    wmma::mma_sync(acc[t], fal, fbh, acc[t]);
                }
            }
            #pragma unroll
            for (int t = 0; t < 2; t++)
                wmma::store_matrix_sync(Cs + mtile * 16 * 80 + (npair * 2 + t) * 16,
                                        acc[t], 80, wmma::mem_row_major);
        }
        __syncthreads();

        {   // ---- ep1: hidden = relu(C + b1) -> split hi/lo ----
            int c0 = q * 16;
            #pragma unroll
            for (int i = 0; i < 8; i++) {
                int c = c0 + 2 * i;
                float f0 = fmaxf(Cs[e_loc * 80 + c]     + __ldg(b1 + c),     0.f);
                float f1 = fmaxf(Cs[e_loc * 80 + c + 1] + __ldg(b1 + c + 1), 0.f);
                uint32_t hh, ll; split2(f0, f1, hh, ll);
                *(uint32_t*)((char*)Hh + (e_loc * 80 + c) * 2) = hh;
                *(uint32_t*)((char*)Hl + (e_loc * 80 + c) * 2) = ll;
            }
        }
        __syncthreads();

        {   // ---- GEMM2 ----
            wmma::fragment<wmma::accumulator, 16, 16, 16, float> acc[2];
            wmma::fill_fragment(acc[0], 0.f);
            wmma::fill_fragment(acc[1], 0.f);
            for (int kt = 0; kt < 4; kt++) {
                wmma::fragment<wmma::matrix_a, 16, 16, 16, __nv_bfloat16, wmma::row_major> fah, fal;
                wmma::load_matrix_sync(fah, Hh + mtile * 16 * 80 + kt * 16, 80);
                wmma::load_matrix_sync(fal, Hl + mtile * 16 * 80 + kt * 16, 80);
                #pragma unroll
                for (int t = 0; t < 2; t++) {
                    int n0 = (npair * 2 + t) * 16;
                    wmma::fragment<wmma::matrix_b, 16, 16, 16, __nv_bfloat16, wmma::col_major> fbh, fbl;
                    wmma::load_matrix_sync(fbh, W2h + n0 * 64 + kt * 16, 64);
                    wmma::load_matrix_sync(fbl, W2l + n0 * 64 + kt * 16, 64);
                    wmma::mma_sync(acc[t], fah, fbh, acc[t]);
                    wmma::mma_sync(acc[t], fah, fbl, acc[t]);
                    wmma::mma_sync(acc[t], fal, fbh, acc[t]);
                }
            }
            #pragma unroll
            for (int t = 0; t < 2; t++)
                wmma::store_matrix_sync(Cs + mtile * 16 * 80 + (npair * 2 + t) * 16,
                                        acc[t], 80, wmma::mem_row_major);
        }
        __syncthreads();

        if (eg < ne) {   // ---- ep2 ----
            int c0 = q * 16;
            if (IS_FX) {
                float* dp = g_x[wbuf] + (size_t)d * 64;
                #pragma unroll
                for (int c = c0; c < c0 + 16; c++)
                    atomicMaxF(dp + c, Cs[e_loc * 80 + c] + __ldg(b2 + c));
            } else {
                float* yp = g_y + (size_t)eg * 64;
                uint32_t* mh = (uint32_t*)(g_ybh + (size_t)eg * 64 + c0);
                uint32_t* ml = (uint32_t*)(g_ybl + (size_t)eg * 64 + c0);
                #pragma unroll
                for (int i = 0; i < 8; i++) {
                    int c = c0 + 2 * i;
                    float f0 = fmaxf(yp[c],     Cs[e_loc * 80 + c]     + __ldg(b2 + c));
                    float f1 = fmaxf(yp[c + 1], Cs[e_loc * 80 + c + 1] + __ldg(b2 + c + 1));
                    yp[c] = f0; yp[c + 1] = f1;
                    uint32_t hh, ll; split2(f0, f1, hh, ll);
                    mh[i] = hh; ml[i] = ll;
                }
            }
        }
        __syncthreads();
    }
}

// ---------------- head ----------------
__global__ __launch_bounds__(256) void k_out(
        const float* __restrict__ w1, const float* __restrict__ b1,
        const float* __restrict__ w2, const float* __restrict__ b2,
        const float* __restrict__ w3, float* __restrict__ out,
        int buf, int n) {
    __shared__ float x_s[16][68];
    __shared__ float h_s[16][68];
    int g = threadIdx.x >> 4, tt = threadIdx.x & 15;
    int node = blockIdx.x * 16 + g;
    *(float4*)(&x_s[g][4 * tt]) = *(const float4*)(g_x[buf] + (size_t)node * 64 + 4 * tt);
    __syncthreads();
    const float4* w1v = (const float4*)w1;
    float4 acc = *(const float4*)(b1 + 4 * tt);
    #pragma unroll 8
    for (int k = 0; k < 64; k++) {
        float sv = x_s[g][k];
        float4 w = w1v[k * 16 + tt];
        acc.x = fmaf(sv, w.x, acc.x);
        acc.y = fmaf(sv, w.y, acc.y);
        acc.z = fmaf(sv, w.z, acc.z);
        acc.w = fmaf(sv, w.w, acc.w);
    }
    *(float4*)(&h_s[g][4 * tt]) = make_float4(fmaxf(acc.x, 0.f), fmaxf(acc.y, 0.f),
                                              fmaxf(acc.z, 0.f), fmaxf(acc.w, 0.f));
    __syncthreads();
    const float4* w2v = (const float4*)w2;
    float4 o = *(const float4*)(b2 + 4 * tt);
    #pragma unroll 8
    for (int k = 0; k < 64; k++) {
        float sv = h_s[g][k];
        float4 w = w2v[k * 16 + tt];
        o.x = fmaf(sv, w.x, o.x);
        o.y = fmaf(sv, w.y, o.y);
        o.z = fmaf(sv, w.z, o.z);
        o.w = fmaf(sv, w.w, o.w);
    }
    float4 w3v = *(const float4*)(w3 + 4 * tt);
    float p = fmaxf(o.x, 0.f) * w3v.x + fmaxf(o.y, 0.f) * w3v.y
            + fmaxf(o.z, 0.f) * w3v.z + fmaxf(o.w, 0.f) * w3v.w;
    #pragma unroll
    for (int sh = 8; sh > 0; sh >>= 1)
        p += __shfl_xor_sync(0xffffffffu, p, sh, 16);
    if (tt == 0) out[node] = p;
}

// ---------------------------------------------------------------------------
extern "C" void kernel_launch(void* const* d_in, const int* in_sizes, int n_in,
                              void* d_out, int out_size) {
    const float* v      = (const float*)d_in[0];
    const float* labels = (const float*)d_in[1];
    const int*   ei     = (const int*)d_in[2];
    const float *hx_w1 = (const float*)d_in[4],  *hx_b1 = (const float*)d_in[5];
    const float *hx_w2 = (const float*)d_in[6],  *hx_b2 = (const float*)d_in[7];
    const float *hy_w1 = (const float*)d_in[8],  *hy_b1 = (const float*)d_in[9];
    const float *hy_w2 = (const float*)d_in[10], *hy_b2 = (const float*)d_in[11];
    const float *fx_w1 = (const float*)d_in[12], *fx_b1 = (const float*)d_in[13];
    const float *fx_w2 = (const float*)d_in[14], *fx_b2 = (const float*)d_in[15];
    const float *fy_w1 = (const float*)d_in[16], *fy_b1 = (const float*)d_in[17];
    const float *fy_w2 = (const float*)d_in[18], *fy_b2 = (const float*)d_in[19];
    const float *fe_w1 = (const float*)d_in[20], *fe_b1 = (const float*)d_in[21];
    const float *fe_w2 = (const float*)d_in[22], *fe_b2 = (const float*)d_in[23];
    const float *fe_w3 = (const float*)d_in[24];

    int n  = in_sizes[0] / 7;       // 50000
    int ne = in_sizes[2] / 2;       // 250000
    float* out = (float*)d_out;

    // dynamic smem: KSEG=3: 2*64*208*2 + 2*64*80*2 + 64*80*4 = 94208
    //               KSEG=2: 2*64*144*2 + 2*64*80*2 + 64*80*4 = 77824
    const int SM_FX = 94208, SM_FY = 77824;
    cudaFuncSetAttribute((const void*)k_edge<3, true>,
                         cudaFuncAttributeMaxDynamicSharedMemorySize, SM_FX);
    cudaFuncSetAttribute((const void*)k_edge<2, false>,
                         cudaFuncAttributeMaxDynamicSharedMemorySize, SM_FY);

    k_goal<<<1, 1024>>>(v, labels, n);
    k_prep_h<<<37, 64>>>(hy_w1, hx_w1, hx_b1);
    k_prep_fxw<<<64, 256>>>(fx_w1, fx_w2);
    k_prep_fyw<<<48, 256>>>(fy_w1, fy_w2);

    k_x0<<<n / 4, 256>>>(v, labels, hx_w2, hx_b2, n);
    k_y0<<<ne / 16, 256>>>(v, labels, ei, hy_b1, hy_w2, hy_b2, ne);
    k_cvt_x<<<(n * 16 + 255) / 256, 256>>>(0, n * 16);
    k_cvt_y<<<(ne * 16 + 255) / 256, 256>>>(ne * 16);

    int copy_blocks = (n * 16 + 255) / 256;
    int ntiles = (ne + 63) / 64;
    const int GRID = 296;

    // iter 1: read x0, write x1
    k_copy<<<copy_blocks, 256>>>(0, 1, n * 16);
    k_edge<3, true><<<GRID, 256, SM_FX>>>(ei, fx_b1, fx_b2, 0, 1, ne, ntiles);
    k_cvt_x<<<(n * 16 + 255) / 256, 256>>>(1, n * 16);
    k_edge<2, false><<<GRID, 256, SM_FY>>>(ei, fy_b1, fy_b2, 1, 0, ne, ntiles);
    // iter 2: read x1, write x0
    k_copy<<<copy_blocks, 256>>>(1, 0, n * 16);
    k_edge<3, true><<<GRID, 256, SM_FX>>>(ei, fx_b1, fx_b2, 1, 0, ne, ntiles);
    k_cvt_x<<<(n * 16 + 255) / 256, 256>>>(0, n * 16);
    k_edge<2, false><<<GRID, 256, SM_FY>>>(ei, fy_b1, fy_b2, 0, 0, ne, ntiles);
    // iter 3: read x0, write x1
    k_copy<<<copy_blocks, 256>>>(0, 1, n * 16);
    k_edge<3, true><<<GRID, 256, SM_FX>>>(ei, fx_b1, fx_b2, 0, 1, ne, ntiles);
    k_cvt_x<<<(n * 16 + 255) / 256, 256>>>(1, n * 16);
    k_edge<2, false><<<GRID, 256, SM_FY>>>(ei, fy_b1, fy_b2, 1, 0, ne, ntiles);

    k_out<<<n / 16, 256>>>(fe_w1, fe_b1, fe_w2, fe_b2, fe_w3, out, 1, n);
}

// round 8
// speedup vs baseline: 1.6637x; 1.3910x over previous
#include <cuda_runtime.h>
#include <cuda_bf16.h>
#include <mma.h>
#include <cstdint>

using namespace nvcuda;

#define NN 50000
#define EE 250000

// ---------------- persistent scratch ----------------
__device__ float g_x[2][(size_t)NN * 64];
__device__ float g_y[(size_t)EE * 64];
__device__ float g_goal[16];
__device__ __nv_bfloat16 g_xbh[2][(size_t)NN * 64];
__device__ __nv_bfloat16 g_xbl[2][(size_t)NN * 64];
__device__ __nv_bfloat16 g_ybh[(size_t)EE * 64];
__device__ __nv_bfloat16 g_ybl[(size_t)EE * 64];
__device__ float g_why[18 * 64];
__device__ float g_whx[18 * 64];
__device__ float g_bhx[64];
// bf16 hi/lo folded weights, layout [seg][j(out 0..63)][k(0..63)]
__device__ __nv_bfloat16 g_bfx1h[3 * 64 * 64], g_bfx1l[3 * 64 * 64];
__device__ __nv_bfloat16 g_bfx2h[64 * 64],     g_bfx2l[64 * 64];
__device__ __nv_bfloat16 g_bfy1h[2 * 64 * 64], g_bfy1l[2 * 64 * 64];
__device__ __nv_bfloat16 g_bfy2h[64 * 64],     g_bfy2l[64 * 64];

__device__ __forceinline__ void atomicMaxF(float* addr, float v) {
    if (v >= 0.f) atomicMax((int*)addr, __float_as_int(v));
    else          atomicMin((unsigned int*)addr, __float_as_uint(v));
}
// split 2 floats into packed bf16x2 hi + lo residual (a = low half of word)
__device__ __forceinline__ void split2(float a, float b, uint32_t& h, uint32_t& l) {
    asm("cvt.rn.bf16x2.f32 %0, %1, %2;" : "=r"(h) : "f"(b), "f"(a));
    float ha = __uint_as_float(h << 16);
    float hb = __uint_as_float(h & 0xFFFF0000u);
    float la = a - ha, lb = b - hb;
    asm("cvt.rn.bf16x2.f32 %0, %1, %2;" : "=r"(l) : "f"(lb), "f"(la));
}

// ---------------- goal ----------------
__global__ void k_goal(const float* __restrict__ v,
                       const float* __restrict__ labels, int n) {
    __shared__ float bv[1024];
    __shared__ int   bi[1024];
    float best = -1e30f; int bidx = 0;
    for (int i = threadIdx.x; i < n; i += 1024) {
        float val = labels[2 * i + 1];
        if (val > best) { best = val; bidx = i; }
    }
    bv[threadIdx.x] = best; bi[threadIdx.x] = bidx;
    __syncthreads();
    for (int s = 512; s > 0; s >>= 1) {
        if (threadIdx.x < s) {
            float ov = bv[threadIdx.x + s]; int oi = bi[threadIdx.x + s];
            if (ov > bv[threadIdx.x] || (ov == bv[threadIdx.x] && oi < bi[threadIdx.x])) {
                bv[threadIdx.x] = ov; bi[threadIdx.x] = oi;
            }
        }
        __syncthreads();
    }
    if (threadIdx.x == 0) {
        int g = bi[0];
        #pragma unroll
        for (int c = 0; c < 7; c++) g_goal[c] = v[g * 7 + c];
        g_goal[7] = labels[2 * g];
        g_goal[8] = labels[2 * g + 1];
    }
}

// ---------------- fp32 folds for hx/hy ----------------
__global__ void k_prep_h(const float* __restrict__ hyw1,
                         const float* __restrict__ hxw1,
                         const float* __restrict__ hxb1) {
    int idx = blockIdx.x * 64 + threadIdx.x;
    if (idx < 1152) {
        int k = idx >> 6, j = idx & 63;
        float o;
        if (k < 9) o = hyw1[k * 64 + j] + hyw1[(9 + k) * 64 + j];
        else       o = hyw1[(9 + k) * 64 + j] - hyw1[(k - 9) * 64 + j];
        g_why[idx] = o;
    } else if (idx < 2304) {
        int r = idx - 1152;
        int k = r >> 6, j = r & 63;
        float o;
        if (k < 9) o = hxw1[k * 64 + j] + hxw1[(18 + k) * 64 + j];
        else       o = hxw1[(18 + k) * 64 + j];
        g_whx[r] = o;
    } else if (idx < 2368) {
        int j = idx - 2304;
        float acc = hxb1[j];
        #pragma unroll
        for (int c = 0; c < 9; c++)
            acc += g_goal[c] * (hxw1[(9 + c) * 64 + j] - hxw1[(18 + c) * 64 + j]);
        g_bhx[j] = acc;
    }
}

// ---------------- bf16 weight preps (fold + transpose + split) ----------------
__global__ void k_prep_fxw(const float* __restrict__ w1, const float* __restrict__ w2) {
    int idx = blockIdx.x * 256 + threadIdx.x;
    if (idx < 12288) {
        int seg = idx >> 12, r = idx & 4095, j = r >> 6, k = r & 63;
        int kg = seg * 64 + k;
        float c;
        if (kg < 64)       c = w1[(64 + kg) * 64 + j] + w1[kg * 64 + j];
        else if (kg < 128) c = w1[(64 + kg) * 64 + j] - w1[(kg - 64) * 64 + j];
        else               c = w1[(64 + kg) * 64 + j];
        __nv_bfloat16 h = __float2bfloat16(c);
        g_bfx1h[idx] = h;
        g_bfx1l[idx] = __float2bfloat16(c - __bfloat162float(h));
    } else if (idx < 16384) {
        int r = idx - 12288, j = r >> 6, k = r & 63;
        float c = w2[k * 64 + j];
        __nv_bfloat16 h = __float2bfloat16(c);
        g_bfx2h[r] = h;
        g_bfx2l[r] = __float2bfloat16(c - __bfloat162float(h));
    }
}
__global__ void k_prep_fyw(const float* __restrict__ w1, const float* __restrict__ w2) {
    int idx = blockIdx.x * 256 + threadIdx.x;
    if (idx < 8192) {
        int seg = idx >> 12, r = idx & 4095, j = r >> 6, k = r & 63;
        int kg = seg * 64 + k;
        float c;
        if (kg < 64) c = w1[kg * 64 + j] + w1[(64 + kg) * 64 + j];
        else         c = w1[(64 + kg) * 64 + j] - w1[(kg - 64) * 64 + j];
        __nv_bfloat16 h = __float2bfloat16(c);
        g_bfy1h[idx] = h;
        g_bfy1l[idx] = __float2bfloat16(c - __bfloat162float(h));
    } else if (idx < 12288) {
        int r = idx - 8192, j = r >> 6, k = r & 63;
        float c = w2[k * 64 + j];
        __nv_bfloat16 h = __float2bfloat16(c);
        g_bfy2h[r] = h;
        g_bfy2l[r] = __float2bfloat16(c - __bfloat162float(h));
    }
}

// ---------------- x0 / y0 (fp32) ----------------
__global__ void k_x0(const float* __restrict__ v, const float* __restrict__ labels,
                     const float* __restrict__ w2, const float* __restrict__ b2, int n) {
    __shared__ float in_s[4][18];
    __shared__ float h_s[4][64];
    int g = threadIdx.x >> 6, j = threadIdx.x & 63;
    int node = blockIdx.x * 4 + g;
    if (j < 9) {
        float vc = (j < 7) ? v[node * 7 + j] : labels[node * 2 + (j - 7)];
        float d  = vc - g_goal[j];
        in_s[g][j]     = vc;
        in_s[g][9 + j] = d * d;
    }
    __syncthreads();
    {
        float acc = g_bhx[j];
        #pragma unroll
        for (int k = 0; k < 18; k++) acc = fmaf(in_s[g][k], g_whx[k * 64 + j], acc);
        h_s[g][j] = fmaxf(acc, 0.f);
    }
    __syncthreads();
    {
        float acc = b2[j];
        #pragma unroll
        for (int k = 0; k < 64; k++) acc = fmaf(h_s[g][k], w2[k * 64 + j], acc);
        g_x[0][(size_t)node * 64 + j] = acc;
    }
}

__global__ __launch_bounds__(256) void k_y0(
        const float* __restrict__ v, const float* __restrict__ labels,
        const int* __restrict__ ei,
        const float* __restrict__ b1,
        const float* __restrict__ w2, const float* __restrict__ b2, int ne) {
    __shared__ float in_s[16][20];
    __shared__ float h_s[16][68];
    int g = threadIdx.x >> 4, tt = threadIdx.x & 15;
    int e = blockIdx.x * 16 + g;
    if (tt < 9) {
        int s = ei[e], d = ei[ne + e];
        float vi = (tt < 7) ? v[s * 7 + tt] : labels[s * 2 + (tt - 7)];
        float vj = (tt < 7) ? v[d * 7 + tt] : labels[d * 2 + (tt - 7)];
        in_s[g][tt]     = vj;
        in_s[g][9 + tt] = vi;
    }
    __syncthreads();
    const float4* w1v = (const float4*)g_why;
    float4 acc = *(const float4*)(b1 + 4 * tt);
    #pragma unroll
    for (int k = 0; k < 18; k++) {
        float sv = in_s[g][k];
        float4 w = w1v[k * 16 + tt];
        acc.x = fmaf(sv, w.x, acc.x);
        acc.y = fmaf(sv, w.y, acc.y);
        acc.z = fmaf(sv, w.z, acc.z);
        acc.w = fmaf(sv, w.w, acc.w);
    }
    *(float4*)(&h_s[g][4 * tt]) = make_float4(fmaxf(acc.x, 0.f), fmaxf(acc.y, 0.f),
                                              fmaxf(acc.z, 0.f), fmaxf(acc.w, 0.f));
    __syncthreads();
    const float4* w2v = (const float4*)w2;
    float4 o = *(const float4*)(b2 + 4 * tt);
    #pragma unroll 8
    for (int k = 0; k < 64; k++) {
        float sv = h_s[g][k];
        float4 w = w2v[k * 16 + tt];
        o.x = fmaf(sv, w.x, o.x);
        o.y = fmaf(sv, w.y, o.y);
        o.z = fmaf(sv, w.z, o.z);
        o.w = fmaf(sv, w.w, o.w);
    }
    *(float4*)(g_y + (size_t)e * 64 + 4 * tt) = o;
}

// ---------------- converts + copy ----------------
__global__ void k_cvt_x(int buf, int n4) {
    int i = blockIdx.x * 256 + threadIdx.x;
    if (i >= n4) return;
    float4 f = ((const float4*)g_x[buf])[i];
    uint32_t h0, l0, h1, l1;
    split2(f.x, f.y, h0, l0);
    split2(f.z, f.w, h1, l1);
    ((uint2*)g_xbh[buf])[i] = make_uint2(h0, h1);
    ((uint2*)g_xbl[buf])[i] = make_uint2(l0, l1);
}
__global__ void k_cvt_y(int n4) {
    int i = blockIdx.x * 256 + threadIdx.x;
    if (i >= n4) return;
    float4 f = ((const float4*)g_y)[i];
    uint32_t h0, l0, h1, l1;
    split2(f.x, f.y, h0, l0);
    split2(f.z, f.w, h1, l1);
    ((uint2*)g_ybh)[i] = make_uint2(h0, h1);
    ((uint2*)g_ybl)[i] = make_uint2(l0, l1);
}
__global__ void k_copy(int from, int to, int n4) {
    int i = blockIdx.x * blockDim.x + threadIdx.x;
    if (i < n4) ((float4*)g_x[to])[i] = ((const float4*)g_x[from])[i];
}

// ---------------------------------------------------------------------------
// k_edge<KSEG,IS_FX>: persistent wmma bf16 edge-MLP.
//   128 edges/tile, 8 warps, each warp a 16x64 output stripe.
//   Weights staged to smem ONCE per CTA; C overlays Ah; H overlays Al.
//   GEMM1: A[128 x KSEG*64] @ W1 -> C   (3-product bf16 hi/lo split)
//   GEMM2: relu(C+b1)       @ W2 -> C
//   IS_FX: segs [x[src], x[dst], y];  ep2: atomicMax into g_x[wbuf][dst]
//   else : segs [x[dst], x[src]];     ep2: y = max(y, .), refresh y mirrors
// ---------------------------------------------------------------------------
template<int KSEG, bool IS_FX>
__global__ __launch_bounds__(256, 1) void k_edge(
        const int* __restrict__ ei,
        const float* __restrict__ b1, const float* __restrict__ b2,
        int rbuf, int wbuf, int ne, int ntiles) {
    extern __shared__ __align__(16) char smem[];
    constexpr int LDA  = (KSEG == 3) ? 216 : 136;  // bf16 elems; conflict-free strides
    constexpr int LDW1 = (KSEG == 3) ? 200 : 136;
    constexpr int LDW2 = 72;
    constexpr int LDC  = LDA / 2;                  // floats (C overlays Ah)
    constexpr int SZ_A  = 128 * LDA * 2;
    constexpr int SZ_W1 = 64 * LDW1 * 2;
    constexpr int SZ_W2 = 64 * LDW2 * 2;
    constexpr int O_AH = 0, O_AL = SZ_A;
    constexpr int O_W1H = 2 * SZ_A, O_W1L = O_W1H + SZ_W1;
    constexpr int O_W2H = O_W1L + SZ_W1, O_W2L = O_W2H + SZ_W2;

    __nv_bfloat16* Ah  = (__nv_bfloat16*)(smem + O_AH);
    __nv_bfloat16* Al  = (__nv_bfloat16*)(smem + O_AL);
    __nv_bfloat16* W1H = (__nv_bfloat16*)(smem + O_W1H);
    __nv_bfloat16* W1L = (__nv_bfloat16*)(smem + O_W1L);
    __nv_bfloat16* W2H = (__nv_bfloat16*)(smem + O_W2H);
    __nv_bfloat16* W2L = (__nv_bfloat16*)(smem + O_W2L);
    float* Cs = (float*)(smem + O_AH);

    int tid = threadIdx.x, wid = tid >> 5;

    // ---- stage weights once (dst layout [n][k], ld LDW) ----
    {
        const uint4* w1h_g = (const uint4*)(IS_FX ? g_bfx1h : g_bfy1h);
        const uint4* w1l_g = (const uint4*)(IS_FX ? g_bfx1l : g_bfy1l);
        const uint4* w2h_g = (const uint4*)(IS_FX ? g_bfx2h : g_bfy2h);
        const uint4* w2l_g = (const uint4*)(IS_FX ? g_bfx2l : g_bfy2l);
        for (int i = tid; i < KSEG * 512; i += 256) {      // uint4 = 8 bf16
            int seg = i >> 9, r = i & 511, j = r >> 3, k8 = (r & 7) * 8;
            int dst = j * LDW1 + seg * 64 + k8;
            *(uint4*)((char*)W1H + dst * 2) = w1h_g[i];
            *(uint4*)((char*)W1L + dst * 2) = w1l_g[i];
        }
        for (int i = tid; i < 512; i += 256) {
            int j = i >> 3, k8 = (i & 7) * 8;
            int dst = j * LDW2 + k8;
            *(uint4*)((char*)W2H + dst * 2) = w2h_g[i];
            *(uint4*)((char*)W2L + dst * 2) = w2l_g[i];
        }
    }
    __syncthreads();

    int e_loc = tid >> 1, half = tid & 1, c0 = half * 32;

    for (int tile = blockIdx.x; tile < ntiles; tile += gridDim.x) {
        int eg = tile * 128 + e_loc;
        int ec = (eg < ne) ? eg : (ne - 1);
        int s = ei[ec], d = ei[ne + ec];
        {   // ---- stage A hi/lo: 2 threads/edge, 4 chunks of 16B per seg each ----
            const __nv_bfloat16 *xh = g_xbh[rbuf], *xl = g_xbl[rbuf];
            const uint4 *sh[3], *sl[3];
            if (IS_FX) {
                sh[0] = (const uint4*)(xh + (size_t)s * 64);
                sh[1] = (const uint4*)(xh + (size_t)d * 64);
                sh[2] = (const uint4*)(g_ybh + (size_t)ec * 64);
                sl[0] = (const uint4*)(xl + (size_t)s * 64);
                sl[1] = (const uint4*)(xl + (size_t)d * 64);
                sl[2] = (const uint4*)(g_ybl + (size_t)ec * 64);
            } else {
                sh[0] = (const uint4*)(xh + (size_t)d * 64);
                sh[1] = (const uint4*)(xh + (size_t)s * 64);
                sl[0] = (const uint4*)(xl + (size_t)d * 64);
                sl[1] = (const uint4*)(xl + (size_t)s * 64);
            }
            #pragma unroll
            for (int sg = 0; sg < KSEG; sg++) {
                #pragma unroll
                for (int c = 0; c < 4; c++) {
                    int ch = half * 4 + c;
                    *(uint4*)((char*)Ah + e_loc * (LDA * 2) + sg * 128 + ch * 16) = sh[sg][ch];
                    *(uint4*)((char*)Al + e_loc * (LDA * 2) + sg * 128 + ch * 16) = sl[sg][ch];
                }
            }
        }
        __syncthreads();

        {   // ---- GEMM1: warp stripe rows 16*wid, cols 0..63 ----
            wmma::fragment<wmma::accumulator, 16, 16, 16, float> acc[4];
            #pragma unroll
            for (int t = 0; t < 4; t++) wmma::fill_fragment(acc[t], 0.f);
            for (int kt = 0; kt < KSEG * 4; kt++) {
                wmma::fragment<wmma::matrix_a, 16, 16, 16, __nv_bfloat16, wmma::row_major> fah, fal;
                wmma::load_matrix_sync(fah, Ah + wid * 16 * LDA + kt * 16, LDA);
                wmma::load_matrix_sync(fal, Al + wid * 16 * LDA + kt * 16, LDA);
                #pragma unroll
                for (int t = 0; t < 4; t++) {
                    wmma::fragment<wmma::matrix_b, 16, 16, 16, __nv_bfloat16, wmma::col_major> fbh, fbl;
                    wmma::load_matrix_sync(fbh, W1H + t * 16 * LDW1 + kt * 16, LDW1);
                    wmma::load_matrix_sync(fbl, W1L + t * 16 * LDW1 + kt * 16, LDW1);
                    wmma::mma_sync(acc[t], fah, fbh, acc[t]);
                    wmma::mma_sync(acc[t], fah, fbl, acc[t]);
                    wmma::mma_sync(acc[t], fal, fbh, acc[t]);
                }
            }
            #pragma unroll
            for (int t = 0; t < 4; t++)
                wmma::store_matrix_sync(Cs + wid * 16 * LDC + t * 16, acc[t], LDC,
                                        wmma::mem_row_major);
        }
        __syncthreads();

        {   // ---- ep1: hidden = relu(C + b1) -> split hi/lo into Al region ----
            const float* Crow = Cs + e_loc * LDC;
            char* hrow = (char*)Al + e_loc * (LDA * 2);
            #pragma unroll
            for (int i = 0; i < 16; i++) {
                int c = c0 + 2 * i;
                float f0 = fmaxf(Crow[c]     + __ldg(b1 + c),     0.f);
                float f1 = fmaxf(Crow[c + 1] + __ldg(b1 + c + 1), 0.f);
                uint32_t hh, ll; split2(f0, f1, hh, ll);
                *(uint32_t*)(hrow + c * 2)       = hh;   // Hh: elems 0..63
                *(uint32_t*)(hrow + 128 + c * 2) = ll;   // Hl: elems 64..127
            }
        }
        __syncthreads();

        {   // ---- GEMM2 ----
            wmma::fragment<wmma::accumulator, 16, 16, 16, float> acc[4];
            #pragma unroll
            for (int t = 0; t < 4; t++) wmma::fill_fragment(acc[t], 0.f);
            #pragma unroll
            for (int kt = 0; kt < 4; kt++) {
                wmma::fragment<wmma::matrix_a, 16, 16, 16, __nv_bfloat16, wmma::row_major> fah, fal;
                wmma::load_matrix_sync(fah, Al + wid * 16 * LDA + kt * 16, LDA);
                wmma::load_matrix_sync(fal, Al + 64 + wid * 16 * LDA + kt * 16, LDA);
                #pragma unroll
                for (int t = 0; t < 4; t++) {
                    wmma::fragment<wmma::matrix_b, 16, 16, 16, __nv_bfloat16, wmma::col_major> fbh, fbl;
                    wmma::load_matrix_sync(fbh, W2H + t * 16 * LDW2 + kt * 16, LDW2);
                    wmma::load_matrix_sync(fbl, W2L + t * 16 * LDW2 + kt * 16, LDW2);
                    wmma::mma_sync(acc[t], fah, fbh, acc[t]);
                    wmma::mma_sync(acc[t], fah, fbl, acc[t]);
                    wmma::mma_sync(acc[t], fal, fbh, acc[t]);
                }
            }
            #pragma unroll
            for (int t = 0; t < 4; t++)
                wmma::store_matrix_sync(Cs + wid * 16 * LDC + t * 16, acc[t], LDC,
                                        wmma::mem_row_major);
        }
        __syncthreads();

        if (eg < ne) {   // ---- ep2 ----
            const float* Crow = Cs + e_loc * LDC;
            if (IS_FX) {
                float* dp = g_x[wbuf] + (size_t)d * 64;
                #pragma unroll
                for (int c = c0; c < c0 + 32; c++)
                    atomicMaxF(dp + c, Crow[c] + __ldg(b2 + c));
            } else {
                float* yp = g_y + (size_t)eg * 64;
                uint32_t* mh = (uint32_t*)(g_ybh + (size_t)eg * 64 + c0);
                uint32_t* ml = (uint32_t*)(g_ybl + (size_t)eg * 64 + c0);
                #pragma unroll
                for (int i = 0; i < 16; i++) {
                    int c = c0 + 2 * i;
                    float f0 = fmaxf(yp[c],     Crow[c]     + __ldg(b2 + c));
                    float f1 = fmaxf(yp[c + 1], Crow[c + 1] + __ldg(b2 + c + 1));
                    yp[c] = f0; yp[c + 1] = f1;
                    uint32_t hh, ll; split2(f0, f1, hh, ll);
                    mh[i] = hh; ml[i] = ll;
                }
            }
        }
        __syncthreads();
    }
}

// ---------------- head ----------------
__global__ __launch_bounds__(256) void k_out(
        const float* __restrict__ w1, const float* __restrict__ b1,
        const float* __restrict__ w2, const float* __restrict__ b2,
        const float* __restrict__ w3, float* __restrict__ out,
        int buf, int n) {
    __shared__ float x_s[16][68];
    __shared__ float h_s[16][68];
    int g = threadIdx.x >> 4, tt = threadIdx.x & 15;
    int node = blockIdx.x * 16 + g;
    *(float4*)(&x_s[g][4 * tt]) = *(const float4*)(g_x[buf] + (size_t)node * 64 + 4 * tt);
    __syncthreads();
    const float4* w1v = (const float4*)w1;
    float4 acc = *(const float4*)(b1 + 4 * tt);
    #pragma unroll 8
    for (int k = 0; k < 64; k++) {
        float sv = x_s[g][k];
        float4 w = w1v[k * 16 + tt];
        acc.x = fmaf(sv, w.x, acc.x);
        acc.y = fmaf(sv, w.y, acc.y);
        acc.z = fmaf(sv, w.z, acc.z);
        acc.w = fmaf(sv, w.w, acc.w);
    }
    *(float4*)(&h_s[g][4 * tt]) = make_float4(fmaxf(acc.x, 0.f), fmaxf(acc.y, 0.f),
                                              fmaxf(acc.z, 0.f), fmaxf(acc.w, 0.f));
    __syncthreads();
    const float4* w2v = (const float4*)w2;
    float4 o = *(const float4*)(b2 + 4 * tt);
    #pragma unroll 8
    for (int k = 0; k < 64; k++) {
        float sv = h_s[g][k];
        float4 w = w2v[k * 16 + tt];
        o.x = fmaf(sv, w.x, o.x);
        o.y = fmaf(sv, w.y, o.y);
        o.z = fmaf(sv, w.z, o.z);
        o.w = fmaf(sv, w.w, o.w);
    }
    float4 w3v = *(const float4*)(w3 + 4 * tt);
    float p = fmaxf(o.x, 0.f) * w3v.x + fmaxf(o.y, 0.f) * w3v.y
            + fmaxf(o.z, 0.f) * w3v.z + fmaxf(o.w, 0.f) * w3v.w;
    #pragma unroll
    for (int sh = 8; sh > 0; sh >>= 1)
        p += __shfl_xor_sync(0xffffffffu, p, sh, 16);
    if (tt == 0) out[node] = p;
}

// ---------------------------------------------------------------------------
extern "C" void kernel_launch(void* const* d_in, const int* in_sizes, int n_in,
                              void* d_out, int out_size) {
    const float* v      = (const float*)d_in[0];
    const float* labels = (const float*)d_in[1];
    const int*   ei     = (const int*)d_in[2];
    const float *hx_w1 = (const float*)d_in[4],  *hx_b1 = (const float*)d_in[5];
    const float *hx_w2 = (const float*)d_in[6],  *hx_b2 = (const float*)d_in[7];
    const float *hy_w1 = (const float*)d_in[8],  *hy_b1 = (const float*)d_in[9];
    const float *hy_w2 = (const float*)d_in[10], *hy_b2 = (const float*)d_in[11];
    const float *fx_w1 = (const float*)d_in[12], *fx_b1 = (const float*)d_in[13];
    const float *fx_w2 = (const float*)d_in[14], *fx_b2 = (const float*)d_in[15];
    const float *fy_w1 = (const float*)d_in[16], *fy_b1 = (const float*)d_in[17];
    const float *fy_w2 = (const float*)d_in[18], *fy_b2 = (const float*)d_in[19];
    const float *fe_w1 = (const float*)d_in[20], *fe_b1 = (const float*)d_in[21];
    const float *fe_w2 = (const float*)d_in[22], *fe_b2 = (const float*)d_in[23];
    const float *fe_w3 = (const float*)d_in[24];

    int n  = in_sizes[0] / 7;       // 50000
    int ne = in_sizes[2] / 2;       // 250000
    float* out = (float*)d_out;

    // smem: fx: 2*128*216*2 + 2*64*200*2 + 2*64*72*2 = 110592+51200+18432 = 180224
    //       fy: 2*128*136*2 + 2*64*136*2 + 2*64*72*2 =  69632+34816+18432 = 122880
    const int SM_FX = 180224, SM_FY = 122880;
    cudaFuncSetAttribute((const void*)k_edge<3, true>,
                         cudaFuncAttributeMaxDynamicSharedMemorySize, SM_FX);
    cudaFuncSetAttribute((const void*)k_edge<2, false>,
                         cudaFuncAttributeMaxDynamicSharedMemorySize, SM_FY);

    k_goal<<<1, 1024>>>(v, labels, n);
    k_prep_h<<<37, 64>>>(hy_w1, hx_w1, hx_b1);
    k_prep_fxw<<<64, 256>>>(fx_w1, fx_w2);
    k_prep_fyw<<<48, 256>>>(fy_w1, fy_w2);

    k_x0<<<n / 4, 256>>>(v, labels, hx_w2, hx_b2, n);
    k_y0<<<ne / 16, 256>>>(v, labels, ei, hy_b1, hy_w2, hy_b2, ne);
    k_cvt_x<<<(n * 16 + 255) / 256, 256>>>(0, n * 16);
    k_cvt_y<<<(ne * 16 + 255) / 256, 256>>>(ne * 16);

    int copy_blocks = (n * 16 + 255) / 256;
    int ntiles = (ne + 127) / 128;
    const int GRID = 148;

    // iter 1: read x0, write x1
    k_copy<<<copy_blocks, 256>>>(0, 1, n * 16);
    k_edge<3, true><<<GRID, 256, SM_FX>>>(ei, fx_b1, fx_b2, 0, 1, ne, ntiles);
    k_cvt_x<<<(n * 16 + 255) / 256, 256>>>(1, n * 16);
    k_edge<2, false><<<GRID, 256, SM_FY>>>(ei, fy_b1, fy_b2, 1, 0, ne, ntiles);
    // iter 2: read x1, write x0
    k_copy<<<copy_blocks, 256>>>(1, 0, n * 16);
    k_edge<3, true><<<GRID, 256, SM_FX>>>(ei, fx_b1, fx_b2, 1, 0, ne, ntiles);
    k_cvt_x<<<(n * 16 + 255) / 256, 256>>>(0, n * 16);
    k_edge<2, false><<<GRID, 256, SM_FY>>>(ei, fy_b1, fy_b2, 0, 0, ne, ntiles);
    // iter 3: read x0, write x1
    k_copy<<<copy_blocks, 256>>>(0, 1, n * 16);
    k_edge<3, true><<<GRID, 256, SM_FX>>>(ei, fx_b1, fx_b2, 0, 1, ne, ntiles);
    k_cvt_x<<<(n * 16 + 255) / 256, 256>>>(1, n * 16);
    k_edge<2, false><<<GRID, 256, SM_FY>>>(ei, fy_b1, fy_b2, 1, 0, ne, ntiles);

    k_out<<<n / 16, 256>>>(fe_w1, fe_b1, fe_w2, fe_b2, fe_w3, out, 1, n);
}

// round 9
// speedup vs baseline: 1.7922x; 1.0773x over previous
#include <cuda_runtime.h>
#include <cuda_bf16.h>
#include <mma.h>
#include <cstdint>

using namespace nvcuda;

#define NN 50000
#define EE 250000

// ---------------- persistent scratch ----------------
__device__ float g_x[2][(size_t)NN * 64];
__device__ float g_y[(size_t)EE * 64];
__device__ float g_goal[16];
__device__ __nv_bfloat16 g_xbh[2][(size_t)NN * 64];
__device__ __nv_bfloat16 g_xbl[2][(size_t)NN * 64];
__device__ __nv_bfloat16 g_ybh[(size_t)EE * 64];
__device__ __nv_bfloat16 g_ybl[(size_t)EE * 64];
__device__ float g_why[18 * 64];
__device__ float g_whx[18 * 64];
__device__ float g_bhx[64];
// bf16 hi/lo folded weights, layout [seg][j(out 0..63)][k(0..63)]
__device__ __nv_bfloat16 g_bfx1h[3 * 64 * 64], g_bfx1l[3 * 64 * 64];
__device__ __nv_bfloat16 g_bfx2h[64 * 64],     g_bfx2l[64 * 64];
__device__ __nv_bfloat16 g_bfy1h[2 * 64 * 64], g_bfy1l[2 * 64 * 64];
__device__ __nv_bfloat16 g_bfy2h[64 * 64],     g_bfy2l[64 * 64];

__device__ __forceinline__ void atomicMaxF(float* addr, float v) {
    if (v >= 0.f) atomicMax((int*)addr, __float_as_int(v));
    else          atomicMin((unsigned int*)addr, __float_as_uint(v));
}
// split 2 floats into packed bf16x2 hi + lo residual (a = low half of word)
__device__ __forceinline__ void split2(float a, float b, uint32_t& h, uint32_t& l) {
    asm("cvt.rn.bf16x2.f32 %0, %1, %2;" : "=r"(h) : "f"(b), "f"(a));
    float ha = __uint_as_float(h << 16);
    float hb = __uint_as_float(h & 0xFFFF0000u);
    float la = a - ha, lb = b - hb;
    asm("cvt.rn.bf16x2.f32 %0, %1, %2;" : "=r"(l) : "f"(lb), "f"(la));
}

// ---------------- goal ----------------
__global__ void k_goal(const float* __restrict__ v,
                       const float* __restrict__ labels, int n) {
    __shared__ float bv[1024];
    __shared__ int   bi[1024];
    float best = -1e30f; int bidx = 0;
    for (int i = threadIdx.x; i < n; i += 1024) {
        float val = labels[2 * i + 1];
        if (val > best) { best = val; bidx = i; }
    }
    bv[threadIdx.x] = best; bi[threadIdx.x] = bidx;
    __syncthreads();
    for (int s = 512; s > 0; s >>= 1) {
        if (threadIdx.x < s) {
            float ov = bv[threadIdx.x + s]; int oi = bi[threadIdx.x + s];
            if (ov > bv[threadIdx.x] || (ov == bv[threadIdx.x] && oi < bi[threadIdx.x])) {
                bv[threadIdx.x] = ov; bi[threadIdx.x] = oi;
            }
        }
        __syncthreads();
    }
    if (threadIdx.x == 0) {
        int g = bi[0];
        #pragma unroll
        for (int c = 0; c < 7; c++) g_goal[c] = v[g * 7 + c];
        g_goal[7] = labels[2 * g];
        g_goal[8] = labels[2 * g + 1];
    }
}

// ---------------- fp32 folds for hx/hy ----------------
__global__ void k_prep_h(const float* __restrict__ hyw1,
                         const float* __restrict__ hxw1,
                         const float* __restrict__ hxb1) {
    int idx = blockIdx.x * 64 + threadIdx.x;
    if (idx < 1152) {
        int k = idx >> 6, j = idx & 63;
        float o;
        if (k < 9) o = hyw1[k * 64 + j] + hyw1[(9 + k) * 64 + j];
        else       o = hyw1[(9 + k) * 64 + j] - hyw1[(k - 9) * 64 + j];
        g_why[idx] = o;
    } else if (idx < 2304) {
        int r = idx - 1152;
        int k = r >> 6, j = r & 63;
        float o;
        if (k < 9) o = hxw1[k * 64 + j] + hxw1[(18 + k) * 64 + j];
        else       o = hxw1[(18 + k) * 64 + j];
        g_whx[r] = o;
    } else if (idx < 2368) {
        int j = idx - 2304;
        float acc = hxb1[j];
        #pragma unroll
        for (int c = 0; c < 9; c++)
            acc += g_goal[c] * (hxw1[(9 + c) * 64 + j] - hxw1[(18 + c) * 64 + j]);
        g_bhx[j] = acc;
    }
}

// ---------------- bf16 weight preps (fold + transpose + split) ----------------
__global__ void k_prep_fxw(const float* __restrict__ w1, const float* __restrict__ w2) {
    int idx = blockIdx.x * 256 + threadIdx.x;
    if (idx < 12288) {
        int seg = idx >> 12, r = idx & 4095, j = r >> 6, k = r & 63;
        int kg = seg * 64 + k;
        float c;
        if (kg < 64)       c = w1[(64 + kg) * 64 + j] + w1[kg * 64 + j];
        else if (kg < 128) c = w1[(64 + kg) * 64 + j] - w1[(kg - 64) * 64 + j];
        else               c = w1[(64 + kg) * 64 + j];
        __nv_bfloat16 h = __float2bfloat16(c);
        g_bfx1h[idx] = h;
        g_bfx1l[idx] = __float2bfloat16(c - __bfloat162float(h));
    } else if (idx < 16384) {
        int r = idx - 12288, j = r >> 6, k = r & 63;
        float c = w2[k * 64 + j];
        __nv_bfloat16 h = __float2bfloat16(c);
        g_bfx2h[r] = h;
        g_bfx2l[r] = __float2bfloat16(c - __bfloat162float(h));
    }
}
__global__ void k_prep_fyw(const float* __restrict__ w1, const float* __restrict__ w2) {
    int idx = blockIdx.x * 256 + threadIdx.x;
    if (idx < 8192) {
        int seg = idx >> 12, r = idx & 4095, j = r >> 6, k = r & 63;
        int kg = seg * 64 + k;
        float c;
        if (kg < 64) c = w1[kg * 64 + j] + w1[(64 + kg) * 64 + j];
        else         c = w1[(64 + kg) * 64 + j] - w1[(kg - 64) * 64 + j];
        __nv_bfloat16 h = __float2bfloat16(c);
        g_bfy1h[idx] = h;
        g_bfy1l[idx] = __float2bfloat16(c - __bfloat162float(h));
    } else if (idx < 12288) {
        int r = idx - 8192, j = r >> 6, k = r & 63;
        float c = w2[k * 64 + j];
        __nv_bfloat16 h = __float2bfloat16(c);
        g_bfy2h[r] = h;
        g_bfy2l[r] = __float2bfloat16(c - __bfloat162float(h));
    }
}

// ---------------- k_init: x0 (first nx blocks) + y0 (rest), mirrors inline ----
__global__ __launch_bounds__(256) void k_init(
        const float* __restrict__ v, const float* __restrict__ labels,
        const int* __restrict__ ei,
        const float* __restrict__ hxw2, const float* __restrict__ hxb2,
        const float* __restrict__ hyb1,
        const float* __restrict__ hyw2, const float* __restrict__ hyb2,
        int n, int ne, int nx) {
    if ((int)blockIdx.x < nx) {
        // ---- x0: 4 nodes/block, 64 threads/node ----
        __shared__ float in_s[4][18];
        __shared__ float h_s[4][64];
        __shared__ float o_s[4][64];
        int g = threadIdx.x >> 6, j = threadIdx.x & 63;
        int node = blockIdx.x * 4 + g;
        if (j < 9) {
            float vc = (j < 7) ? v[node * 7 + j] : labels[node * 2 + (j - 7)];
            float d  = vc - g_goal[j];
            in_s[g][j]     = vc;
            in_s[g][9 + j] = d * d;
        }
        __syncthreads();
        {
            float acc = g_bhx[j];
            #pragma unroll
            for (int k = 0; k < 18; k++) acc = fmaf(in_s[g][k], g_whx[k * 64 + j], acc);
            h_s[g][j] = fmaxf(acc, 0.f);
        }
        __syncthreads();
        {
            float acc = hxb2[j];
            #pragma unroll
            for (int k = 0; k < 64; k++) acc = fmaf(h_s[g][k], hxw2[k * 64 + j], acc);
            g_x[0][(size_t)node * 64 + j] = acc;
            g_x[1][(size_t)node * 64 + j] = acc;   // seed for iter-1 scatter-max
            o_s[g][j] = acc;
        }
        __syncthreads();
        if (j < 32) {
            uint32_t h, l;
            split2(o_s[g][2 * j], o_s[g][2 * j + 1], h, l);
            ((uint32_t*)(g_xbh[0] + (size_t)node * 64))[j] = h;
            ((uint32_t*)(g_xbl[0] + (size_t)node * 64))[j] = l;
        }
    } else {
        // ---- y0: 16 edges/block, 16 threads/edge ----
        __shared__ float in_s[16][20];
        __shared__ float h_s[16][68];
        int g = threadIdx.x >> 4, tt = threadIdx.x & 15;
        int e = (blockIdx.x - nx) * 16 + g;
        if (tt < 9) {
            int s = ei[e], d = ei[ne + e];
            float vi = (tt < 7) ? v[s * 7 + tt] : labels[s * 2 + (tt - 7)];
            float vj = (tt < 7) ? v[d * 7 + tt] : labels[d * 2 + (tt - 7)];
            in_s[g][tt]     = vj;
            in_s[g][9 + tt] = vi;
        }
        __syncthreads();
        const float4* w1v = (const float4*)g_why;
        float4 acc = *(const float4*)(hyb1 + 4 * tt);
        #pragma unroll
        for (int k = 0; k < 18; k++) {
            float sv = in_s[g][k];
            float4 w = w1v[k * 16 + tt];
            acc.x = fmaf(sv, w.x, acc.x);
            acc.y = fmaf(sv, w.y, acc.y);
            acc.z = fmaf(sv, w.z, acc.z);
            acc.w = fmaf(sv, w.w, acc.w);
        }
        *(float4*)(&h_s[g][4 * tt]) = make_float4(fmaxf(acc.x, 0.f), fmaxf(acc.y, 0.f),
                                                  fmaxf(acc.z, 0.f), fmaxf(acc.w, 0.f));
        __syncthreads();
        const float4* w2v = (const float4*)hyw2;
        float4 o = *(const float4*)(hyb2 + 4 * tt);
        #pragma unroll 8
        for (int k = 0; k < 64; k++) {
            float sv = h_s[g][k];
            float4 w = w2v[k * 16 + tt];
            o.x = fmaf(sv, w.x, o.x);
            o.y = fmaf(sv, w.y, o.y);
            o.z = fmaf(sv, w.z, o.z);
            o.w = fmaf(sv, w.w, o.w);
        }
        *(float4*)(g_y + (size_t)e * 64 + 4 * tt) = o;
        uint32_t h0, l0, h1, l1;
        split2(o.x, o.y, h0, l0);
        split2(o.z, o.w, h1, l1);
        ((uint2*)(g_ybh + (size_t)e * 64))[tt] = make_uint2(h0, h1);
        ((uint2*)(g_ybl + (size_t)e * 64))[tt] = make_uint2(l0, l1);
    }
}

// ---------------- cvtx_seed: mirrors of mbuf (+ optional seed copy) ----------
__global__ void cvtx_seed(int mbuf, int sbuf, int n4) {
    int i = blockIdx.x * 256 + threadIdx.x;
    if (i >= n4) return;
    float4 f = ((const float4*)g_x[mbuf])[i];
    uint32_t h0, l0, h1, l1;
    split2(f.x, f.y, h0, l0);
    split2(f.z, f.w, h1, l1);
    ((uint2*)g_xbh[mbuf])[i] = make_uint2(h0, h1);
    ((uint2*)g_xbl[mbuf])[i] = make_uint2(l0, l1);
    if (sbuf >= 0) ((float4*)g_x[sbuf])[i] = f;
}

// ---------------------------------------------------------------------------
// k_edge<KSEG,IS_FX>: persistent wmma bf16 edge-MLP. 64 edges/tile, 8 warps,
// warp = 16 edges x 32 cols. W1 staged in smem once; W2 read from global (L1).
// C (fp32) overlays Ah; H (hidden hi/lo) overlays Al. 2 CTAs/SM.
// ---------------------------------------------------------------------------
template<int KSEG, bool IS_FX>
__global__ __launch_bounds__(256, 2) void k_edge(
        const int* __restrict__ ei,
        const float* __restrict__ b1, const float* __restrict__ b2,
        int rbuf, int wbuf, int ne, int ntiles) {
    extern __shared__ __align__(16) char smem[];
    constexpr int LDA  = (KSEG == 3) ? 216 : 136;  // bf16 elems, conflict-free
    constexpr int LDW1 = (KSEG == 3) ? 200 : 136;
    constexpr int LDC  = LDA / 2;                  // floats (C overlays Ah)
    constexpr int SZ_A  = 64 * LDA * 2;
    constexpr int SZ_W1 = 64 * LDW1 * 2;
    constexpr int O_AH = 0, O_AL = SZ_A;
    constexpr int O_W1H = 2 * SZ_A, O_W1L = O_W1H + SZ_W1;

    __nv_bfloat16* Ah  = (__nv_bfloat16*)(smem + O_AH);
    __nv_bfloat16* Al  = (__nv_bfloat16*)(smem + O_AL);
    __nv_bfloat16* W1H = (__nv_bfloat16*)(smem + O_W1H);
    __nv_bfloat16* W1L = (__nv_bfloat16*)(smem + O_W1L);
    float* Cs = (float*)(smem + O_AH);

    const __nv_bfloat16* W2H = IS_FX ? g_bfx2h : g_bfy2h;
    const __nv_bfloat16* W2L = IS_FX ? g_bfx2l : g_bfy2l;

    int tid = threadIdx.x, wid = tid >> 5;
    int mq = wid >> 1, nq = wid & 1;               // warp: rows 16*mq, cols 32*nq

    {   // ---- stage W1 once ----
        const uint4* w1h_g = (const uint4*)(IS_FX ? g_bfx1h : g_bfy1h);
        const uint4* w1l_g = (const uint4*)(IS_FX ? g_bfx1l : g_bfy1l);
        for (int i = tid; i < KSEG * 512; i += 256) {  // uint4 = 8 bf16
            int seg = i >> 9, r = i & 511, j = r >> 3, k8 = (r & 7) * 8;
            int dst = j * LDW1 + seg * 64 + k8;
            *(uint4*)((char*)W1H + dst * 2) = w1h_g[i];
            *(uint4*)((char*)W1L + dst * 2) = w1l_g[i];
        }
    }
    __syncthreads();

    int e_loc = tid >> 2, q = tid & 3, c0 = q * 16;

    for (int tile = blockIdx.x; tile < ntiles; tile += gridDim.x) {
        int eg = tile * 64 + e_loc;
        int ec = (eg < ne) ? eg : (ne - 1);
        int s = ei[ec], d = ei[ne + ec];
        {   // ---- stage A hi/lo: 4 threads/edge, 2 chunks of 16B per seg ----
            const __nv_bfloat16 *xh = g_xbh[rbuf], *xl = g_xbl[rbuf];
            const uint4 *sh[3], *sl[3];
            if (IS_FX) {
                sh[0] = (const uint4*)(xh + (size_t)s * 64);
                sh[1] = (const uint4*)(xh + (size_t)d * 64);
                sh[2] = (const uint4*)(g_ybh + (size_t)ec * 64);
                sl[0] = (const uint4*)(xl + (size_t)s * 64);
                sl[1] = (const uint4*)(xl + (size_t)d * 64);
                sl[2] = (const uint4*)(g_ybl + (size_t)ec * 64);
            } else {
                sh[0] = (const uint4*)(xh + (size_t)d * 64);
                sh[1] = (const uint4*)(xh + (size_t)s * 64);
                sl[0] = (const uint4*)(xl + (size_t)d * 64);
                sl[1] = (const uint4*)(xl + (size_t)s * 64);
            }
            #pragma unroll
            for (int sg = 0; sg < KSEG; sg++) {
                #pragma unroll
                for (int c = 0; c < 2; c++) {
                    int ch = q * 2 + c;
                    *(uint4*)((char*)Ah + e_loc * (LDA * 2) + sg * 128 + ch * 16) = sh[sg][ch];
                    *(uint4*)((char*)Al + e_loc * (LDA * 2) + sg * 128 + ch * 16) = sl[sg][ch];
                }
            }
        }
        __syncthreads();

        {   // ---- GEMM1 ----
            wmma::fragment<wmma::accumulator, 16, 16, 16, float> acc[2];
            wmma::fill_fragment(acc[0], 0.f);
            wmma::fill_fragment(acc[1], 0.f);
            for (int kt = 0; kt < KSEG * 4; kt++) {
                wmma::fragment<wmma::matrix_a, 16, 16, 16, __nv_bfloat16, wmma::row_major> fah, fal;
                wmma::load_matrix_sync(fah, Ah + mq * 16 * LDA + kt * 16, LDA);
                wmma::load_matrix_sync(fal, Al + mq * 16 * LDA + kt * 16, LDA);
                #pragma unroll
                for (int t = 0; t < 2; t++) {
                    int nt = nq * 2 + t;
                    wmma::fragment<wmma::matrix_b, 16, 16, 16, __nv_bfloat16, wmma::col_major> fbh, fbl;
                    wmma::load_matrix_sync(fbh, W1H + nt * 16 * LDW1 + kt * 16, LDW1);
                    wmma::load_matrix_sync(fbl, W1L + nt * 16 * LDW1 + kt * 16, LDW1);
                    wmma::mma_sync(acc[t], fah, fbh, acc[t]);
                    wmma::mma_sync(acc[t], fah, fbl, acc[t]);
                    wmma::mma_sync(acc[t], fal, fbh, acc[t]);
                }
            }
            __syncthreads();   // all A reads done before C overlays Ah
            #pragma unroll
            for (int t = 0; t < 2; t++)
                wmma::store_matrix_sync(Cs + mq * 16 * LDC + (nq * 2 + t) * 16,
                                        acc[t], LDC, wmma::mem_row_major);
        }
        __syncthreads();

        {   // ---- ep1: hidden = relu(C + b1) -> split hi/lo into Al region ----
            const float* Crow = Cs + e_loc * LDC;
            char* hrow = (char*)Al + e_loc * (LDA * 2);
            #pragma unroll
            for (int i = 0; i < 8; i++) {
                int c = c0 + 2 * i;
                float f0 = fmaxf(Crow[c]     + __ldg(b1 + c),     0.f);
                float f1 = fmaxf(Crow[c + 1] + __ldg(b1 + c + 1), 0.f);
                uint32_t hh, ll; split2(f0, f1, hh, ll);
                *(uint32_t*)(hrow + c * 2)       = hh;   // Hh: elems 0..63
                *(uint32_t*)(hrow + 128 + c * 2) = ll;   // Hl: elems 64..127
            }
        }
        __syncthreads();

        {   // ---- GEMM2 (A from Al overlay, B from global/L1) ----
            wmma::fragment<wmma::accumulator, 16, 16, 16, float> acc[2];
            wmma::fill_fragment(acc[0], 0.f);
            wmma::fill_fragment(acc[1], 0.f);
            #pragma unroll
            for (int kt = 0; kt < 4; kt++) {
                wmma::fragment<wmma::matrix_a, 16, 16, 16, __nv_bfloat16, wmma::row_major> fah, fal;
                wmma::load_matrix_sync(fah, Al + mq * 16 * LDA + kt * 16, LDA);
                wmma::load_matrix_sync(fal, Al + 64 + mq * 16 * LDA + kt * 16, LDA);
                #pragma unroll
                for (int t = 0; t < 2; t++) {
                    int nt = nq * 2 + t;
                    wmma::fragment<wmma::matrix_b, 16, 16, 16, __nv_bfloat16, wmma::col_major> fbh, fbl;
                    wmma::load_matrix_sync(fbh, W2H + nt * 16 * 64 + kt * 16, 64);
                    wmma::load_matrix_sync(fbl, W2L + nt * 16 * 64 + kt * 16, 64);
                    wmma::mma_sync(acc[t], fah, fbh, acc[t]);
                    wmma::mma_sync(acc[t], fah, fbl, acc[t]);
                    wmma::mma_sync(acc[t], fal, fbh, acc[t]);
                }
            }
            #pragma unroll
            for (int t = 0; t < 2; t++)
                wmma::store_matrix_sync(Cs + mq * 16 * LDC + (nq * 2 + t) * 16,
                                        acc[t], LDC, wmma::mem_row_major);
        }
        __syncthreads();

        if (eg < ne) {   // ---- ep2 ----
            const float* Crow = Cs + e_loc * LDC;
            if (IS_FX) {
                float* dp = g_x[wbuf] + (size_t)d * 64;
                #pragma unroll
                for (int c = c0; c < c0 + 16; c++)
                    atomicMaxF(dp + c, Crow[c] + __ldg(b2 + c));
            } else {
                float* yp = g_y + (size_t)eg * 64;
                uint32_t* mh = (uint32_t*)(g_ybh + (size_t)eg * 64 + c0);
                uint32_t* ml = (uint32_t*)(g_ybl + (size_t)eg * 64 + c0);
                #pragma unroll
                for (int i = 0; i < 8; i++) {
                    int c = c0 + 2 * i;
                    float f0 = fmaxf(yp[c],     Crow[c]     + __ldg(b2 + c));
                    float f1 = fmaxf(yp[c + 1], Crow[c + 1] + __ldg(b2 + c + 1));
                    yp[c] = f0; yp[c + 1] = f1;
                    uint32_t hh, ll; split2(f0, f1, hh, ll);
                    mh[i] = hh; ml[i] = ll;
                }
            }
        }
        __syncthreads();
    }
}

// ---------------- head ----------------
__global__ __launch_bounds__(256) void k_out(
        const float* __restrict__ w1, const float* __restrict__ b1,
        const float* __restrict__ w2, const float* __restrict__ b2,
        const float* __restrict__ w3, float* __restrict__ out,
        int buf, int n) {
    __shared__ float x_s[16][68];
    __shared__ float h_s[16][68];
    int g = threadIdx.x >> 4, tt = threadIdx.x & 15;
    int node = blockIdx.x * 16 + g;
    *(float4*)(&x_s[g][4 * tt]) = *(const float4*)(g_x[buf] + (size_t)node * 64 + 4 * tt);
    __syncthreads();
    const float4* w1v = (const float4*)w1;
    float4 acc = *(const float4*)(b1 + 4 * tt);
    #pragma unroll 8
    for (int k = 0; k < 64; k++) {
        float sv = x_s[g][k];
        float4 w = w1v[k * 16 + tt];
        acc.x = fmaf(sv, w.x, acc.x);
        acc.y = fmaf(sv, w.y, acc.y);
        acc.z = fmaf(sv, w.z, acc.z);
        acc.w = fmaf(sv, w.w, acc.w);
    }
    *(float4*)(&h_s[g][4 * tt]) = make_float4(fmaxf(acc.x, 0.f), fmaxf(acc.y, 0.f),
                                              fmaxf(acc.z, 0.f), fmaxf(acc.w, 0.f));
    __syncthreads();
    const float4* w2v = (const float4*)w2;
    float4 o = *(const float4*)(b2 + 4 * tt);
    #pragma unroll 8
    for (int k = 0; k < 64; k++) {
        float sv = h_s[g][k];
        float4 w = w2v[k * 16 + tt];
        o.x = fmaf(sv, w.x, o.x);
        o.y = fmaf(sv, w.y, o.y);
        o.z = fmaf(sv, w.z, o.z);
        o.w = fmaf(sv, w.w, o.w);
    }
    float4 w3v = *(const float4*)(w3 + 4 * tt);
    float p = fmaxf(o.x, 0.f) * w3v.x + fmaxf(o.y, 0.f) * w3v.y
            + fmaxf(o.z, 0.f) * w3v.z + fmaxf(o.w, 0.f) * w3v.w;
    #pragma unroll
    for (int sh = 8; sh > 0; sh >>= 1)
        p += __shfl_xor_sync(0xffffffffu, p, sh, 16);
    if (tt == 0) out[node] = p;
}

// ---------------------------------------------------------------------------
extern "C" void kernel_launch(void* const* d_in, const int* in_sizes, int n_in,
                              void* d_out, int out_size) {
    const float* v      = (const float*)d_in[0];
    const float* labels = (const float*)d_in[1];
    const int*   ei     = (const int*)d_in[2];
    const float *hx_w1 = (const float*)d_in[4],  *hx_b1 = (const float*)d_in[5];
    const float *hx_w2 = (const float*)d_in[6],  *hx_b2 = (const float*)d_in[7];
    const float *hy_w1 = (const float*)d_in[8],  *hy_b1 = (const float*)d_in[9];
    const float *hy_w2 = (const float*)d_in[10], *hy_b2 = (const float*)d_in[11];
    const float *fx_w1 = (const float*)d_in[12], *fx_b1 = (const float*)d_in[13];
    const float *fx_w2 = (const float*)d_in[14], *fx_b2 = (const float*)d_in[15];
    const float *fy_w1 = (const float*)d_in[16], *fy_b1 = (const float*)d_in[17];
    const float *fy_w2 = (const float*)d_in[18], *fy_b2 = (const float*)d_in[19];
    const float *fe_w1 = (const float*)d_in[20], *fe_b1 = (const float*)d_in[21];
    const float *fe_w2 = (const float*)d_in[22], *fe_b2 = (const float*)d_in[23];
    const float *fe_w3 = (const float*)d_in[24];

    int n  = in_sizes[0] / 7;       // 50000
    int ne = in_sizes[2] / 2;       // 250000
    float* out = (float*)d_out;

    // smem: fx: 2*64*216*2 + 2*64*200*2 = 55296 + 51200 = 106496  (2 CTAs/SM)
    //       fy: 2*64*136*2 + 2*64*136*2 = 34816 + 34816 =  69632
    const int SM_FX = 106496, SM_FY = 69632;
    cudaFuncSetAttribute((const void*)k_edge<3, true>,
                         cudaFuncAttributeMaxDynamicSharedMemorySize, SM_FX);
    cudaFuncSetAttribute((const void*)k_edge<2, false>,
                         cudaFuncAttributeMaxDynamicSharedMemorySize, SM_FY);

    int nx = n / 4;                 // 12500 x0 blocks
    int nyb = ne / 16;              // 15625 y0 blocks
    int cvb = (n * 16 + 255) / 256;
    int ntiles = (ne + 63) / 64;
    const int GRID = 296;

    // launch index:            0       1        2          3
    k_goal<<<1, 1024>>>(v, labels, n);
    k_prep_h<<<37, 64>>>(hy_w1, hx_w1, hx_b1);
    k_prep_fxw<<<64, 256>>>(fx_w1, fx_w2);
    k_prep_fyw<<<48, 256>>>(fy_w1, fy_w2);
    // 4
    k_init<<<nx + nyb, 256>>>(v, labels, ei, hx_w2, hx_b2, hy_b1, hy_w2, hy_b2, n, ne, nx);

    // iter 1 — 5 (ncu captures this fx), 6, 7
    k_edge<3, true><<<GRID, 256, SM_FX>>>(ei, fx_b1, fx_b2, 0, 1, ne, ntiles);
    cvtx_seed<<<cvb, 256>>>(1, 0, n * 16);
    k_edge<2, false><<<GRID, 256, SM_FY>>>(ei, fy_b1, fy_b2, 1, 0, ne, ntiles);
    // iter 2
    k_edge<3, true><<<GRID, 256, SM_FX>>>(ei, fx_b1, fx_b2, 1, 0, ne, ntiles);
    cvtx_seed<<<cvb, 256>>>(0, 1, n * 16);
    k_edge<2, false><<<GRID, 256, SM_FY>>>(ei, fy_b1, fy_b2, 0, 0, ne, ntiles);
    // iter 3
    k_edge<3, true><<<GRID, 256, SM_FX>>>(ei, fx_b1, fx_b2, 0, 1, ne, ntiles);
    cvtx_seed<<<cvb, 256>>>(1, -1, n * 16);
    k_edge<2, false><<<GRID, 256, SM_FY>>>(ei, fy_b1, fy_b2, 1, 0, ne, ntiles);

    k_out<<<n / 16, 256>>>(fe_w1, fe_b1, fe_w2, fe_b2, fe_w3, out, 1, n);
}

// round 10
// speedup vs baseline: 2.2344x; 1.2467x over previous
#include <cuda_runtime.h>
#include <cuda_bf16.h>
#include <mma.h>
#include <cstdint>

using namespace nvcuda;

#define NN 50000
#define EE 250000
#define NPAD 50048   // 391 * 128

// ---------------- persistent scratch ----------------
__device__ float g_x[2][(size_t)NPAD * 64];
__device__ float g_y[(size_t)EE * 64];
__device__ float g_goal[16];
__device__ __nv_bfloat16 g_ybh[(size_t)EE * 64];
__device__ __nv_bfloat16 g_ybl[(size_t)EE * 64];
__device__ float g_P0[(size_t)NPAD * 64];    // node partials (seg0 weights)
__device__ float g_P1[(size_t)NPAD * 64];    // node partials (seg1 weights)
__device__ float g_why[18 * 64];
__device__ float g_whx[18 * 64];
__device__ float g_bhx[64];
// bf16 hi/lo folded weights, layout [seg][j(out 0..63)][k(0..63)]
__device__ __nv_bfloat16 g_bfx1h[3 * 64 * 64], g_bfx1l[3 * 64 * 64];
__device__ __nv_bfloat16 g_bfx2h[64 * 64],     g_bfx2l[64 * 64];
__device__ __nv_bfloat16 g_bfy1h[2 * 64 * 64], g_bfy1l[2 * 64 * 64];
__device__ __nv_bfloat16 g_bfy2h[64 * 64],     g_bfy2l[64 * 64];

__device__ __forceinline__ void atomicMaxF(float* addr, float v) {
    if (v >= 0.f) atomicMax((int*)addr, __float_as_int(v));
    else          atomicMin((unsigned int*)addr, __float_as_uint(v));
}
// split 2 floats into packed bf16x2 hi + lo residual (a = low half of word)
__device__ __forceinline__ void split2(float a, float b, uint32_t& h, uint32_t& l) {
    asm("cvt.rn.bf16x2.f32 %0, %1, %2;" : "=r"(h) : "f"(b), "f"(a));
    float ha = __uint_as_float(h << 16);
    float hb = __uint_as_float(h & 0xFFFF0000u);
    float la = a - ha, lb = b - hb;
    asm("cvt.rn.bf16x2.f32 %0, %1, %2;" : "=r"(l) : "f"(lb), "f"(la));
}

// ---------------- goal ----------------
__global__ void k_goal(const float* __restrict__ v,
                       const float* __restrict__ labels, int n) {
    __shared__ float bv[1024];
    __shared__ int   bi[1024];
    float best = -1e30f; int bidx = 0;
    for (int i = threadIdx.x; i < n; i += 1024) {
        float val = labels[2 * i + 1];
        if (val > best) { best = val; bidx = i; }
    }
    bv[threadIdx.x] = best; bi[threadIdx.x] = bidx;
    __syncthreads();
    for (int s = 512; s > 0; s >>= 1) {
        if (threadIdx.x < s) {
            float ov = bv[threadIdx.x + s]; int oi = bi[threadIdx.x + s];
            if (ov > bv[threadIdx.x] || (ov == bv[threadIdx.x] && oi < bi[threadIdx.x])) {
                bv[threadIdx.x] = ov; bi[threadIdx.x] = oi;
            }
        }
        __syncthreads();
    }
    if (threadIdx.x == 0) {
        int g = bi[0];
        #pragma unroll
        for (int c = 0; c < 7; c++) g_goal[c] = v[g * 7 + c];
        g_goal[7] = labels[2 * g];
        g_goal[8] = labels[2 * g + 1];
    }
}

// ---------------- fp32 folds for hx/hy ----------------
__global__ void k_prep_h(const float* __restrict__ hyw1,
                         const float* __restrict__ hxw1,
                         const float* __restrict__ hxb1) {
    int idx = blockIdx.x * 64 + threadIdx.x;
    if (idx < 1152) {
        int k = idx >> 6, j = idx & 63;
        float o;
        if (k < 9) o = hyw1[k * 64 + j] + hyw1[(9 + k) * 64 + j];
        else       o = hyw1[(9 + k) * 64 + j] - hyw1[(k - 9) * 64 + j];
        g_why[idx] = o;
    } else if (idx < 2304) {
        int r = idx - 1152;
        int k = r >> 6, j = r & 63;
        float o;
        if (k < 9) o = hxw1[k * 64 + j] + hxw1[(18 + k) * 64 + j];
        else       o = hxw1[(18 + k) * 64 + j];
        g_whx[r] = o;
    } else if (idx < 2368) {
        int j = idx - 2304;
        float acc = hxb1[j];
        #pragma unroll
        for (int c = 0; c < 9; c++)
            acc += g_goal[c] * (hxw1[(9 + c) * 64 + j] - hxw1[(18 + c) * 64 + j]);
        g_bhx[j] = acc;
    }
}

// ---------------- bf16 weight preps (fold + transpose + split) ----------------
__global__ void k_prep_fxw(const float* __restrict__ w1, const float* __restrict__ w2) {
    int idx = blockIdx.x * 256 + threadIdx.x;
    if (idx < 12288) {
        int seg = idx >> 12, r = idx & 4095, j = r >> 6, k = r & 63;
        int kg = seg * 64 + k;
        float c;
        if (kg < 64)       c = w1[(64 + kg) * 64 + j] + w1[kg * 64 + j];
        else if (kg < 128) c = w1[(64 + kg) * 64 + j] - w1[(kg - 64) * 64 + j];
        else               c = w1[(64 + kg) * 64 + j];
        __nv_bfloat16 h = __float2bfloat16(c);
        g_bfx1h[idx] = h;
        g_bfx1l[idx] = __float2bfloat16(c - __bfloat162float(h));
    } else if (idx < 16384) {
        int r = idx - 12288, j = r >> 6, k = r & 63;
        float c = w2[k * 64 + j];
        __nv_bfloat16 h = __float2bfloat16(c);
        g_bfx2h[r] = h;
        g_bfx2l[r] = __float2bfloat16(c - __bfloat162float(h));
    }
}
__global__ void k_prep_fyw(const float* __restrict__ w1, const float* __restrict__ w2) {
    int idx = blockIdx.x * 256 + threadIdx.x;
    if (idx < 8192) {
        int seg = idx >> 12, r = idx & 4095, j = r >> 6, k = r & 63;
        int kg = seg * 64 + k;
        float c;
        if (kg < 64) c = w1[kg * 64 + j] + w1[(64 + kg) * 64 + j];
        else         c = w1[(64 + kg) * 64 + j] - w1[(kg - 64) * 64 + j];
        __nv_bfloat16 h = __float2bfloat16(c);
        g_bfy1h[idx] = h;
        g_bfy1l[idx] = __float2bfloat16(c - __bfloat162float(h));
    } else if (idx < 12288) {
        int r = idx - 8192, j = r >> 6, k = r & 63;
        float c = w2[k * 64 + j];
        __nv_bfloat16 h = __float2bfloat16(c);
        g_bfy2h[r] = h;
        g_bfy2l[r] = __float2bfloat16(c - __bfloat162float(h));
    }
}

// ---------------- k_init: x0 (first nx blocks) + y0 (rest) ----------------
__global__ __launch_bounds__(256) void k_init(
        const float* __restrict__ v, const float* __restrict__ labels,
        const int* __restrict__ ei,
        const float* __restrict__ hxw2, const float* __restrict__ hxb2,
        const float* __restrict__ hyb1,
        const float* __restrict__ hyw2, const float* __restrict__ hyb2,
        int n, int ne, int nx) {
    if ((int)blockIdx.x < nx) {
        __shared__ float in_s[4][18];
        __shared__ float h_s[4][64];
        int g = threadIdx.x >> 6, j = threadIdx.x & 63;
        int node = blockIdx.x * 4 + g;
        if (j < 9) {
            float vc = (j < 7) ? v[node * 7 + j] : labels[node * 2 + (j - 7)];
            float d  = vc - g_goal[j];
            in_s[g][j]     = vc;
            in_s[g][9 + j] = d * d;
        }
        __syncthreads();
        {
            float acc = g_bhx[j];
            #pragma unroll
            for (int k = 0; k < 18; k++) acc = fmaf(in_s[g][k], g_whx[k * 64 + j], acc);
            h_s[g][j] = fmaxf(acc, 0.f);
        }
        __syncthreads();
        {
            float acc = hxb2[j];
            #pragma unroll
            for (int k = 0; k < 64; k++) acc = fmaf(h_s[g][k], hxw2[k * 64 + j], acc);
            g_x[0][(size_t)node * 64 + j] = acc;
        }
    } else {
        __shared__ float in_s[16][20];
        __shared__ float h_s[16][68];
        int g = threadIdx.x >> 4, tt = threadIdx.x & 15;
        int e = (blockIdx.x - nx) * 16 + g;
        if (tt < 9) {
            int s = ei[e], d = ei[ne + e];
            float vi = (tt < 7) ? v[s * 7 + tt] : labels[s * 2 + (tt - 7)];
            float vj = (tt < 7) ? v[d * 7 + tt] : labels[d * 2 + (tt - 7)];
            in_s[g][tt]     = vj;
            in_s[g][9 + tt] = vi;
        }
        __syncthreads();
        const float4* w1v = (const float4*)g_why;
        float4 acc = *(const float4*)(hyb1 + 4 * tt);
        #pragma unroll
        for (int k = 0; k < 18; k++) {
            float sv = in_s[g][k];
            float4 w = w1v[k * 16 + tt];
            acc.x = fmaf(sv, w.x, acc.x);
            acc.y = fmaf(sv, w.y, acc.y);
            acc.z = fmaf(sv, w.z, acc.z);
            acc.w = fmaf(sv, w.w, acc.w);
        }
        *(float4*)(&h_s[g][4 * tt]) = make_float4(fmaxf(acc.x, 0.f), fmaxf(acc.y, 0.f),
                                                  fmaxf(acc.z, 0.f), fmaxf(acc.w, 0.f));
        __syncthreads();
        const float4* w2v = (const float4*)hyw2;
        float4 o = *(const float4*)(hyb2 + 4 * tt);
        #pragma unroll 8
        for (int k = 0; k < 64; k++) {
            float sv = h_s[g][k];
            float4 w = w2v[k * 16 + tt];
            o.x = fmaf(sv, w.x, o.x);
            o.y = fmaf(sv, w.y, o.y);
            o.z = fmaf(sv, w.z, o.z);
            o.w = fmaf(sv, w.w, o.w);
        }
        *(float4*)(g_y + (size_t)e * 64 + 4 * tt) = o;
        uint32_t h0, l0, h1, l1;
        split2(o.x, o.y, h0, l0);
        split2(o.z, o.w, h1, l1);
        ((uint2*)(g_ybh + (size_t)e * 64))[tt] = make_uint2(h0, h1);
        ((uint2*)(g_ybl + (size_t)e * 64))[tt] = make_uint2(l0, l1);
    }
}

// ---------------------------------------------------------------------------
// k_nodeP: P0 = x@W[seg0], P1 = x@W[seg1] (3-product bf16 split), 128 nodes/blk.
// Optionally copies x[rbuf] -> x[wbuf] (scatter-max seed) while staging.
// sel: 0 = fx weights (g_bfx1 segs 0,1), 1 = fy weights (g_bfy1 segs 0,1).
// ---------------------------------------------------------------------------
__global__ __launch_bounds__(256) void k_nodeP(int rbuf, int wbuf, int sel, int n) {
    extern __shared__ __align__(16) char smem[];
    __nv_bfloat16* Ah = (__nv_bfloat16*)smem;               // 128 x 72
    __nv_bfloat16* Al = (__nv_bfloat16*)(smem + 18432);
    __nv_bfloat16* WH = (__nv_bfloat16*)(smem + 36864);     // 128 x 72 (2 segs)
    __nv_bfloat16* WL = (__nv_bfloat16*)(smem + 55296);
    const __nv_bfloat16* w1h = sel ? g_bfy1h : g_bfx1h;
    const __nv_bfloat16* w1l = sel ? g_bfy1l : g_bfx1l;
    int tid = threadIdx.x, wid = tid >> 5;

    for (int i = tid; i < 1024; i += 256) {     // 128 rows x 64 bf16 (uint4 = 8)
        int j = i >> 3, k8 = (i & 7) * 8;
        *(uint4*)&WH[j * 72 + k8] = ((const uint4*)w1h)[i];
        *(uint4*)&WL[j * 72 + k8] = ((const uint4*)w1l)[i];
    }
    {
        int r = tid >> 1, half = tid & 1;
        int node = blockIdx.x * 128 + r;
        int ncl = node < n ? node : n - 1;
        const float4* xs = (const float4*)(g_x[rbuf] + (size_t)ncl * 64) + half * 8;
        float4* xw = (wbuf >= 0) ? (float4*)(g_x[wbuf] + (size_t)node * 64) + half * 8
                                 : (float4*)0;
        #pragma unroll
        for (int i = 0; i < 8; i++) {
            float4 f = xs[i];
            if (xw) xw[i] = f;
            uint32_t h0, l0, h1, l1;
            split2(f.x, f.y, h0, l0);
            split2(f.z, f.w, h1, l1);
            int c = half * 32 + i * 4;
            *(uint32_t*)&Ah[r * 72 + c]     = h0;
            *(uint32_t*)&Ah[r * 72 + c + 2] = h1;
            *(uint32_t*)&Al[r * 72 + c]     = l0;
            *(uint32_t*)&Al[r * 72 + c + 2] = l1;
        }
    }
    __syncthreads();

    wmma::fragment<wmma::accumulator, 16, 16, 16, float> acc0[4], acc1[4];
    #pragma unroll
    for (int t = 0; t < 4; t++) { wmma::fill_fragment(acc0[t], 0.f); wmma::fill_fragment(acc1[t], 0.f); }
    #pragma unroll
    for (int kt = 0; kt < 4; kt++) {
        wmma::fragment<wmma::matrix_a, 16, 16, 16, __nv_bfloat16, wmma::row_major> fah, fal;
        wmma::load_matrix_sync(fah, Ah + wid * 16 * 72 + kt * 16, 72);
        wmma::load_matrix_sync(fal, Al + wid * 16 * 72 + kt * 16, 72);
        #pragma unroll
        for (int t = 0; t < 4; t++) {
            wmma::fragment<wmma::matrix_b, 16, 16, 16, __nv_bfloat16, wmma::col_major> fbh, fbl;
            wmma::load_matrix_sync(fbh, WH + (t * 16) * 72 + kt * 16, 72);
            wmma::load_matrix_sync(fbl, WL + (t * 16) * 72 + kt * 16, 72);
            wmma::mma_sync(acc0[t], fah, fbh, acc0[t]);
            wmma::mma_sync(acc0[t], fah, fbl, acc0[t]);
            wmma::mma_sync(acc0[t], fal, fbh, acc0[t]);
            wmma::load_matrix_sync(fbh, WH + (64 + t * 16) * 72 + kt * 16, 72);
            wmma::load_matrix_sync(fbl, WL + (64 + t * 16) * 72 + kt * 16, 72);
            wmma::mma_sync(acc1[t], fah, fbh, acc1[t]);
            wmma::mma_sync(acc1[t], fah, fbl, acc1[t]);
            wmma::mma_sync(acc1[t], fal, fbh, acc1[t]);
        }
    }
    size_t ro = (size_t)(blockIdx.x * 128 + wid * 16) * 64;
    #pragma unroll
    for (int t = 0; t < 4; t++) {
        wmma::store_matrix_sync(g_P0 + ro + t * 16, acc0[t], 64, wmma::mem_row_major);
        wmma::store_matrix_sync(g_P1 + ro + t * 16, acc1[t], 64, wmma::mem_row_major);
    }
}

// ---------------------------------------------------------------------------
// k_fx2: per-warp independent 16-edge chunks, NO block barriers in loop.
//   GEMM1: y[e0..e0+15] @ W1y  (A direct from global mirrors)
//   ep1:   H = relu(C + P0[src] + P1[dst] + b1)  -> split -> smem stripe
//   GEMM2: H @ W2 ; ep2: atomicMax into g_x[wbuf][dst]
// ---------------------------------------------------------------------------
__global__ __launch_bounds__(256, 2) void k_fx2(
        const int* __restrict__ ei,
        const float* __restrict__ b1, const float* __restrict__ b2,
        int wbuf, int ne, int nch) {
    extern __shared__ __align__(16) char smem[];
    __nv_bfloat16* HH  = (__nv_bfloat16*)(smem);             // 128 x 72
    __nv_bfloat16* HL  = (__nv_bfloat16*)(smem + 18432);
    float*         CS  = (float*)(smem + 36864);             // 128 x 72 f32
    __nv_bfloat16* W1H = (__nv_bfloat16*)(smem + 73728);     // 64 x 72
    __nv_bfloat16* W1L = (__nv_bfloat16*)(smem + 82944);
    __nv_bfloat16* W2H = (__nv_bfloat16*)(smem + 92160);
    __nv_bfloat16* W2L = (__nv_bfloat16*)(smem + 101376);    // total 110592

    int tid = threadIdx.x, wid = tid >> 5, lane = tid & 31;
    for (int i = tid; i < 512; i += 256) {
        int j = i >> 3, k8 = (i & 7) * 8;
        *(uint4*)&W1H[j * 72 + k8] = ((const uint4*)(g_bfx1h + 8192))[i];   // seg2 (y)
        *(uint4*)&W1L[j * 72 + k8] = ((const uint4*)(g_bfx1l + 8192))[i];
        *(uint4*)&W2H[j * 72 + k8] = ((const uint4*)g_bfx2h)[i];
        *(uint4*)&W2L[j * 72 + k8] = ((const uint4*)g_bfx2l)[i];
    }
    __syncthreads();

    int er = lane >> 1, half = lane & 1, c0 = half * 32;
    int row = wid * 16 + er;
    float*         Crow = CS + row * 72 + c0;
    __nv_bfloat16* hh   = HH + row * 72 + c0;
    __nv_bfloat16* hl   = HL + row * 72 + c0;
    const float4* b1v = (const float4*)(b1 + c0);
    const float4* b2v = (const float4*)(b2 + c0);

    for (int ch = blockIdx.x * 8 + wid; ch < nch; ch += gridDim.x * 8) {
        int e0 = ch * 16;
        wmma::fragment<wmma::accumulator, 16, 16, 16, float> acc[4];
        #pragma unroll
        for (int t = 0; t < 4; t++) wmma::fill_fragment(acc[t], 0.f);
        #pragma unroll
        for (int kt = 0; kt < 4; kt++) {
            wmma::fragment<wmma::matrix_a, 16, 16, 16, __nv_bfloat16, wmma::row_major> fah, fal;
            wmma::load_matrix_sync(fah, g_ybh + (size_t)e0 * 64 + kt * 16, 64);
            wmma::load_matrix_sync(fal, g_ybl + (size_t)e0 * 64 + kt * 16, 64);
            #pragma unroll
            for (int t = 0; t < 4; t++) {
                wmma::fragment<wmma::matrix_b, 16, 16, 16, __nv_bfloat16, wmma::col_major> fbh, fbl;
                wmma::load_matrix_sync(fbh, W1H + (t * 16) * 72 + kt * 16, 72);
                wmma::load_matrix_sync(fbl, W1L + (t * 16) * 72 + kt * 16, 72);
                wmma::mma_sync(acc[t], fah, fbh, acc[t]);
                wmma::mma_sync(acc[t], fah, fbl, acc[t]);
                wmma::mma_sync(acc[t], fal, fbh, acc[t]);
            }
        }
        #pragma unroll
        for (int t = 0; t < 4; t++)
            wmma::store_matrix_sync(CS + (wid * 16) * 72 + t * 16, acc[t], 72, wmma::mem_row_major);
        __syncwarp();

        int e = e0 + er;
        int s = ei[e], d = ei[ne + e];
        {
            const float4* ps = (const float4*)(g_P0 + (size_t)s * 64 + c0);
            const float4* pd = (const float4*)(g_P1 + (size_t)d * 64 + c0);
            #pragma unroll
            for (int i = 0; i < 8; i++) {
                float4 cv = ((const float4*)Crow)[i];
                float4 av = ps[i], bv = pd[i], biv = b1v[i];
                float f0 = fmaxf(cv.x + av.x + bv.x + biv.x, 0.f);
                float f1 = fmaxf(cv.y + av.y + bv.y + biv.y, 0.f);
                float f2 = fmaxf(cv.z + av.z + bv.z + biv.z, 0.f);
                float f3 = fmaxf(cv.w + av.w + bv.w + biv.w, 0.f);
                uint32_t h0, l0, h1, l1;
                split2(f0, f1, h0, l0);
                split2(f2, f3, h1, l1);
                *(uint32_t*)&hh[i * 4]     = h0;
                *(uint32_t*)&hh[i * 4 + 2] = h1;
                *(uint32_t*)&hl[i * 4]     = l0;
                *(uint32_t*)&hl[i * 4 + 2] = l1;
            }
        }
        __syncwarp();
        #pragma unroll
        for (int t = 0; t < 4; t++) wmma::fill_fragment(acc[t], 0.f);
        #pragma unroll
        for (int kt = 0; kt < 4; kt++) {
            wmma::fragment<wmma::matrix_a, 16, 16, 16, __nv_bfloat16, wmma::row_major> fah, fal;
            wmma::load_matrix_sync(fah, HH + (wid * 16) * 72 + kt * 16, 72);
            wmma::load_matrix_sync(fal, HL + (wid * 16) * 72 + kt * 16, 72);
            #pragma unroll
            for (int t = 0; t < 4; t++) {
                wmma::fragment<wmma::matrix_b, 16, 16, 16, __nv_bfloat16, wmma::col_major> fbh, fbl;
                wmma::load_matrix_sync(fbh, W2H + (t * 16) * 72 + kt * 16, 72);
                wmma::load_matrix_sync(fbl, W2L + (t * 16) * 72 + kt * 16, 72);
                wmma::mma_sync(acc[t], fah, fbh, acc[t]);
                wmma::mma_sync(acc[t], fah, fbl, acc[t]);
                wmma::mma_sync(acc[t], fal, fbh, acc[t]);
            }
        }
        #pragma unroll
        for (int t = 0; t < 4; t++)
            wmma::store_matrix_sync(CS + (wid * 16) * 72 + t * 16, acc[t], 72, wmma::mem_row_major);
        __syncwarp();
        {
            float* dp = g_x[wbuf] + (size_t)d * 64 + c0;
            #pragma unroll
            for (int i = 0; i < 8; i++) {
                float4 cv  = ((const float4*)Crow)[i];
                float4 biv = b2v[i];
                atomicMaxF(dp + i * 4 + 0, cv.x + biv.x);
                atomicMaxF(dp + i * 4 + 1, cv.y + biv.y);
                atomicMaxF(dp + i * 4 + 2, cv.z + biv.z);
                atomicMaxF(dp + i * 4 + 3, cv.w + biv.w);
            }
        }
        __syncwarp();
    }
}

// ---------------------------------------------------------------------------
// k_fy2: H = relu(P0[dst] + P1[src] + b1); y = max(y, H@W2 + b2); mirrors.
// Per-warp independent chunks, no block barriers.
// ---------------------------------------------------------------------------
__global__ __launch_bounds__(256, 2) void k_fy2(
        const int* __restrict__ ei,
        const float* __restrict__ b1, const float* __restrict__ b2,
        int ne, int nch) {
    extern __shared__ __align__(16) char smem[];
    __nv_bfloat16* HH  = (__nv_bfloat16*)(smem);
    __nv_bfloat16* HL  = (__nv_bfloat16*)(smem + 18432);
    float*         CS  = (float*)(smem + 36864);
    __nv_bfloat16* W2H = (__nv_bfloat16*)(smem + 73728);
    __nv_bfloat16* W2L = (__nv_bfloat16*)(smem + 82944);     // total 92160

    int tid = threadIdx.x, wid = tid >> 5, lane = tid & 31;
    for (int i = tid; i < 512; i += 256) {
        int j = i >> 3, k8 = (i & 7) * 8;
        *(uint4*)&W2H[j * 72 + k8] = ((const uint4*)g_bfy2h)[i];
        *(uint4*)&W2L[j * 72 + k8] = ((const uint4*)g_bfy2l)[i];
    }
    __syncthreads();

    int er = lane >> 1, half = lane & 1, c0 = half * 32;
    int row = wid * 16 + er;
    float*         Crow = CS + row * 72 + c0;
    __nv_bfloat16* hh   = HH + row * 72 + c0;
    __nv_bfloat16* hl   = HL + row * 72 + c0;
    const float4* b1v = (const float4*)(b1 + c0);
    const float4* b2v = (const float4*)(b2 + c0);

    for (int ch = blockIdx.x * 8 + wid; ch < nch; ch += gridDim.x * 8) {
        int e = ch * 16 + er;
        int s = ei[e], d = ei[ne + e];
        {
            const float4* pj = (const float4*)(g_P0 + (size_t)d * 64 + c0);
            const float4* pi = (const float4*)(g_P1 + (size_t)s * 64 + c0);
            #pragma unroll
            for (int i = 0; i < 8; i++) {
                float4 av = pj[i], bv = pi[i], biv = b1v[i];
                float f0 = fmaxf(av.x + bv.x + biv.x, 0.f);
                float f1 = fmaxf(av.y + bv.y + biv.y, 0.f);
                float f2 = fmaxf(av.z + bv.z + biv.z, 0.f);
                float f3 = fmaxf(av.w + bv.w + biv.w, 0.f);
                uint32_t h0, l0, h1, l1;
                split2(f0, f1, h0, l0);
                split2(f2, f3, h1, l1);
                *(uint32_t*)&hh[i * 4]     = h0;
                *(uint32_t*)&hh[i * 4 + 2] = h1;
                *(uint32_t*)&hl[i * 4]     = l0;
                *(uint32_t*)&hl[i * 4 + 2] = l1;
            }
        }
        __syncwarp();
        wmma::fragment<wmma::accumulator, 16, 16, 16, float> acc[4];
        #pragma unroll
        for (int t = 0; t < 4; t++) wmma::fill_fragment(acc[t], 0.f);
        #pragma unroll
        for (int kt = 0; kt < 4; kt++) {
            wmma::fragment<wmma::matrix_a, 16, 16, 16, __nv_bfloat16, wmma::row_major> fah, fal;
            wmma::load_matrix_sync(fah, HH + (wid * 16) * 72 + kt * 16, 72);
            wmma::load_matrix_sync(fal, HL + (wid * 16) * 72 + kt * 16, 72);
            #pragma unroll
            for (int t = 0; t < 4; t++) {
                wmma::fragment<wmma::matrix_b, 16, 16, 16, __nv_bfloat16, wmma::col_major> fbh, fbl;
                wmma::load_matrix_sync(fbh, W2H + (t * 16) * 72 + kt * 16, 72);
                wmma::load_matrix_sync(fbl, W2L + (t * 16) * 72 + kt * 16, 72);
                wmma::mma_sync(acc[t], fah, fbh, acc[t]);
                wmma::mma_sync(acc[t], fah, fbl, acc[t]);
                wmma::mma_sync(acc[t], fal, fbh, acc[t]);
            }
        }
        #pragma unroll
        for (int t = 0; t < 4; t++)
            wmma::store_matrix_sync(CS + (wid * 16) * 72 + t * 16, acc[t], 72, wmma::mem_row_major);
        __syncwarp();
        {
            float4*   yp = (float4*)(g_y + (size_t)e * 64 + c0);
            uint32_t* mh = (uint32_t*)(g_ybh + (size_t)e * 64 + c0);
            uint32_t* ml = (uint32_t*)(g_ybl + (size_t)e * 64 + c0);
            #pragma unroll
            for (int i = 0; i < 8; i++) {
                float4 cv  = ((const float4*)Crow)[i];
                float4 biv = b2v[i];
                float4 yv  = yp[i];
                yv.x = fmaxf(yv.x, cv.x + biv.x);
                yv.y = fmaxf(yv.y, cv.y + biv.y);
                yv.z = fmaxf(yv.z, cv.z + biv.z);
                yv.w = fmaxf(yv.w, cv.w + biv.w);
                yp[i] = yv;
                uint32_t h0, l0, h1, l1;
                split2(yv.x, yv.y, h0, l0);
                split2(yv.z, yv.w, h1, l1);
                mh[2 * i] = h0; mh[2 * i + 1] = h1;
                ml[2 * i] = l0; ml[2 * i + 1] = l1;
            }
        }
        __syncwarp();
    }
}

// ---------------- head ----------------
__global__ __launch_bounds__(256) void k_out(
        const float* __restrict__ w1, const float* __restrict__ b1,
        const float* __restrict__ w2, const float* __restrict__ b2,
        const float* __restrict__ w3, float* __restrict__ out,
        int buf, int n) {
    __shared__ float x_s[16][68];
    __shared__ float h_s[16][68];
    int g = threadIdx.x >> 4, tt = threadIdx.x & 15;
    int node = blockIdx.x * 16 + g;
    *(float4*)(&x_s[g][4 * tt]) = *(const float4*)(g_x[buf] + (size_t)node * 64 + 4 * tt);
    __syncthreads();
    const float4* w1v = (const float4*)w1;
    float4 acc = *(const float4*)(b1 + 4 * tt);
    #pragma unroll 8
    for (int k = 0; k < 64; k++) {
        float sv = x_s[g][k];
        float4 w = w1v[k * 16 + tt];
        acc.x = fmaf(sv, w.x, acc.x);
        acc.y = fmaf(sv, w.y, acc.y);
        acc.z = fmaf(sv, w.z, acc.z);
        acc.w = fmaf(sv, w.w, acc.w);
    }
    *(float4*)(&h_s[g][4 * tt]) = make_float4(fmaxf(acc.x, 0.f), fmaxf(acc.y, 0.f),
                                              fmaxf(acc.z, 0.f), fmaxf(acc.w, 0.f));
    __syncthreads();
    const float4* w2v = (const float4*)w2;
    float4 o = *(const float4*)(b2 + 4 * tt);
    #pragma unroll 8
    for (int k = 0; k < 64; k++) {
        float sv = h_s[g][k];
        float4 w = w2v[k * 16 + tt];
        o.x = fmaf(sv, w.x, o.x);
        o.y = fmaf(sv, w.y, o.y);
        o.z = fmaf(sv, w.z, o.z);
        o.w = fmaf(sv, w.w, o.w);
    }
    float4 w3v = *(const float4*)(w3 + 4 * tt);
    float p = fmaxf(o.x, 0.f) * w3v.x + fmaxf(o.y, 0.f) * w3v.y
            + fmaxf(o.z, 0.f) * w3v.z + fmaxf(o.w, 0.f) * w3v.w;
    #pragma unroll
    for (int sh = 8; sh > 0; sh >>= 1)
        p += __shfl_xor_sync(0xffffffffu, p, sh, 16);
    if (tt == 0) out[node] = p;
}

// ---------------------------------------------------------------------------
extern "C" void kernel_launch(void* const* d_in, const int* in_sizes, int n_in,
                              void* d_out, int out_size) {
    const float* v      = (const float*)d_in[0];
    const float* labels = (const float*)d_in[1];
    const int*   ei     = (const int*)d_in[2];
    const float *hx_w1 = (const float*)d_in[4],  *hx_b1 = (const float*)d_in[5];
    const float *hx_w2 = (const float*)d_in[6],  *hx_b2 = (const float*)d_in[7];
    const float *hy_w1 = (const float*)d_in[8],  *hy_b1 = (const float*)d_in[9];
    const float *hy_w2 = (const float*)d_in[10], *hy_b2 = (const float*)d_in[11];
    const float *fx_w1 = (const float*)d_in[12], *fx_b1 = (const float*)d_in[13];
    const float *fx_w2 = (const float*)d_in[14], *fx_b2 = (const float*)d_in[15];
    const float *fy_w1 = (const float*)d_in[16], *fy_b1 = (const float*)d_in[17];
    const float *fy_w2 = (const float*)d_in[18], *fy_b2 = (const float*)d_in[19];
    const float *fe_w1 = (const float*)d_in[20], *fe_b1 = (const float*)d_in[21];
    const float *fe_w2 = (const float*)d_in[22], *fe_b2 = (const float*)d_in[23];
    const float *fe_w3 = (const float*)d_in[24];

    int n  = in_sizes[0] / 7;       // 50000
    int ne = in_sizes[2] / 2;       // 250000
    float* out = (float*)d_out;

    const int SM_NP = 73728, SM_FX = 110592, SM_FY = 92160;
    cudaFuncSetAttribute((const void*)k_nodeP,
                         cudaFuncAttributeMaxDynamicSharedMemorySize, SM_NP);
    cudaFuncSetAttribute((const void*)k_fx2,
                         cudaFuncAttributeMaxDynamicSharedMemorySize, SM_FX);
    cudaFuncSetAttribute((const void*)k_fy2,
                         cudaFuncAttributeMaxDynamicSharedMemorySize, SM_FY);

    int nx  = n / 4;                 // x0 blocks
    int nyb = ne / 16;               // y0 blocks
    int npb = NPAD / 128;            // 391 nodeP blocks
    int nch = ne / 16;               // 15625 edge chunks
    const int GRID = 296;

    k_goal<<<1, 1024>>>(v, labels, n);
    k_prep_h<<<37, 64>>>(hy_w1, hx_w1, hx_b1);
    k_prep_fxw<<<64, 256>>>(fx_w1, fx_w2);
    k_prep_fyw<<<48, 256>>>(fy_w1, fy_w2);
    k_init<<<nx + nyb, 256>>>(v, labels, ei, hx_w2, hx_b2, hy_b1, hy_w2, hy_b2, n, ne, nx);

    // iter 1: read x0 -> write x1
    k_nodeP<<<npb, 256, SM_NP>>>(0, 1, 0, n);
    k_fx2<<<GRID, 256, SM_FX>>>(ei, fx_b1, fx_b2, 1, ne, nch);
    k_nodeP<<<npb, 256, SM_NP>>>(1, -1, 1, n);
    k_fy2<<<GRID, 256, SM_FY>>>(ei, fy_b1, fy_b2, ne, nch);
    // iter 2: read x1 -> write x0
    k_nodeP<<<npb, 256, SM_NP>>>(1, 0, 0, n);
    k_fx2<<<GRID, 256, SM_FX>>>(ei, fx_b1, fx_b2, 0, ne, nch);
    k_nodeP<<<npb, 256, SM_NP>>>(0, -1, 1, n);
    k_fy2<<<GRID, 256, SM_FY>>>(ei, fy_b1, fy_b2, ne, nch);
    // iter 3: read x0 -> write x1
    k_nodeP<<<npb, 256, SM_NP>>>(0, 1, 0, n);
    k_fx2<<<GRID, 256, SM_FX>>>(ei, fx_b1, fx_b2, 1, ne, nch);
    k_nodeP<<<npb, 256, SM_NP>>>(1, -1, 1, n);
    k_fy2<<<GRID, 256, SM_FY>>>(ei, fy_b1, fy_b2, ne, nch);

    k_out<<<n / 16, 256>>>(fe_w1, fe_b1, fe_w2, fe_b2, fe_w3, out, 1, n);
}

// round 11
// speedup vs baseline: 2.7958x; 1.2513x over previous
#include <cuda_runtime.h>
#include <cuda_bf16.h>
#include <mma.h>
#include <cstdint>

using namespace nvcuda;

#define NN 50000
#define EE 250000
#define NPAD 50048   // 391 * 128

// ---------------- persistent scratch ----------------
__device__ float g_x[2][(size_t)NPAD * 64];
__device__ float g_y[(size_t)EE * 64];
__device__ float g_goal[16];
__device__ __nv_bfloat16 g_ybh[(size_t)EE * 64];
__device__ __nv_bfloat16 g_ybl[(size_t)EE * 64];
__device__ float g_P0[(size_t)NPAD * 64];    // node partials (seg0 weights)
__device__ float g_P1[(size_t)NPAD * 64];    // node partials (seg1 weights)
__device__ float g_why[18 * 64];
__device__ float g_whx[18 * 64];
__device__ float g_bhx[64];
// bf16 hi/lo folded weights, layout [seg][j(out 0..63)][k(0..63)]
__device__ __nv_bfloat16 g_bfx1h[3 * 64 * 64], g_bfx1l[3 * 64 * 64];
__device__ __nv_bfloat16 g_bfx2h[64 * 64],     g_bfx2l[64 * 64];
__device__ __nv_bfloat16 g_bfy1h[2 * 64 * 64], g_bfy1l[2 * 64 * 64];
__device__ __nv_bfloat16 g_bfy2h[64 * 64],     g_bfy2l[64 * 64];
__device__ __nv_bfloat16 g_bhy2h[64 * 64],     g_bhy2l[64 * 64];   // hy W2 (for y0 init)

__device__ __forceinline__ void atomicMaxF(float* addr, float v) {
    if (v >= 0.f) atomicMax((int*)addr, __float_as_int(v));
    else          atomicMin((unsigned int*)addr, __float_as_uint(v));
}
// split 2 floats into packed bf16x2 hi + lo residual (a = low half of word)
__device__ __forceinline__ void split2(float a, float b, uint32_t& h, uint32_t& l) {
    asm("cvt.rn.bf16x2.f32 %0, %1, %2;" : "=r"(h) : "f"(b), "f"(a));
    float ha = __uint_as_float(h << 16);
    float hb = __uint_as_float(h & 0xFFFF0000u);
    float la = a - ha, lb = b - hb;
    asm("cvt.rn.bf16x2.f32 %0, %1, %2;" : "=r"(l) : "f"(lb), "f"(la));
}

// ---------------- goal ----------------
__global__ void k_goal(const float* __restrict__ v,
                       const float* __restrict__ labels, int n) {
    __shared__ float bv[1024];
    __shared__ int   bi[1024];
    float best = -1e30f; int bidx = 0;
    for (int i = threadIdx.x; i < n; i += 1024) {
        float val = labels[2 * i + 1];
        if (val > best) { best = val; bidx = i; }
    }
    bv[threadIdx.x] = best; bi[threadIdx.x] = bidx;
    __syncthreads();
    for (int s = 512; s > 0; s >>= 1) {
        if (threadIdx.x < s) {
            float ov = bv[threadIdx.x + s]; int oi = bi[threadIdx.x + s];
            if (ov > bv[threadIdx.x] || (ov == bv[threadIdx.x] && oi < bi[threadIdx.x])) {
                bv[threadIdx.x] = ov; bi[threadIdx.x] = oi;
            }
        }
        __syncthreads();
    }
    if (threadIdx.x == 0) {
        int g = bi[0];
        #pragma unroll
        for (int c = 0; c < 7; c++) g_goal[c] = v[g * 7 + c];
        g_goal[7] = labels[2 * g];
        g_goal[8] = labels[2 * g + 1];
    }
}

// ---------------- fp32 folds for hx/hy ----------------
__global__ void k_prep_h(const float* __restrict__ hyw1,
                         const float* __restrict__ hxw1,
                         const float* __restrict__ hxb1) {
    int idx = blockIdx.x * 64 + threadIdx.x;
    if (idx < 1152) {
        int k = idx >> 6, j = idx & 63;
        float o;
        if (k < 9) o = hyw1[k * 64 + j] + hyw1[(9 + k) * 64 + j];
        else       o = hyw1[(9 + k) * 64 + j] - hyw1[(k - 9) * 64 + j];
        g_why[idx] = o;
    } else if (idx < 2304) {
        int r = idx - 1152;
        int k = r >> 6, j = r & 63;
        float o;
        if (k < 9) o = hxw1[k * 64 + j] + hxw1[(18 + k) * 64 + j];
        else       o = hxw1[(18 + k) * 64 + j];
        g_whx[r] = o;
    } else if (idx < 2368) {
        int j = idx - 2304;
        float acc = hxb1[j];
        #pragma unroll
        for (int c = 0; c < 9; c++)
            acc += g_goal[c] * (hxw1[(9 + c) * 64 + j] - hxw1[(18 + c) * 64 + j]);
        g_bhx[j] = acc;
    }
}

// ---------------- bf16 weight preps (fold + transpose + split) ----------------
__global__ void k_prep_fxw(const float* __restrict__ w1, const float* __restrict__ w2) {
    int idx = blockIdx.x * 256 + threadIdx.x;
    if (idx < 12288) {
        int seg = idx >> 12, r = idx & 4095, j = r >> 6, k = r & 63;
        int kg = seg * 64 + k;
        float c;
        if (kg < 64)       c = w1[(64 + kg) * 64 + j] + w1[kg * 64 + j];
        else if (kg < 128) c = w1[(64 + kg) * 64 + j] - w1[(kg - 64) * 64 + j];
        else               c = w1[(64 + kg) * 64 + j];
        __nv_bfloat16 h = __float2bfloat16(c);
        g_bfx1h[idx] = h;
        g_bfx1l[idx] = __float2bfloat16(c - __bfloat162float(h));
    } else if (idx < 16384) {
        int r = idx - 12288, j = r >> 6, k = r & 63;
        float c = w2[k * 64 + j];
        __nv_bfloat16 h = __float2bfloat16(c);
        g_bfx2h[r] = h;
        g_bfx2l[r] = __float2bfloat16(c - __bfloat162float(h));
    }
}
__global__ void k_prep_fyw(const float* __restrict__ w1, const float* __restrict__ w2,
                           const float* __restrict__ hyw2) {
    int idx = blockIdx.x * 256 + threadIdx.x;
    if (idx < 8192) {
        int seg = idx >> 12, r = idx & 4095, j = r >> 6, k = r & 63;
        int kg = seg * 64 + k;
        float c;
        if (kg < 64) c = w1[kg * 64 + j] + w1[(64 + kg) * 64 + j];
        else         c = w1[(64 + kg) * 64 + j] - w1[(kg - 64) * 64 + j];
        __nv_bfloat16 h = __float2bfloat16(c);
        g_bfy1h[idx] = h;
        g_bfy1l[idx] = __float2bfloat16(c - __bfloat162float(h));
    } else if (idx < 12288) {
        int r = idx - 8192, j = r >> 6, k = r & 63;
        float c = w2[k * 64 + j];
        __nv_bfloat16 h = __float2bfloat16(c);
        g_bfy2h[r] = h;
        g_bfy2l[r] = __float2bfloat16(c - __bfloat162float(h));
    } else if (idx < 16384) {
        int r = idx - 12288, j = r >> 6, k = r & 63;
        float c = hyw2[k * 64 + j];
        __nv_bfloat16 h = __float2bfloat16(c);
        g_bhy2h[r] = h;
        g_bhy2l[r] = __float2bfloat16(c - __bfloat162float(h));
    }
}

// ---------------- k_initA: x0 (first nx blocks) + Q0/Q1 (rest) ----------------
__global__ __launch_bounds__(256) void k_initA(
        const float* __restrict__ v, const float* __restrict__ labels,
        const float* __restrict__ hxw2, const float* __restrict__ hxb2,
        int n, int nx) {
    if ((int)blockIdx.x < nx) {
        __shared__ float in_s[4][18];
        __shared__ float h_s[4][64];
        int g = threadIdx.x >> 6, j = threadIdx.x & 63;
        int node = blockIdx.x * 4 + g;
        if (j < 9) {
            float vc = (j < 7) ? v[node * 7 + j] : labels[node * 2 + (j - 7)];
            float d  = vc - g_goal[j];
            in_s[g][j]     = vc;
            in_s[g][9 + j] = d * d;
        }
        __syncthreads();
        {
            float acc = g_bhx[j];
            #pragma unroll
            for (int k = 0; k < 18; k++) acc = fmaf(in_s[g][k], g_whx[k * 64 + j], acc);
            h_s[g][j] = fmaxf(acc, 0.f);
        }
        __syncthreads();
        {
            float acc = hxb2[j];
            #pragma unroll
            for (int k = 0; k < 64; k++) acc = fmaf(h_s[g][k], hxw2[k * 64 + j], acc);
            g_x[0][(size_t)node * 64 + j] = acc;
        }
    } else {
        // Q0 = vc@Wvj, Q1 = vc@Wvi  (hoisted y0 node partials)
        __shared__ float vc_s[4][12];
        int g = threadIdx.x >> 6, j = threadIdx.x & 63;
        int node = ((int)blockIdx.x - nx) * 4 + g;
        if (j < 9) {
            float vc = (j < 7) ? v[node * 7 + j] : labels[node * 2 + (j - 7)];
            vc_s[g][j] = vc;
        }
        __syncthreads();
        float q0 = 0.f, q1 = 0.f;
        #pragma unroll
        for (int c = 0; c < 9; c++) {
            float sv = vc_s[g][c];
            q0 = fmaf(sv, g_why[c * 64 + j], q0);
            q1 = fmaf(sv, g_why[(9 + c) * 64 + j], q1);
        }
        g_P0[(size_t)node * 64 + j] = q0;
        g_P1[(size_t)node * 64 + j] = q1;
    }
}

// ---------------------------------------------------------------------------
// k_nodeP: P0 = x@W[seg0], P1 = x@W[seg1] (3-product bf16 split), 128 nodes/blk.
// Optionally copies x[rbuf] -> x[wbuf] (scatter-max seed) while staging.
// sel: 0 = fx weights (g_bfx1 segs 0,1), 1 = fy weights (g_bfy1 segs 0,1).
// ---------------------------------------------------------------------------
__global__ __launch_bounds__(256) void k_nodeP(int rbuf, int wbuf, int sel, int n) {
    extern __shared__ __align__(16) char smem[];
    __nv_bfloat16* Ah = (__nv_bfloat16*)smem;               // 128 x 72
    __nv_bfloat16* Al = (__nv_bfloat16*)(smem + 18432);
    __nv_bfloat16* WH = (__nv_bfloat16*)(smem + 36864);     // 128 x 72 (2 segs)
    __nv_bfloat16* WL = (__nv_bfloat16*)(smem + 55296);
    const __nv_bfloat16* w1h = sel ? g_bfy1h : g_bfx1h;
    const __nv_bfloat16* w1l = sel ? g_bfy1l : g_bfx1l;
    int tid = threadIdx.x, wid = tid >> 5;

    for (int i = tid; i < 1024; i += 256) {     // 128 rows x 64 bf16 (uint4 = 8)
        int j = i >> 3, k8 = (i & 7) * 8;
        *(uint4*)&WH[j * 72 + k8] = ((const uint4*)w1h)[i];
        *(uint4*)&WL[j * 72 + k8] = ((const uint4*)w1l)[i];
    }
    {
        int r = tid >> 1, half = tid & 1;
        int node = blockIdx.x * 128 + r;
        int ncl = node < n ? node : n - 1;
        const float4* xs = (const float4*)(g_x[rbuf] + (size_t)ncl * 64) + half * 8;
        float4* xw = (wbuf >= 0) ? (float4*)(g_x[wbuf] + (size_t)node * 64) + half * 8
                                 : (float4*)0;
        #pragma unroll
        for (int i = 0; i < 8; i++) {
            float4 f = xs[i];
            if (xw) xw[i] = f;
            uint32_t h0, l0, h1, l1;
            split2(f.x, f.y, h0, l0);
            split2(f.z, f.w, h1, l1);
            int c = half * 32 + i * 4;
            *(uint2*)&Ah[r * 72 + c] = make_uint2(h0, h1);
            *(uint2*)&Al[r * 72 + c] = make_uint2(l0, l1);
        }
    }
    __syncthreads();

    wmma::fragment<wmma::accumulator, 16, 16, 16, float> acc0[4], acc1[4];
    #pragma unroll
    for (int t = 0; t < 4; t++) { wmma::fill_fragment(acc0[t], 0.f); wmma::fill_fragment(acc1[t], 0.f); }
    #pragma unroll
    for (int kt = 0; kt < 4; kt++) {
        wmma::fragment<wmma::matrix_a, 16, 16, 16, __nv_bfloat16, wmma::row_major> fah, fal;
        wmma::load_matrix_sync(fah, Ah + wid * 16 * 72 + kt * 16, 72);
        wmma::load_matrix_sync(fal, Al + wid * 16 * 72 + kt * 16, 72);
        #pragma unroll
        for (int t = 0; t < 4; t++) {
            wmma::fragment<wmma::matrix_b, 16, 16, 16, __nv_bfloat16, wmma::col_major> fbh, fbl;
            wmma::load_matrix_sync(fbh, WH + (t * 16) * 72 + kt * 16, 72);
            wmma::load_matrix_sync(fbl, WL + (t * 16) * 72 + kt * 16, 72);
            wmma::mma_sync(acc0[t], fah, fbh, acc0[t]);
            wmma::mma_sync(acc0[t], fah, fbl, acc0[t]);
            wmma::mma_sync(acc0[t], fal, fbh, acc0[t]);
            wmma::load_matrix_sync(fbh, WH + (64 + t * 16) * 72 + kt * 16, 72);
            wmma::load_matrix_sync(fbl, WL + (64 + t * 16) * 72 + kt * 16, 72);
            wmma::mma_sync(acc1[t], fah, fbh, acc1[t]);
            wmma::mma_sync(acc1[t], fah, fbl, acc1[t]);
            wmma::mma_sync(acc1[t], fal, fbh, acc1[t]);
        }
    }
    size_t ro = (size_t)(blockIdx.x * 128 + wid * 16) * 64;
    #pragma unroll
    for (int t = 0; t < 4; t++) {
        wmma::store_matrix_sync(g_P0 + ro + t * 16, acc0[t], 64, wmma::mem_row_major);
        wmma::store_matrix_sync(g_P1 + ro + t * 16, acc1[t], 64, wmma::mem_row_major);
    }
}

// ---------------------------------------------------------------------------
// k_fx2: per-warp independent 16-edge chunks, NO block barriers in loop.
// ---------------------------------------------------------------------------
__global__ __launch_bounds__(256, 2) void k_fx2(
        const int* __restrict__ ei,
        const float* __restrict__ b1, const float* __restrict__ b2,
        int wbuf, int ne, int nch) {
    extern __shared__ __align__(16) char smem[];
    __nv_bfloat16* HH  = (__nv_bfloat16*)(smem);             // 128 x 72
    __nv_bfloat16* HL  = (__nv_bfloat16*)(smem + 18432);
    float*         CS  = (float*)(smem + 36864);             // 128 x 72 f32
    __nv_bfloat16* W1H = (__nv_bfloat16*)(smem + 73728);     // 64 x 72
    __nv_bfloat16* W1L = (__nv_bfloat16*)(smem + 82944);
    __nv_bfloat16* W2H = (__nv_bfloat16*)(smem + 92160);
    __nv_bfloat16* W2L = (__nv_bfloat16*)(smem + 101376);    // total 110592

    int tid = threadIdx.x, wid = tid >> 5, lane = tid & 31;
    for (int i = tid; i < 512; i += 256) {
        int j = i >> 3, k8 = (i & 7) * 8;
        *(uint4*)&W1H[j * 72 + k8] = ((const uint4*)(g_bfx1h + 8192))[i];   // seg2 (y)
        *(uint4*)&W1L[j * 72 + k8] = ((const uint4*)(g_bfx1l + 8192))[i];
        *(uint4*)&W2H[j * 72 + k8] = ((const uint4*)g_bfx2h)[i];
        *(uint4*)&W2L[j * 72 + k8] = ((const uint4*)g_bfx2l)[i];
    }
    __syncthreads();

    int er = lane >> 1, half = lane & 1, c0 = half * 32;
    int row = wid * 16 + er;
    float*         Crow = CS + row * 72 + c0;
    __nv_bfloat16* hh   = HH + row * 72 + c0;
    __nv_bfloat16* hl   = HL + row * 72 + c0;
    const float4* b1v = (const float4*)(b1 + c0);
    const float4* b2v = (const float4*)(b2 + c0);

    for (int ch = blockIdx.x * 8 + wid; ch < nch; ch += gridDim.x * 8) {
        int e0 = ch * 16;
        wmma::fragment<wmma::accumulator, 16, 16, 16, float> acc[4];
        #pragma unroll
        for (int t = 0; t < 4; t++) wmma::fill_fragment(acc[t], 0.f);
        #pragma unroll
        for (int kt = 0; kt < 4; kt++) {
            wmma::fragment<wmma::matrix_a, 16, 16, 16, __nv_bfloat16, wmma::row_major> fah, fal;
            wmma::load_matrix_sync(fah, g_ybh + (size_t)e0 * 64 + kt * 16, 64);
            wmma::load_matrix_sync(fal, g_ybl + (size_t)e0 * 64 + kt * 16, 64);
            #pragma unroll
            for (int t = 0; t < 4; t++) {
                wmma::fragment<wmma::matrix_b, 16, 16, 16, __nv_bfloat16, wmma::col_major> fbh, fbl;
                wmma::load_matrix_sync(fbh, W1H + (t * 16) * 72 + kt * 16, 72);
                wmma::load_matrix_sync(fbl, W1L + (t * 16) * 72 + kt * 16, 72);
                wmma::mma_sync(acc[t], fah, fbh, acc[t]);
                wmma::mma_sync(acc[t], fah, fbl, acc[t]);
                wmma::mma_sync(acc[t], fal, fbh, acc[t]);
            }
        }
        #pragma unroll
        for (int t = 0; t < 4; t++)
            wmma::store_matrix_sync(CS + (wid * 16) * 72 + t * 16, acc[t], 72, wmma::mem_row_major);
        __syncwarp();

        int e = e0 + er;
        int s = ei[e], d = ei[ne + e];
        {
            const float4* ps = (const float4*)(g_P0 + (size_t)s * 64 + c0);
            const float4* pd = (const float4*)(g_P1 + (size_t)d * 64 + c0);
            #pragma unroll
            for (int i = 0; i < 8; i++) {
                float4 cv = ((const float4*)Crow)[i];
                float4 av = ps[i], bv = pd[i], biv = b1v[i];
                float f0 = fmaxf(cv.x + av.x + bv.x + biv.x, 0.f);
                float f1 = fmaxf(cv.y + av.y + bv.y + biv.y, 0.f);
                float f2 = fmaxf(cv.z + av.z + bv.z + biv.z, 0.f);
                float f3 = fmaxf(cv.w + av.w + bv.w + biv.w, 0.f);
                uint32_t h0, l0, h1, l1;
                split2(f0, f1, h0, l0);
                split2(f2, f3, h1, l1);
                *(uint2*)&hh[i * 4] = make_uint2(h0, h1);
                *(uint2*)&hl[i * 4] = make_uint2(l0, l1);
            }
        }
        __syncwarp();
        #pragma unroll
        for (int t = 0; t < 4; t++) wmma::fill_fragment(acc[t], 0.f);
        #pragma unroll
        for (int kt = 0; kt < 4; kt++) {
            wmma::fragment<wmma::matrix_a, 16, 16, 16, __nv_bfloat16, wmma::row_major> fah, fal;
            wmma::load_matrix_sync(fah, HH + (wid * 16) * 72 + kt * 16, 72);
            wmma::load_matrix_sync(fal, HL + (wid * 16) * 72 + kt * 16, 72);
            #pragma unroll
            for (int t = 0; t < 4; t++) {
                wmma::fragment<wmma::matrix_b, 16, 16, 16, __nv_bfloat16, wmma::col_major> fbh, fbl;
                wmma::load_matrix_sync(fbh, W2H + (t * 16) * 72 + kt * 16, 72);
                wmma::load_matrix_sync(fbl, W2L + (t * 16) * 72 + kt * 16, 72);
                wmma::mma_sync(acc[t], fah, fbh, acc[t]);
                wmma::mma_sync(acc[t], fah, fbl, acc[t]);
                wmma::mma_sync(acc[t], fal, fbh, acc[t]);
            }
        }
        #pragma unroll
        for (int t = 0; t < 4; t++)
            wmma::store_matrix_sync(CS + (wid * 16) * 72 + t * 16, acc[t], 72, wmma::mem_row_major);
        __syncwarp();
        {
            float* dp = g_x[wbuf] + (size_t)d * 64 + c0;
            #pragma unroll
            for (int i = 0; i < 8; i++) {
                float4 cv  = ((const float4*)Crow)[i];
                float4 biv = b2v[i];
                atomicMaxF(dp + i * 4 + 0, cv.x + biv.x);
                atomicMaxF(dp + i * 4 + 1, cv.y + biv.y);
                atomicMaxF(dp + i * 4 + 2, cv.z + biv.z);
                atomicMaxF(dp + i * 4 + 3, cv.w + biv.w);
            }
        }
        __syncwarp();
    }
}

// ---------------------------------------------------------------------------
// k_fy2: H = relu(P0[dst] + P1[src] + b1); y' = H@W2 + b2
//   init=0: y = max(y, y'); init=1: y = y'  (y0 path, sel=1 -> hy W2)
// ---------------------------------------------------------------------------
__global__ __launch_bounds__(256, 2) void k_fy2(
        const int* __restrict__ ei,
        const float* __restrict__ b1, const float* __restrict__ b2,
        int ne, int nch, int sel, int init) {
    extern __shared__ __align__(16) char smem[];
    __nv_bfloat16* HH  = (__nv_bfloat16*)(smem);
    __nv_bfloat16* HL  = (__nv_bfloat16*)(smem + 18432);
    float*         CS  = (float*)(smem + 36864);
    __nv_bfloat16* W2H = (__nv_bfloat16*)(smem + 73728);
    __nv_bfloat16* W2L = (__nv_bfloat16*)(smem + 82944);     // total 92160

    int tid = threadIdx.x, wid = tid >> 5, lane = tid & 31;
    {
        const uint4* w2h_g = sel ? (const uint4*)g_bhy2h : (const uint4*)g_bfy2h;
        const uint4* w2l_g = sel ? (const uint4*)g_bhy2l : (const uint4*)g_bfy2l;
        for (int i = tid; i < 512; i += 256) {
            int j = i >> 3, k8 = (i & 7) * 8;
            *(uint4*)&W2H[j * 72 + k8] = w2h_g[i];
            *(uint4*)&W2L[j * 72 + k8] = w2l_g[i];
        }
    }
    __syncthreads();

    int er = lane >> 1, half = lane & 1, c0 = half * 32;
    int row = wid * 16 + er;
    float*         Crow = CS + row * 72 + c0;
    __nv_bfloat16* hh   = HH + row * 72 + c0;
    __nv_bfloat16* hl   = HL + row * 72 + c0;
    const float4* b1v = (const float4*)(b1 + c0);
    const float4* b2v = (const float4*)(b2 + c0);

    for (int ch = blockIdx.x * 8 + wid; ch < nch; ch += gridDim.x * 8) {
        int e = ch * 16 + er;
        int s = ei[e], d = ei[ne + e];
        {
            const float4* pj = (const float4*)(g_P0 + (size_t)d * 64 + c0);
            const float4* pi = (const float4*)(g_P1 + (size_t)s * 64 + c0);
            #pragma unroll
            for (int i = 0; i < 8; i++) {
                float4 av = pj[i], bv = pi[i], biv = b1v[i];
                float f0 = fmaxf(av.x + bv.x + biv.x, 0.f);
                float f1 = fmaxf(av.y + bv.y + biv.y, 0.f);
                float f2 = fmaxf(av.z + bv.z + biv.z, 0.f);
                float f3 = fmaxf(av.w + bv.w + biv.w, 0.f);
                uint32_t h0, l0, h1, l1;
                split2(f0, f1, h0, l0);
                split2(f2, f3, h1, l1);
                *(uint2*)&hh[i * 4] = make_uint2(h0, h1);
                *(uint2*)&hl[i * 4] = make_uint2(l0, l1);
            }
        }
        __syncwarp();
        wmma::fragment<wmma::accumulator, 16, 16, 16, float> acc[4];
        #pragma unroll
        for (int t = 0; t < 4; t++) wmma::fill_fragment(acc[t], 0.f);
        #pragma unroll
        for (int kt = 0; kt < 4; kt++) {
            wmma::fragment<wmma::matrix_a, 16, 16, 16, __nv_bfloat16, wmma::row_major> fah, fal;
            wmma::load_matrix_sync(fah, HH + (wid * 16) * 72 + kt * 16, 72);
            wmma::load_matrix_sync(fal, HL + (wid * 16) * 72 + kt * 16, 72);
            #pragma unroll
            for (int t = 0; t < 4; t++) {
                wmma::fragment<wmma::matrix_b, 16, 16, 16, __nv_bfloat16, wmma::col_major> fbh, fbl;
                wmma::load_matrix_sync(fbh, W2H + (t * 16) * 72 + kt * 16, 72);
                wmma::load_matrix_sync(fbl, W2L + (t * 16) * 72 + kt * 16, 72);
                wmma::mma_sync(acc[t], fah, fbh, acc[t]);
                wmma::mma_sync(acc[t], fah, fbl, acc[t]);
                wmma::mma_sync(acc[t], fal, fbh, acc[t]);
            }
        }
        #pragma unroll
        for (int t = 0; t < 4; t++)
            wmma::store_matrix_sync(CS + (wid * 16) * 72 + t * 16, acc[t], 72, wmma::mem_row_major);
        __syncwarp();
        {
            float4*   yp = (float4*)(g_y + (size_t)e * 64 + c0);
            uint32_t* mh = (uint32_t*)(g_ybh + (size_t)e * 64 + c0);
            uint32_t* ml = (uint32_t*)(g_ybl + (size_t)e * 64 + c0);
            #pragma unroll
            for (int i = 0; i < 8; i++) {
                float4 cv  = ((const float4*)Crow)[i];
                float4 biv = b2v[i];
                float4 yv;
                yv.x = cv.x + biv.x;
                yv.y = cv.y + biv.y;
                yv.z = cv.z + biv.z;
                yv.w = cv.w + biv.w;
                if (!init) {
                    float4 yo = yp[i];
                    yv.x = fmaxf(yo.x, yv.x);
                    yv.y = fmaxf(yo.y, yv.y);
                    yv.z = fmaxf(yo.z, yv.z);
                    yv.w = fmaxf(yo.w, yv.w);
                }
                yp[i] = yv;
                uint32_t h0, l0, h1, l1;
                split2(yv.x, yv.y, h0, l0);
                split2(yv.z, yv.w, h1, l1);
                *(uint2*)&mh[2 * i] = make_uint2(h0, h1);
                *(uint2*)&ml[2 * i] = make_uint2(l0, l1);
            }
        }
        __syncwarp();
    }
}

// ---------------- head ----------------
__global__ __launch_bounds__(256) void k_out(
        const float* __restrict__ w1, const float* __restrict__ b1,
        const float* __restrict__ w2, const float* __restrict__ b2,
        const float* __restrict__ w3, float* __restrict__ out,
        int buf, int n) {
    __shared__ float x_s[16][68];
    __shared__ float h_s[16][68];
    int g = threadIdx.x >> 4, tt = threadIdx.x & 15;
    int node = blockIdx.x * 16 + g;
    *(float4*)(&x_s[g][4 * tt]) = *(const float4*)(g_x[buf] + (size_t)node * 64 + 4 * tt);
    __syncthreads();
    const float4* w1v = (const float4*)w1;
    float4 acc = *(const float4*)(b1 + 4 * tt);
    #pragma unroll 8
    for (int k = 0; k < 64; k++) {
        float sv = x_s[g][k];
        float4 w = w1v[k * 16 + tt];
        acc.x = fmaf(sv, w.x, acc.x);
        acc.y = fmaf(sv, w.y, acc.y);
        acc.z = fmaf(sv, w.z, acc.z);
        acc.w = fmaf(sv, w.w, acc.w);
    }
    *(float4*)(&h_s[g][4 * tt]) = make_float4(fmaxf(acc.x, 0.f), fmaxf(acc.y, 0.f),
                                              fmaxf(acc.z, 0.f), fmaxf(acc.w, 0.f));
    __syncthreads();
    const float4* w2v = (const float4*)w2;
    float4 o = *(const float4*)(b2 + 4 * tt);
    #pragma unroll 8
    for (int k = 0; k < 64; k++) {
        float sv = h_s[g][k];
        float4 w = w2v[k * 16 + tt];
        o.x = fmaf(sv, w.x, o.x);
        o.y = fmaf(sv, w.y, o.y);
        o.z = fmaf(sv, w.z, o.z);
        o.w = fmaf(sv, w.w, o.w);
    }
    float4 w3v = *(const float4*)(w3 + 4 * tt);
    float p = fmaxf(o.x, 0.f) * w3v.x + fmaxf(o.y, 0.f) * w3v.y
            + fmaxf(o.z, 0.f) * w3v.z + fmaxf(o.w, 0.f) * w3v.w;
    #pragma unroll
    for (int sh = 8; sh > 0; sh >>= 1)
        p += __shfl_xor_sync(0xffffffffu, p, sh, 16);
    if (tt == 0) out[node] = p;
}

// ---------------------------------------------------------------------------
extern "C" void kernel_launch(void* const* d_in, const int* in_sizes, int n_in,
                              void* d_out, int out_size) {
    const float* v      = (const float*)d_in[0];
    const float* labels = (const float*)d_in[1];
    const int*   ei     = (const int*)d_in[2];
    const float *hx_w1 = (const float*)d_in[4],  *hx_b1 = (const float*)d_in[5];
    const float *hx_w2 = (const float*)d_in[6],  *hx_b2 = (const float*)d_in[7];
    const float *hy_w1 = (const float*)d_in[8],  *hy_b1 = (const float*)d_in[9];
    const float *hy_w2 = (const float*)d_in[10], *hy_b2 = (const float*)d_in[11];
    const float *fx_w1 = (const float*)d_in[12], *fx_b1 = (const float*)d_in[13];
    const float *fx_w2 = (const float*)d_in[14], *fx_b2 = (const float*)d_in[15];
    const float *fy_w1 = (const float*)d_in[16], *fy_b1 = (const float*)d_in[17];
    const float *fy_w2 = (const float*)d_in[18], *fy_b2 = (const float*)d_in[19];
    const float *fe_w1 = (const float*)d_in[20], *fe_b1 = (const float*)d_in[21];
    const float *fe_w2 = (const float*)d_in[22], *fe_b2 = (const float*)d_in[23];
    const float *fe_w3 = (const float*)d_in[24];

    int n  = in_sizes[0] / 7;       // 50000
    int ne = in_sizes[2] / 2;       // 250000
    float* out = (float*)d_out;

    const int SM_NP = 73728, SM_FX = 110592, SM_FY = 92160;
    cudaFuncSetAttribute((const void*)k_nodeP,
                         cudaFuncAttributeMaxDynamicSharedMemorySize, SM_NP);
    cudaFuncSetAttribute((const void*)k_fx2,
                         cudaFuncAttributeMaxDynamicSharedMemorySize, SM_FX);
    cudaFuncSetAttribute((const void*)k_fy2,
                         cudaFuncAttributeMaxDynamicSharedMemorySize, SM_FY);

    int nx  = n / 4;                 // x0 blocks
    int nq  = n / 4;                 // Q blocks
    int npb = NPAD / 128;            // 391 nodeP blocks
    int nch = ne / 16;               // 15625 edge chunks
    const int GRID = 296;

    k_goal<<<1, 1024>>>(v, labels, n);
    k_prep_h<<<37, 64>>>(hy_w1, hx_w1, hx_b1);
    k_prep_fxw<<<64, 256>>>(fx_w1, fx_w2);
    k_prep_fyw<<<64, 256>>>(fy_w1, fy_w2, hy_w2);
    k_initA<<<nx + nq, 256>>>(v, labels, hx_w2, hx_b2, n, nx);
    // y0 via hoisted partials (sel=1: hy W2, init=1: no max)
    k_fy2<<<GRID, 256, SM_FY>>>(ei, hy_b1, hy_b2, ne, nch, 1, 1);

    // iter 1: read x0 -> write x1
    k_nodeP<<<npb, 256, SM_NP>>>(0, 1, 0, n);
    k_fx2<<<GRID, 256, SM_FX>>>(ei, fx_b1, fx_b2, 1, ne, nch);
    k_nodeP<<<npb, 256, SM_NP>>>(1, -1, 1, n);
    k_fy2<<<GRID, 256, SM_FY>>>(ei, fy_b1, fy_b2, ne, nch, 0, 0);
    // iter 2: read x1 -> write x0
    k_nodeP<<<npb, 256, SM_NP>>>(1, 0, 0, n);
    k_fx2<<<GRID, 256, SM_FX>>>(ei, fx_b1, fx_b2, 0, ne, nch);
    k_nodeP<<<npb, 256, SM_NP>>>(0, -1, 1, n);
    k_fy2<<<GRID, 256, SM_FY>>>(ei, fy_b1, fy_b2, ne, nch, 0, 0);
    // iter 3: read x0 -> write x1  (final y update is dead code — dropped)
    k_nodeP<<<npb, 256, SM_NP>>>(0, 1, 0, n);
    k_fx2<<<GRID, 256, SM_FX>>>(ei, fx_b1, fx_b2, 1, ne, nch);

    k_out<<<n / 16, 256>>>(fe_w1, fe_b1, fe_w2, fe_b2, fe_w3, out, 1, n);
}

// round 12
// speedup vs baseline: 3.0488x; 1.0905x over previous
#include <cuda_runtime.h>
#include <cuda_bf16.h>
#include <mma.h>
#include <cstdint>

using namespace nvcuda;

#define NN 50000
#define EE 250000
#define NPAD 50048   // 391 * 128

// ---------------- persistent scratch ----------------
__device__ float g_x[2][(size_t)NPAD * 64];
__device__ float g_goal[16];
__device__ __nv_bfloat16 g_ybh[(size_t)EE * 64];
__device__ __nv_bfloat16 g_ybl[(size_t)EE * 64];
__device__ float g_P0[(size_t)NPAD * 64];    // fx node partials (seg0)
__device__ float g_P1[(size_t)NPAD * 64];    // fx node partials (seg1)
__device__ float g_Q0[(size_t)NPAD * 64];    // fy node partials (seg0)
__device__ float g_Q1[(size_t)NPAD * 64];    // fy node partials (seg1)
__device__ float g_why[18 * 64];
__device__ float g_whx[18 * 64];
__device__ float g_bhx[64];
// bf16 hi/lo folded weights, layout [seg][j(out 0..63)][k(0..63)]
__device__ __nv_bfloat16 g_bfx1h[3 * 64 * 64], g_bfx1l[3 * 64 * 64];
__device__ __nv_bfloat16 g_bfx2h[64 * 64],     g_bfx2l[64 * 64];
__device__ __nv_bfloat16 g_bfy1h[2 * 64 * 64], g_bfy1l[2 * 64 * 64];
__device__ __nv_bfloat16 g_bfy2h[64 * 64],     g_bfy2l[64 * 64];
__device__ __nv_bfloat16 g_bhy2h[64 * 64],     g_bhy2l[64 * 64];   // hy W2 (y0 init)

__device__ __forceinline__ void atomicMaxF(float* addr, float v) {
    if (v >= 0.f) atomicMax((int*)addr, __float_as_int(v));
    else          atomicMin((unsigned int*)addr, __float_as_uint(v));
}
// split 2 floats into packed bf16x2 hi + lo residual (a = low half of word)
__device__ __forceinline__ void split2(float a, float b, uint32_t& h, uint32_t& l) {
    asm("cvt.rn.bf16x2.f32 %0, %1, %2;" : "=r"(h) : "f"(b), "f"(a));
    float ha = __uint_as_float(h << 16);
    float hb = __uint_as_float(h & 0xFFFF0000u);
    float la = a - ha, lb = b - hb;
    asm("cvt.rn.bf16x2.f32 %0, %1, %2;" : "=r"(l) : "f"(lb), "f"(la));
}

// ---------------- goal ----------------
__global__ void k_goal(const float* __restrict__ v,
                       const float* __restrict__ labels, int n) {
    __shared__ float bv[1024];
    __shared__ int   bi[1024];
    float best = -1e30f; int bidx = 0;
    for (int i = threadIdx.x; i < n; i += 1024) {
        float val = labels[2 * i + 1];
        if (val > best) { best = val; bidx = i; }
    }
    bv[threadIdx.x] = best; bi[threadIdx.x] = bidx;
    __syncthreads();
    for (int s = 512; s > 0; s >>= 1) {
        if (threadIdx.x < s) {
            float ov = bv[threadIdx.x + s]; int oi = bi[threadIdx.x + s];
            if (ov > bv[threadIdx.x] || (ov == bv[threadIdx.x] && oi < bi[threadIdx.x])) {
                bv[threadIdx.x] = ov; bi[threadIdx.x] = oi;
            }
        }
        __syncthreads();
    }
    if (threadIdx.x == 0) {
        int g = bi[0];
        #pragma unroll
        for (int c = 0; c < 7; c++) g_goal[c] = v[g * 7 + c];
        g_goal[7] = labels[2 * g];
        g_goal[8] = labels[2 * g + 1];
    }
}

// ---------------- fp32 folds for hx/hy ----------------
__global__ void k_prep_h(const float* __restrict__ hyw1,
                         const float* __restrict__ hxw1,
                         const float* __restrict__ hxb1) {
    int idx = blockIdx.x * 64 + threadIdx.x;
    if (idx < 1152) {
        int k = idx >> 6, j = idx & 63;
        float o;
        if (k < 9) o = hyw1[k * 64 + j] + hyw1[(9 + k) * 64 + j];
        else       o = hyw1[(9 + k) * 64 + j] - hyw1[(k - 9) * 64 + j];
        g_why[idx] = o;
    } else if (idx < 2304) {
        int r = idx - 1152;
        int k = r >> 6, j = r & 63;
        float o;
        if (k < 9) o = hxw1[k * 64 + j] + hxw1[(18 + k) * 64 + j];
        else       o = hxw1[(18 + k) * 64 + j];
        g_whx[r] = o;
    } else if (idx < 2368) {
        int j = idx - 2304;
        float acc = hxb1[j];
        #pragma unroll
        for (int c = 0; c < 9; c++)
            acc += g_goal[c] * (hxw1[(9 + c) * 64 + j] - hxw1[(18 + c) * 64 + j]);
        g_bhx[j] = acc;
    }
}

// ---------------- bf16 weight preps (fold + transpose + split) ----------------
__global__ void k_prep_fxw(const float* __restrict__ w1, const float* __restrict__ w2) {
    int idx = blockIdx.x * 256 + threadIdx.x;
    if (idx < 12288) {
        int seg = idx >> 12, r = idx & 4095, j = r >> 6, k = r & 63;
        int kg = seg * 64 + k;
        float c;
        if (kg < 64)       c = w1[(64 + kg) * 64 + j] + w1[kg * 64 + j];
        else if (kg < 128) c = w1[(64 + kg) * 64 + j] - w1[(kg - 64) * 64 + j];
        else               c = w1[(64 + kg) * 64 + j];
        __nv_bfloat16 h = __float2bfloat16(c);
        g_bfx1h[idx] = h;
        g_bfx1l[idx] = __float2bfloat16(c - __bfloat162float(h));
    } else if (idx < 16384) {
        int r = idx - 12288, j = r >> 6, k = r & 63;
        float c = w2[k * 64 + j];
        __nv_bfloat16 h = __float2bfloat16(c);
        g_bfx2h[r] = h;
        g_bfx2l[r] = __float2bfloat16(c - __bfloat162float(h));
    }
}
__global__ void k_prep_fyw(const float* __restrict__ w1, const float* __restrict__ w2,
                           const float* __restrict__ hyw2) {
    int idx = blockIdx.x * 256 + threadIdx.x;
    if (idx < 8192) {
        int seg = idx >> 12, r = idx & 4095, j = r >> 6, k = r & 63;
        int kg = seg * 64 + k;
        float c;
        if (kg < 64) c = w1[kg * 64 + j] + w1[(64 + kg) * 64 + j];
        else         c = w1[(64 + kg) * 64 + j] - w1[(kg - 64) * 64 + j];
        __nv_bfloat16 h = __float2bfloat16(c);
        g_bfy1h[idx] = h;
        g_bfy1l[idx] = __float2bfloat16(c - __bfloat162float(h));
    } else if (idx < 12288) {
        int r = idx - 8192, j = r >> 6, k = r & 63;
        float c = w2[k * 64 + j];
        __nv_bfloat16 h = __float2bfloat16(c);
        g_bfy2h[r] = h;
        g_bfy2l[r] = __float2bfloat16(c - __bfloat162float(h));
    } else if (idx < 16384) {
        int r = idx - 12288, j = r >> 6, k = r & 63;
        float c = hyw2[k * 64 + j];
        __nv_bfloat16 h = __float2bfloat16(c);
        g_bhy2h[r] = h;
        g_bhy2l[r] = __float2bfloat16(c - __bfloat162float(h));
    }
}

// ---------------- k_initA: x0 (first nx blocks) + Q0/Q1 for y0 (rest) --------
__global__ __launch_bounds__(256) void k_initA(
        const float* __restrict__ v, const float* __restrict__ labels,
        const float* __restrict__ hxw2, const float* __restrict__ hxb2,
        int n, int nx) {
    if ((int)blockIdx.x < nx) {
        __shared__ float in_s[4][18];
        __shared__ float h_s[4][64];
        int g = threadIdx.x >> 6, j = threadIdx.x & 63;
        int node = blockIdx.x * 4 + g;
        if (j < 9) {
            float vc = (j < 7) ? v[node * 7 + j] : labels[node * 2 + (j - 7)];
            float d  = vc - g_goal[j];
            in_s[g][j]     = vc;
            in_s[g][9 + j] = d * d;
        }
        __syncthreads();
        {
            float acc = g_bhx[j];
            #pragma unroll
            for (int k = 0; k < 18; k++) acc = fmaf(in_s[g][k], g_whx[k * 64 + j], acc);
            h_s[g][j] = fmaxf(acc, 0.f);
        }
        __syncthreads();
        {
            float acc = hxb2[j];
            #pragma unroll
            for (int k = 0; k < 64; k++) acc = fmaf(h_s[g][k], hxw2[k * 64 + j], acc);
            g_x[0][(size_t)node * 64 + j] = acc;
        }
    } else {
        // Q0 = vc@Wvj, Q1 = vc@Wvi  (hoisted y0 node partials)
        __shared__ float vc_s[4][12];
        int g = threadIdx.x >> 6, j = threadIdx.x & 63;
        int node = ((int)blockIdx.x - nx) * 4 + g;
        if (j < 9) {
            float vc = (j < 7) ? v[node * 7 + j] : labels[node * 2 + (j - 7)];
            vc_s[g][j] = vc;
        }
        __syncthreads();
        float q0 = 0.f, q1 = 0.f;
        #pragma unroll
        for (int c = 0; c < 9; c++) {
            float sv = vc_s[g][c];
            q0 = fmaf(sv, g_why[c * 64 + j], q0);
            q1 = fmaf(sv, g_why[(9 + c) * 64 + j], q1);
        }
        g_Q0[(size_t)node * 64 + j] = q0;
        g_Q1[(size_t)node * 64 + j] = q1;
    }
}

// ---------------------------------------------------------------------------
// k_nodePB: from x[rbuf] compute fx partials P0/P1 (always) and fy partials
// Q0/Q1 (if do_fy). Optional seed copy x[rbuf] -> x[wbuf]. 128 nodes/block.
// ---------------------------------------------------------------------------
__global__ __launch_bounds__(256) void k_nodePB(int rbuf, int wbuf, int do_fy, int n) {
    extern __shared__ __align__(16) char smem[];
    __nv_bfloat16* Ah  = (__nv_bfloat16*)smem;               // 128 x 72
    __nv_bfloat16* Al  = (__nv_bfloat16*)(smem + 18432);
    __nv_bfloat16* WXH = (__nv_bfloat16*)(smem + 36864);     // 128 x 72 (fx segs)
    __nv_bfloat16* WXL = (__nv_bfloat16*)(smem + 55296);
    __nv_bfloat16* WYH = (__nv_bfloat16*)(smem + 73728);     // 128 x 72 (fy segs)
    __nv_bfloat16* WYL = (__nv_bfloat16*)(smem + 92160);     // total 110592
    int tid = threadIdx.x, wid = tid >> 5;

    for (int i = tid; i < 1024; i += 256) {     // 128 rows x 64 bf16 (uint4 = 8)
        int j = i >> 3, k8 = (i & 7) * 8;
        *(uint4*)&WXH[j * 72 + k8] = ((const uint4*)g_bfx1h)[i];
        *(uint4*)&WXL[j * 72 + k8] = ((const uint4*)g_bfx1l)[i];
        if (do_fy) {
            *(uint4*)&WYH[j * 72 + k8] = ((const uint4*)g_bfy1h)[i];
            *(uint4*)&WYL[j * 72 + k8] = ((const uint4*)g_bfy1l)[i];
        }
    }
    {
        int r = tid >> 1, half = tid & 1;
        int node = blockIdx.x * 128 + r;
        int ncl = node < n ? node : n - 1;
        const float4* xs = (const float4*)(g_x[rbuf] + (size_t)ncl * 64) + half * 8;
        float4* xw = (wbuf >= 0) ? (float4*)(g_x[wbuf] + (size_t)node * 64) + half * 8
                                 : (float4*)0;
        #pragma unroll
        for (int i = 0; i < 8; i++) {
            float4 f = xs[i];
            if (xw) xw[i] = f;
            uint32_t h0, l0, h1, l1;
            split2(f.x, f.y, h0, l0);
            split2(f.z, f.w, h1, l1);
            int c = half * 32 + i * 4;
            *(uint2*)&Ah[r * 72 + c] = make_uint2(h0, h1);
            *(uint2*)&Al[r * 72 + c] = make_uint2(l0, l1);
        }
    }
    __syncthreads();

    size_t ro = (size_t)(blockIdx.x * 128 + wid * 16) * 64;
    for (int pass = 0; pass < (do_fy ? 2 : 1); pass++) {
        const __nv_bfloat16* WH = pass ? WYH : WXH;
        const __nv_bfloat16* WL = pass ? WYL : WXL;
        float* D0 = pass ? g_Q0 : g_P0;
        float* D1 = pass ? g_Q1 : g_P1;
        wmma::fragment<wmma::accumulator, 16, 16, 16, float> acc0[4], acc1[4];
        #pragma unroll
        for (int t = 0; t < 4; t++) { wmma::fill_fragment(acc0[t], 0.f); wmma::fill_fragment(acc1[t], 0.f); }
        #pragma unroll
        for (int kt = 0; kt < 4; kt++) {
            wmma::fragment<wmma::matrix_a, 16, 16, 16, __nv_bfloat16, wmma::row_major> fah, fal;
            wmma::load_matrix_sync(fah, Ah + wid * 16 * 72 + kt * 16, 72);
            wmma::load_matrix_sync(fal, Al + wid * 16 * 72 + kt * 16, 72);
            #pragma unroll
            for (int t = 0; t < 4; t++) {
                wmma::fragment<wmma::matrix_b, 16, 16, 16, __nv_bfloat16, wmma::col_major> fbh, fbl;
                wmma::load_matrix_sync(fbh, WH + (t * 16) * 72 + kt * 16, 72);
                wmma::load_matrix_sync(fbl, WL + (t * 16) * 72 + kt * 16, 72);
                wmma::mma_sync(acc0[t], fah, fbh, acc0[t]);
                wmma::mma_sync(acc0[t], fah, fbl, acc0[t]);
                wmma::mma_sync(acc0[t], fal, fbh, acc0[t]);
                wmma::load_matrix_sync(fbh, WH + (64 + t * 16) * 72 + kt * 16, 72);
                wmma::load_matrix_sync(fbl, WL + (64 + t * 16) * 72 + kt * 16, 72);
                wmma::mma_sync(acc1[t], fah, fbh, acc1[t]);
                wmma::mma_sync(acc1[t], fah, fbl, acc1[t]);
                wmma::mma_sync(acc1[t], fal, fbh, acc1[t]);
            }
        }
        #pragma unroll
        for (int t = 0; t < 4; t++) {
            wmma::store_matrix_sync(D0 + ro + t * 16, acc0[t], 64, wmma::mem_row_major);
            wmma::store_matrix_sync(D1 + ro + t * 16, acc1[t], 64, wmma::mem_row_major);
        }
    }
}

// ---------------------------------------------------------------------------
// k_fx2: per-warp independent 16-edge chunks, NO block barriers in loop.
// Atomics pruned by monotone snapshot check.
// ---------------------------------------------------------------------------
__global__ __launch_bounds__(256, 2) void k_fx2(
        const int* __restrict__ ei,
        const float* __restrict__ b1, const float* __restrict__ b2,
        int wbuf, int ne, int nch) {
    extern __shared__ __align__(16) char smem[];
    __nv_bfloat16* HH  = (__nv_bfloat16*)(smem);             // 128 x 72
    __nv_bfloat16* HL  = (__nv_bfloat16*)(smem + 18432);
    float*         CS  = (float*)(smem + 36864);             // 128 x 72 f32
    __nv_bfloat16* W1H = (__nv_bfloat16*)(smem + 73728);     // 64 x 72
    __nv_bfloat16* W1L = (__nv_bfloat16*)(smem + 82944);
    __nv_bfloat16* W2H = (__nv_bfloat16*)(smem + 92160);
    __nv_bfloat16* W2L = (__nv_bfloat16*)(smem + 101376);    // total 110592

    int tid = threadIdx.x, wid = tid >> 5, lane = tid & 31;
    for (int i = tid; i < 512; i += 256) {
        int j = i >> 3, k8 = (i & 7) * 8;
        *(uint4*)&W1H[j * 72 + k8] = ((const uint4*)(g_bfx1h + 8192))[i];   // seg2 (y)
        *(uint4*)&W1L[j * 72 + k8] = ((const uint4*)(g_bfx1l + 8192))[i];
        *(uint4*)&W2H[j * 72 + k8] = ((const uint4*)g_bfx2h)[i];
        *(uint4*)&W2L[j * 72 + k8] = ((const uint4*)g_bfx2l)[i];
    }
    __syncthreads();

    int er = lane >> 1, half = lane & 1, c0 = half * 32;
    int row = wid * 16 + er;
    float*         Crow = CS + row * 72 + c0;
    __nv_bfloat16* hh   = HH + row * 72 + c0;
    __nv_bfloat16* hl   = HL + row * 72 + c0;
    const float4* b1v = (const float4*)(b1 + c0);
    const float4* b2v = (const float4*)(b2 + c0);

    for (int ch = blockIdx.x * 8 + wid; ch < nch; ch += gridDim.x * 8) {
        int e0 = ch * 16;
        wmma::fragment<wmma::accumulator, 16, 16, 16, float> acc[4];
        #pragma unroll
        for (int t = 0; t < 4; t++) wmma::fill_fragment(acc[t], 0.f);
        #pragma unroll
        for (int kt = 0; kt < 4; kt++) {
            wmma::fragment<wmma::matrix_a, 16, 16, 16, __nv_bfloat16, wmma::row_major> fah, fal;
            wmma::load_matrix_sync(fah, g_ybh + (size_t)e0 * 64 + kt * 16, 64);
            wmma::load_matrix_sync(fal, g_ybl + (size_t)e0 * 64 + kt * 16, 64);
            #pragma unroll
            for (int t = 0; t < 4; t++) {
                wmma::fragment<wmma::matrix_b, 16, 16, 16, __nv_bfloat16, wmma::col_major> fbh, fbl;
                wmma::load_matrix_sync(fbh, W1H + (t * 16) * 72 + kt * 16, 72);
                wmma::load_matrix_sync(fbl, W1L + (t * 16) * 72 + kt * 16, 72);
                wmma::mma_sync(acc[t], fah, fbh, acc[t]);
                wmma::mma_sync(acc[t], fah, fbl, acc[t]);
                wmma::mma_sync(acc[t], fal, fbh, acc[t]);
            }
        }
        #pragma unroll
        for (int t = 0; t < 4; t++)
            wmma::store_matrix_sync(CS + (wid * 16) * 72 + t * 16, acc[t], 72, wmma::mem_row_major);
        __syncwarp();

        int e = e0 + er;
        int s = ei[e], d = ei[ne + e];
        {
            const float4* ps = (const float4*)(g_P0 + (size_t)s * 64 + c0);
            const float4* pd = (const float4*)(g_P1 + (size_t)d * 64 + c0);
            #pragma unroll
            for (int i = 0; i < 8; i++) {
                float4 cv = ((const float4*)Crow)[i];
                float4 av = ps[i], bv = pd[i], biv = b1v[i];
                float f0 = fmaxf(cv.x + av.x + bv.x + biv.x, 0.f);
                float f1 = fmaxf(cv.y + av.y + bv.y + biv.y, 0.f);
                float f2 = fmaxf(cv.z + av.z + bv.z + biv.z, 0.f);
                float f3 = fmaxf(cv.w + av.w + bv.w + biv.w, 0.f);
                uint32_t h0, l0, h1, l1;
                split2(f0, f1, h0, l0);
                split2(f2, f3, h1, l1);
                *(uint2*)&hh[i * 4] = make_uint2(h0, h1);
                *(uint2*)&hl[i * 4] = make_uint2(l0, l1);
            }
        }
        __syncwarp();
        #pragma unroll
        for (int t = 0; t < 4; t++) wmma::fill_fragment(acc[t], 0.f);
        #pragma unroll
        for (int kt = 0; kt < 4; kt++) {
            wmma::fragment<wmma::matrix_a, 16, 16, 16, __nv_bfloat16, wmma::row_major> fah, fal;
            wmma::load_matrix_sync(fah, HH + (wid * 16) * 72 + kt * 16, 72);
            wmma::load_matrix_sync(fal, HL + (wid * 16) * 72 + kt * 16, 72);
            #pragma unroll
            for (int t = 0; t < 4; t++) {
                wmma::fragment<wmma::matrix_b, 16, 16, 16, __nv_bfloat16, wmma::col_major> fbh, fbl;
                wmma::load_matrix_sync(fbh, W2H + (t * 16) * 72 + kt * 16, 72);
                wmma::load_matrix_sync(fbl, W2L + (t * 16) * 72 + kt * 16, 72);
                wmma::mma_sync(acc[t], fah, fbh, acc[t]);
                wmma::mma_sync(acc[t], fah, fbl, acc[t]);
                wmma::mma_sync(acc[t], fal, fbh, acc[t]);
            }
        }
        #pragma unroll
        for (int t = 0; t < 4; t++)
            wmma::store_matrix_sync(CS + (wid * 16) * 72 + t * 16, acc[t], 72, wmma::mem_row_major);
        __syncwarp();
        {
            float* dp = g_x[wbuf] + (size_t)d * 64 + c0;
            #pragma unroll
            for (int i = 0; i < 8; i++) {
                float4 cv  = ((const float4*)Crow)[i];
                float4 biv = b2v[i];
                float4 cur = *(const float4*)(dp + i * 4);   // monotone snapshot
                float m0 = cv.x + biv.x, m1 = cv.y + biv.y;
                float m2 = cv.z + biv.z, m3 = cv.w + biv.w;
                if (m0 > cur.x) atomicMaxF(dp + i * 4 + 0, m0);
                if (m1 > cur.y) atomicMaxF(dp + i * 4 + 1, m1);
                if (m2 > cur.z) atomicMaxF(dp + i * 4 + 2, m2);
                if (m3 > cur.w) atomicMaxF(dp + i * 4 + 3, m3);
            }
        }
        __syncwarp();
    }
}

// ---------------------------------------------------------------------------
// k_fy2: H = relu(Q0[dst] + Q1[src] + b1); y' = H@W2 + b2
//   init=0: y = max(y_old, y') with y_old = hi+lo from mirrors; init=1: y = y'
//   Writes mirrors only (no fp32 y kept).
// ---------------------------------------------------------------------------
__global__ __launch_bounds__(256, 2) void k_fy2(
        const int* __restrict__ ei,
        const float* __restrict__ b1, const float* __restrict__ b2,
        int ne, int nch, int sel, int init) {
    extern __shared__ __align__(16) char smem[];
    __nv_bfloat16* HH  = (__nv_bfloat16*)(smem);
    __nv_bfloat16* HL  = (__nv_bfloat16*)(smem + 18432);
    float*         CS  = (float*)(smem + 36864);
    __nv_bfloat16* W2H = (__nv_bfloat16*)(smem + 73728);
    __nv_bfloat16* W2L = (__nv_bfloat16*)(smem + 82944);     // total 92160

    int tid = threadIdx.x, wid = tid >> 5, lane = tid & 31;
    {
        const uint4* w2h_g = sel ? (const uint4*)g_bhy2h : (const uint4*)g_bfy2h;
        const uint4* w2l_g = sel ? (const uint4*)g_bhy2l : (const uint4*)g_bfy2l;
        for (int i = tid; i < 512; i += 256) {
            int j = i >> 3, k8 = (i & 7) * 8;
            *(uint4*)&W2H[j * 72 + k8] = w2h_g[i];
            *(uint4*)&W2L[j * 72 + k8] = w2l_g[i];
        }
    }
    __syncthreads();

    int er = lane >> 1, half = lane & 1, c0 = half * 32;
    int row = wid * 16 + er;
    float*         Crow = CS + row * 72 + c0;
    __nv_bfloat16* hh   = HH + row * 72 + c0;
    __nv_bfloat16* hl   = HL + row * 72 + c0;
    const float4* b1v = (const float4*)(b1 + c0);
    const float4* b2v = (const float4*)(b2 + c0);

    for (int ch = blockIdx.x * 8 + wid; ch < nch; ch += gridDim.x * 8) {
        int e = ch * 16 + er;
        int s = ei[e], d = ei[ne + e];
        {
            const float4* pj = (const float4*)(g_Q0 + (size_t)d * 64 + c0);
            const float4* pi = (const float4*)(g_Q1 + (size_t)s * 64 + c0);
            #pragma unroll
            for (int i = 0; i < 8; i++) {
                float4 av = pj[i], bv = pi[i], biv = b1v[i];
                float f0 = fmaxf(av.x + bv.x + biv.x, 0.f);
                float f1 = fmaxf(av.y + bv.y + biv.y, 0.f);
                float f2 = fmaxf(av.z + bv.z + biv.z, 0.f);
                float f3 = fmaxf(av.w + bv.w + biv.w, 0.f);
                uint32_t h0, l0, h1, l1;
                split2(f0, f1, h0, l0);
                split2(f2, f3, h1, l1);
                *(uint2*)&hh[i * 4] = make_uint2(h0, h1);
                *(uint2*)&hl[i * 4] = make_uint2(l0, l1);
            }
        }
        __syncwarp();
        wmma::fragment<wmma::accumulator, 16, 16, 16, float> acc[4];
        #pragma unroll
        for (int t = 0; t < 4; t++) wmma::fill_fragment(acc[t], 0.f);
        #pragma unroll
        for (int kt = 0; kt < 4; kt++) {
            wmma::fragment<wmma::matrix_a, 16, 16, 16, __nv_bfloat16, wmma::row_major> fah, fal;
            wmma::load_matrix_sync(fah, HH + (wid * 16) * 72 + kt * 16, 72);
            wmma::load_matrix_sync(fal, HL + (wid * 16) * 72 + kt * 16, 72);
            #pragma unroll
            for (int t = 0; t < 4; t++) {
                wmma::fragment<wmma::matrix_b, 16, 16, 16, __nv_bfloat16, wmma::col_major> fbh, fbl;
                wmma::load_matrix_sync(fbh, W2H + (t * 16) * 72 + kt * 16, 72);
                wmma::load_matrix_sync(fbl, W2L + (t * 16) * 72 + kt * 16, 72);
                wmma::mma_sync(acc[t], fah, fbh, acc[t]);
                wmma::mma_sync(acc[t], fah, fbl, acc[t]);
                wmma::mma_sync(acc[t], fal, fbh, acc[t]);
            }
        }
        #pragma unroll
        for (int t = 0; t < 4; t++)
            wmma::store_matrix_sync(CS + (wid * 16) * 72 + t * 16, acc[t], 72, wmma::mem_row_major);
        __syncwarp();
        {
            uint32_t* mh = (uint32_t*)(g_ybh + (size_t)e * 64 + c0);
            uint32_t* ml = (uint32_t*)(g_ybl + (size_t)e * 64 + c0);
            #pragma unroll
            for (int i = 0; i < 8; i++) {
                float4 cv  = ((const float4*)Crow)[i];
                float4 biv = b2v[i];
                float y0 = cv.x + biv.x, y1 = cv.y + biv.y;
                float y2 = cv.z + biv.z, y3 = cv.w + biv.w;
                if (!init) {
                    uint2 hw = *(uint2*)&mh[2 * i];
                    uint2 lw = *(uint2*)&ml[2 * i];
                    y0 = fmaxf(y0, __uint_as_float(hw.x << 16)        + __uint_as_float(lw.x << 16));
                    y1 = fmaxf(y1, __uint_as_float(hw.x & 0xFFFF0000u) + __uint_as_float(lw.x & 0xFFFF0000u));
                    y2 = fmaxf(y2, __uint_as_float(hw.y << 16)        + __uint_as_float(lw.y << 16));
                    y3 = fmaxf(y3, __uint_as_float(hw.y & 0xFFFF0000u) + __uint_as_float(lw.y & 0xFFFF0000u));
                }
                uint32_t h0, l0, h1, l1;
                split2(y0, y1, h0, l0);
                split2(y2, y3, h1, l1);
                *(uint2*)&mh[2 * i] = make_uint2(h0, h1);
                *(uint2*)&ml[2 * i] = make_uint2(l0, l1);
            }
        }
        __syncwarp();
    }
}

// ---------------- head ----------------
__global__ __launch_bounds__(256) void k_out(
        const float* __restrict__ w1, const float* __restrict__ b1,
        const float* __restrict__ w2, const float* __restrict__ b2,
        const float* __restrict__ w3, float* __restrict__ out,
        int buf, int n) {
    __shared__ float x_s[16][68];
    __shared__ float h_s[16][68];
    int g = threadIdx.x >> 4, tt = threadIdx.x & 15;
    int node = blockIdx.x * 16 + g;
    *(float4*)(&x_s[g][4 * tt]) = *(const float4*)(g_x[buf] + (size_t)node * 64 + 4 * tt);
    __syncthreads();
    const float4* w1v = (const float4*)w1;
    float4 acc = *(const float4*)(b1 + 4 * tt);
    #pragma unroll 8
    for (int k = 0; k < 64; k++) {
        float sv = x_s[g][k];
        float4 w = w1v[k * 16 + tt];
        acc.x = fmaf(sv, w.x, acc.x);
        acc.y = fmaf(sv, w.y, acc.y);
        acc.z = fmaf(sv, w.z, acc.z);
        acc.w = fmaf(sv, w.w, acc.w);
    }
    *(float4*)(&h_s[g][4 * tt]) = make_float4(fmaxf(acc.x, 0.f), fmaxf(acc.y, 0.f),
                                              fmaxf(acc.z, 0.f), fmaxf(acc.w, 0.f));
    __syncthreads();
    const float4* w2v = (const float4*)w2;
    float4 o = *(const float4*)(b2 + 4 * tt);
    #pragma unroll 8
    for (int k = 0; k < 64; k++) {
        float sv = h_s[g][k];
        float4 w = w2v[k * 16 + tt];
        o.x = fmaf(sv, w.x, o.x);
        o.y = fmaf(sv, w.y, o.y);
        o.z = fmaf(sv, w.z, o.z);
        o.w = fmaf(sv, w.w, o.w);
    }
    float4 w3v = *(const float4*)(w3 + 4 * tt);
    float p = fmaxf(o.x, 0.f) * w3v.x + fmaxf(o.y, 0.f) * w3v.y
            + fmaxf(o.z, 0.f) * w3v.z + fmaxf(o.w, 0.f) * w3v.w;
    #pragma unroll
    for (int sh = 8; sh > 0; sh >>= 1)
        p += __shfl_xor_sync(0xffffffffu, p, sh, 16);
    if (tt == 0) out[node] = p;
}

// ---------------------------------------------------------------------------
extern "C" void kernel_launch(void* const* d_in, const int* in_sizes, int n_in,
                              void* d_out, int out_size) {
    const float* v      = (const float*)d_in[0];
    const float* labels = (const float*)d_in[1];
    const int*   ei     = (const int*)d_in[2];
    const float *hx_w1 = (const float*)d_in[4],  *hx_b1 = (const float*)d_in[5];
    const float *hx_w2 = (const float*)d_in[6],  *hx_b2 = (const float*)d_in[7];
    const float *hy_w1 = (const float*)d_in[8],  *hy_b1 = (const float*)d_in[9];
    const float *hy_w2 = (const float*)d_in[10], *hy_b2 = (const float*)d_in[11];
    const float *fx_w1 = (const float*)d_in[12], *fx_b1 = (const float*)d_in[13];
    const float *fx_w2 = (const float*)d_in[14], *fx_b2 = (const float*)d_in[15];
    const float *fy_w1 = (const float*)d_in[16], *fy_b1 = (const float*)d_in[17];
    const float *fy_w2 = (const float*)d_in[18], *fy_b2 = (const float*)d_in[19];
    const float *fe_w1 = (const float*)d_in[20], *fe_b1 = (const float*)d_in[21];
    const float *fe_w2 = (const float*)d_in[22], *fe_b2 = (const float*)d_in[23];
    const float *fe_w3 = (const float*)d_in[24];

    int n  = in_sizes[0] / 7;       // 50000
    int ne = in_sizes[2] / 2;       // 250000
    float* out = (float*)d_out;

    const int SM_NP = 110592, SM_FX = 110592, SM_FY = 92160;
    cudaFuncSetAttribute((const void*)k_nodePB,
                         cudaFuncAttributeMaxDynamicSharedMemorySize, SM_NP);
    cudaFuncSetAttribute((const void*)k_fx2,
                         cudaFuncAttributeMaxDynamicSharedMemorySize, SM_FX);
    cudaFuncSetAttribute((const void*)k_fy2,
                         cudaFuncAttributeMaxDynamicSharedMemorySize, SM_FY);

    int nx  = n / 4;                 // x0 blocks
    int nq  = n / 4;                 // Q blocks
    int npb = NPAD / 128;            // 391 nodePB blocks
    int nch = ne / 16;               // 15625 edge chunks
    const int GRID = 296;

    k_goal<<<1, 1024>>>(v, labels, n);
    k_prep_h<<<37, 64>>>(hy_w1, hx_w1, hx_b1);
    k_prep_fxw<<<64, 256>>>(fx_w1, fx_w2);
    k_prep_fyw<<<64, 256>>>(fy_w1, fy_w2, hy_w2);
    k_initA<<<nx + nq, 256>>>(v, labels, hx_w2, hx_b2, n, nx);
    // y0 via hoisted partials (sel=1: hy W2, init=1: no max) -> mirrors
    k_fy2<<<GRID, 256, SM_FY>>>(ei, hy_b1, hy_b2, ne, nch, 1, 1);

    // iter 1: fx partials from x0, seed x0->x1
    k_nodePB<<<npb, 256, SM_NP>>>(0, 1, 0, n);
    k_fx2<<<GRID, 256, SM_FX>>>(ei, fx_b1, fx_b2, 1, ne, nch);
    // from x1: fy partials (iter-1 y) + fx partials (iter 2), seed x1->x0
    k_nodePB<<<npb, 256, SM_NP>>>(1, 0, 1, n);
    k_fy2<<<GRID, 256, SM_FY>>>(ei, fy_b1, fy_b2, ne, nch, 0, 0);
    k_fx2<<<GRID, 256, SM_FX>>>(ei, fx_b1, fx_b2, 0, ne, nch);
    // from x0: fy partials (iter-2 y) + fx partials (iter 3), seed x0->x1
    k_nodePB<<<npb, 256, SM_NP>>>(0, 1, 1, n);
    k_fy2<<<GRID, 256, SM_FY>>>(ei, fy_b1, fy_b2, ne, nch, 0, 0);
    k_fx2<<<GRID, 256, SM_FX>>>(ei, fx_b1, fx_b2, 1, ne, nch);
    // iter-3 y update is dead code — dropped

    k_out<<<n / 16, 256>>>(fe_w1, fe_b1, fe_w2, fe_b2, fe_w3, out, 1, n);
}